// round 1
// baseline (speedup 1.0000x reference)
#include <cuda_runtime.h>
#include <math.h>
#include <stdint.h>

// ---------------- problem constants ----------------
#define T_SEQ      2048
#define HIDDEN     4096
#define NUM_HEADS  32
#define HEAD_DIM   128
#define KV_GROUPS  2
#define Q_SZ       (NUM_HEADS * HEAD_DIM)              // 4096
#define KV_SZ      (KV_GROUPS * HEAD_DIM)              // 256
#define QKV_DIM    (Q_SZ + 2 * KV_SZ)                  // 4608
#define GQA_REP    (NUM_HEADS / KV_GROUPS)             // 16

// ---------------- scratch (static device memory; no allocs allowed) ----
__device__ float g_qkv[(size_t)T_SEQ * QKV_DIM];   // ~37.7 MB
__device__ float g_ctx[(size_t)T_SEQ * HIDDEN];    // ~33.6 MB

// =======================================================================
// SGEMM: C[M,N] = A[M,K] @ B[K,N] (+ bias[N]); 128x128 tile, K-step 8,
// 256 threads, 8x8 per thread, register prefetch of next K-tile.
// Requires M%128==0, N%128==0, K%8==0 (true for all three calls).
// =======================================================================
template <bool HAS_BIAS>
__global__ __launch_bounds__(256)
void sgemm128(const float* __restrict__ A, const float* __restrict__ B,
              const float* __restrict__ bias, float* __restrict__ C,
              int M, int N, int K)
{
    __shared__ float As[8][132];   // [k][m], padded to kill store conflicts
    __shared__ float Bs[8][128];   // [k][n]

    const int tid = threadIdx.x;
    const int tx = tid & 15;       // 0..15 -> N
    const int ty = tid >> 4;       // 0..15 -> M
    const int mBase = blockIdx.y * 128;
    const int nBase = blockIdx.x * 128;

    // A-tile loader: 128 rows x 8 k; each thread one float4
    const int aRow = tid >> 1;           // 0..127
    const int aK   = (tid & 1) * 4;      // 0 or 4
    // B-tile loader: 8 k x 128 cols; each thread one float4
    const int bK   = tid >> 5;           // 0..7
    const int bCol = (tid & 31) * 4;     // 0..124

    const float* Aptr = A + (size_t)(mBase + aRow) * K + aK;
    const float* Bptr = B + (size_t)bK * N + nBase + bCol;

    float c[8][8];
    #pragma unroll
    for (int i = 0; i < 8; ++i)
        #pragma unroll
        for (int j = 0; j < 8; ++j) c[i][j] = 0.f;

    const int KT = K >> 3;
    float4 aNext = *(const float4*)Aptr;
    float4 bNext = *(const float4*)Bptr;

    for (int kt = 0; kt < KT; ++kt) {
        As[aK + 0][aRow] = aNext.x;
        As[aK + 1][aRow] = aNext.y;
        As[aK + 2][aRow] = aNext.z;
        As[aK + 3][aRow] = aNext.w;
        *(float4*)&Bs[bK][bCol] = bNext;
        __syncthreads();

        if (kt + 1 < KT) {
            aNext = *(const float4*)(Aptr + (size_t)(kt + 1) * 8);
            bNext = *(const float4*)(Bptr + (size_t)(kt + 1) * 8 * N);
        }

        #pragma unroll
        for (int kk = 0; kk < 8; ++kk) {
            float4 a0 = *(const float4*)&As[kk][ty * 4];
            float4 a1 = *(const float4*)&As[kk][64 + ty * 4];
            float4 b0 = *(const float4*)&Bs[kk][tx * 4];
            float4 b1 = *(const float4*)&Bs[kk][64 + tx * 4];
            float ar[8] = {a0.x, a0.y, a0.z, a0.w, a1.x, a1.y, a1.z, a1.w};
            float br[8] = {b0.x, b0.y, b0.z, b0.w, b1.x, b1.y, b1.z, b1.w};
            #pragma unroll
            for (int i = 0; i < 8; ++i)
                #pragma unroll
                for (int j = 0; j < 8; ++j)
                    c[i][j] = fmaf(ar[i], br[j], c[i][j]);
        }
        __syncthreads();
    }

    // epilogue: rows {ty*4+i, 64+ty*4+i}, cols {tx*4+j, 64+tx*4+j}
    #pragma unroll
    for (int i = 0; i < 8; ++i) {
        const int row = mBase + ((i < 4) ? (ty * 4 + i) : (64 + ty * 4 + i - 4));
        #pragma unroll
        for (int half = 0; half < 2; ++half) {
            const int col = nBase + ((half == 0) ? (tx * 4) : (64 + tx * 4));
            float4 v;
            v.x = c[i][half * 4 + 0];
            v.y = c[i][half * 4 + 1];
            v.z = c[i][half * 4 + 2];
            v.w = c[i][half * 4 + 3];
            if (HAS_BIAS) {
                const float4 bv = *(const float4*)&bias[col];
                v.x += bv.x; v.y += bv.y; v.z += bv.z; v.w += bv.w;
            }
            *(float4*)&C[(size_t)row * N + col] = v;
        }
    }
}

// =======================================================================
// RoPE (interleaved pairs), applied in-place to Q and K slices of g_qkv.
// pairs per head = HEAD_DIM/4 = 32 (rot_dim = 64, rest passes through).
// =======================================================================
__global__ void rope_kernel(const int* __restrict__ positions)
{
    const int totalQ = T_SEQ * NUM_HEADS * 32;
    const int totalK = T_SEQ * KV_GROUPS * 32;
    int idx = blockIdx.x * blockDim.x + threadIdx.x;

    int t, p, col0;
    if (idx < totalQ) {
        p = idx & 31;
        int h = (idx >> 5) & (NUM_HEADS - 1);
        t = idx >> 10;
        col0 = h * HEAD_DIM + 2 * p;
    } else {
        int r = idx - totalQ;
        if (r >= totalK) return;
        p = r & 31;
        int g = (r >> 5) & (KV_GROUPS - 1);
        t = r >> 6;
        col0 = Q_SZ + g * HEAD_DIM + 2 * p;
    }

    const float pos   = (float)positions[t];
    const float theta = powf(10000.0f, -(float)p * (1.0f / 32.0f));
    float sn, cs;
    sincosf(pos * theta, &sn, &cs);

    float* b = g_qkv + (size_t)t * QKV_DIM + col0;
    const float x0 = b[0], x1 = b[1];
    b[0] = x0 * cs - x1 * sn;
    b[1] = x1 * cs + x0 * sn;
}

// =======================================================================
// Flash attention, fp32. One CTA per (query block of 64, head).
// BM=BN=64, 256 threads as 16x16; thread computes 4x4 of S
// (rows ty*4+i, cols tx+16*j for conflict-free LDS.128 on K),
// online softmax with half-warp shfl reductions, P staged via smem,
// O fragment 4 rows x 8 head-dims per thread.
// =======================================================================
#define BM 64
#define BN 64

struct AttnSmem {
    float Q[BM][132];
    float K[BN][132];
    float V[BN][132];
    float P[BM][BN];
};

__global__ __launch_bounds__(256)
void attn_kernel()
{
    extern __shared__ char smem_raw[];
    AttnSmem& sm = *reinterpret_cast<AttnSmem*>(smem_raw);

    const int head = blockIdx.y;
    const int mb   = blockIdx.x;
    const int tid  = threadIdx.x;
    const int tx   = tid & 15;
    const int ty   = tid >> 4;
    const int g    = head / GQA_REP;
    const float scale = 0.08838834764831845f;  // 1/sqrt(128)

    // load Q tile, pre-scaled
    for (int i = tid; i < BM * 32; i += 256) {   // 32 float4 per row
        const int r = i >> 5, c4 = (i & 31) * 4;
        float4 v = *(const float4*)(g_qkv + (size_t)(mb * BM + r) * QKV_DIM +
                                    head * HEAD_DIM + c4);
        v.x *= scale; v.y *= scale; v.z *= scale; v.w *= scale;
        *(float4*)&sm.Q[r][c4] = v;
    }

    float m[4], l[4], o[4][8];
    #pragma unroll
    for (int i = 0; i < 4; ++i) {
        m[i] = -1e30f; l[i] = 0.f;
        #pragma unroll
        for (int c = 0; c < 8; ++c) o[i][c] = 0.f;
    }

    for (int nb = 0; nb <= mb; ++nb) {
        __syncthreads();   // protect K/V/P reuse from previous iteration
        // load K and V tiles for kv-group g
        for (int i = tid; i < BN * 32; i += 256) {
            const int r = i >> 5, c4 = (i & 31) * 4;
            const size_t rowOff = (size_t)(nb * BN + r) * QKV_DIM;
            *(float4*)&sm.K[r][c4] =
                *(const float4*)(g_qkv + rowOff + Q_SZ + g * HEAD_DIM + c4);
            *(float4*)&sm.V[r][c4] =
                *(const float4*)(g_qkv + rowOff + Q_SZ + KV_SZ + g * HEAD_DIM + c4);
        }
        __syncthreads();

        // ---- S = Q K^T (scaled) ----
        float s[4][4];
        #pragma unroll
        for (int i = 0; i < 4; ++i)
            #pragma unroll
            for (int j = 0; j < 4; ++j) s[i][j] = 0.f;

        #pragma unroll 4
        for (int d = 0; d < HEAD_DIM; d += 4) {
            float4 q4[4], k4[4];
            #pragma unroll
            for (int i = 0; i < 4; ++i) q4[i] = *(const float4*)&sm.Q[ty * 4 + i][d];
            #pragma unroll
            for (int j = 0; j < 4; ++j) k4[j] = *(const float4*)&sm.K[tx + 16 * j][d];
            #pragma unroll
            for (int i = 0; i < 4; ++i)
                #pragma unroll
                for (int j = 0; j < 4; ++j) {
                    s[i][j] = fmaf(q4[i].x, k4[j].x, s[i][j]);
                    s[i][j] = fmaf(q4[i].y, k4[j].y, s[i][j]);
                    s[i][j] = fmaf(q4[i].z, k4[j].z, s[i][j]);
                    s[i][j] = fmaf(q4[i].w, k4[j].w, s[i][j]);
                }
        }

        // causal mask on the diagonal block
        if (nb == mb) {
            #pragma unroll
            for (int i = 0; i < 4; ++i)
                #pragma unroll
                for (int j = 0; j < 4; ++j)
                    if (tx + 16 * j > ty * 4 + i) s[i][j] = -1e30f;
        }

        // ---- online softmax stats (row groups = 16 lanes of a half-warp) --
        float mnew[4], rsum[4], alpha[4];
        #pragma unroll
        for (int i = 0; i < 4; ++i) {
            float v = fmaxf(fmaxf(s[i][0], s[i][1]), fmaxf(s[i][2], s[i][3]));
            #pragma unroll
            for (int off = 8; off >= 1; off >>= 1)
                v = fmaxf(v, __shfl_xor_sync(0xffffffffu, v, off));
            mnew[i] = fmaxf(m[i], v);
        }
        #pragma unroll
        for (int i = 0; i < 4; ++i) {
            float rs = 0.f;
            #pragma unroll
            for (int j = 0; j < 4; ++j) {
                const float p = __expf(s[i][j] - mnew[i]);
                s[i][j] = p;
                rs += p;
            }
            #pragma unroll
            for (int off = 8; off >= 1; off >>= 1)
                rs += __shfl_xor_sync(0xffffffffu, rs, off);
            rsum[i] = rs;
            alpha[i] = __expf(m[i] - mnew[i]);
            l[i] = l[i] * alpha[i] + rs;
            m[i] = mnew[i];
            #pragma unroll
            for (int c = 0; c < 8; ++c) o[i][c] *= alpha[i];
        }

        // stage P into smem for the PV stage
        #pragma unroll
        for (int i = 0; i < 4; ++i)
            #pragma unroll
            for (int j = 0; j < 4; ++j)
                sm.P[ty * 4 + i][tx + 16 * j] = s[i][j];
        __syncthreads();

        // ---- O += P @ V (thread owns rows ty*4+i, cols tx*8..tx*8+7) ----
        #pragma unroll 2
        for (int n = 0; n < BN; ++n) {
            const float4 v0 = *(const float4*)&sm.V[n][tx * 8];
            const float4 v1 = *(const float4*)&sm.V[n][tx * 8 + 4];
            #pragma unroll
            for (int i = 0; i < 4; ++i) {
                const float p = sm.P[ty * 4 + i][n];
                o[i][0] = fmaf(p, v0.x, o[i][0]);
                o[i][1] = fmaf(p, v0.y, o[i][1]);
                o[i][2] = fmaf(p, v0.z, o[i][2]);
                o[i][3] = fmaf(p, v0.w, o[i][3]);
                o[i][4] = fmaf(p, v1.x, o[i][4]);
                o[i][5] = fmaf(p, v1.y, o[i][5]);
                o[i][6] = fmaf(p, v1.z, o[i][6]);
                o[i][7] = fmaf(p, v1.w, o[i][7]);
            }
        }
    }

    // epilogue: normalize and write ctx
    #pragma unroll
    for (int i = 0; i < 4; ++i) {
        const float inv = 1.0f / l[i];
        const int t = mb * BM + ty * 4 + i;
        float* dst = g_ctx + (size_t)t * HIDDEN + head * HEAD_DIM + tx * 8;
        float4 w0, w1;
        w0.x = o[i][0] * inv; w0.y = o[i][1] * inv;
        w0.z = o[i][2] * inv; w0.w = o[i][3] * inv;
        w1.x = o[i][4] * inv; w1.y = o[i][5] * inv;
        w1.z = o[i][6] * inv; w1.w = o[i][7] * inv;
        *(float4*)dst = w0;
        *(float4*)(dst + 4) = w1;
    }
}

// =======================================================================
// launch
// =======================================================================
extern "C" void kernel_launch(void* const* d_in, const int* in_sizes, int n_in,
                              void* d_out, int out_size)
{
    const int*   positions = (const int*)d_in[0];
    const float* hidden    = (const float*)d_in[1];
    const float* w_qkv     = (const float*)d_in[2];
    const float* b_qkv     = (const float*)d_in[3];
    const float* w_dense   = (const float*)d_in[4];
    float*       out       = (float*)d_out;

    float *qkv_ptr, *ctx_ptr;
    cudaGetSymbolAddress((void**)&qkv_ptr, g_qkv);
    cudaGetSymbolAddress((void**)&ctx_ptr, g_ctx);

    // 1) QKV = hidden @ w_qkv + b_qkv
    sgemm128<true><<<dim3(QKV_DIM / 128, T_SEQ / 128), 256>>>(
        hidden, w_qkv, b_qkv, qkv_ptr, T_SEQ, QKV_DIM, HIDDEN);

    // 2) RoPE on Q and K (in place)
    const int totalRope = T_SEQ * NUM_HEADS * 32 + T_SEQ * KV_GROUPS * 32;
    rope_kernel<<<(totalRope + 255) / 256, 256>>>(positions);

    // 3) causal GQA flash attention -> g_ctx
    const int smemBytes = (int)sizeof(AttnSmem);
    cudaFuncSetAttribute(attn_kernel,
                         cudaFuncAttributeMaxDynamicSharedMemorySize, smemBytes);
    attn_kernel<<<dim3(T_SEQ / BM, NUM_HEADS), 256, smemBytes>>>();

    // 4) out = ctx @ w_dense
    sgemm128<false><<<dim3(HIDDEN / 128, T_SEQ / 128), 256>>>(
        ctx_ptr, w_dense, nullptr, out, T_SEQ, HIDDEN, HIDDEN);
}

// round 3
// speedup vs baseline: 1.5932x; 1.5932x over previous
#include <cuda_runtime.h>
#include <math.h>
#include <stdint.h>

// ---------------- problem constants ----------------
#define T_SEQ      2048
#define HIDDEN     4096
#define NUM_HEADS  32
#define HEAD_DIM   128
#define KV_GROUPS  2
#define Q_SZ       (NUM_HEADS * HEAD_DIM)              // 4096
#define KV_SZ      (KV_GROUPS * HEAD_DIM)              // 256
#define QKV_DIM    (Q_SZ + 2 * KV_SZ)                  // 4608
#define GQA_REP    (NUM_HEADS / KV_GROUPS)             // 16

// ---------------- scratch (static device memory; no allocs allowed) ----
__device__ float g_qkv[(size_t)T_SEQ * QKV_DIM];   // ~37.7 MB
__device__ float g_ctx[(size_t)T_SEQ * HIDDEN];    // ~33.6 MB

// =======================================================================
// helpers
// =======================================================================
__device__ __forceinline__ float f_tf32(float x) {
    uint32_t r;
    asm("cvt.rna.tf32.f32 %0, %1;" : "=r"(r) : "f"(x));
    return __uint_as_float(r);
}
__device__ __forceinline__ float4 f4_tf32(float4 v) {
    v.x = f_tf32(v.x); v.y = f_tf32(v.y);
    v.z = f_tf32(v.z); v.w = f_tf32(v.w);
    return v;
}

// =======================================================================
// tf32 tensor-core GEMM via mma.sync (sm_80-base PTX; compiles to
// non-'a' target). C[M,N] = A[M,K] @ B[K,N] (+bias).
// CTA tile 128x128, K-slab 32, 8 warps -> warp tile 64x32 of m16n8k8.
// Requires M%128==0, N%128==0, K%32==0.
// =======================================================================
#define GK    32
#define APAD  36      // A smem row pitch (floats): conflict-free frags
#define BPAD  136     // B smem row pitch (floats): conflict-free frags
#define AS_SZ (128 * APAD)
#define BS_SZ (GK * BPAD)
#define GEMM_SMEM ((2 * AS_SZ + 2 * BS_SZ) * 4)   // 71680 B

template <bool HAS_BIAS>
__global__ void __launch_bounds__(256)
gemm_tc(const float* __restrict__ A, const float* __restrict__ B,
        const float* __restrict__ bias, float* __restrict__ C,
        int M, int N, int K)
{
    extern __shared__ float smf[];
    float* As = smf;                    // [2][128][APAD]
    float* Bs = smf + 2 * AS_SZ;        // [2][GK][BPAD]

    const int tid  = threadIdx.x;
    const int lane = tid & 31;
    const int wid  = tid >> 5;
    const int wm   = (wid & 1) * 64;    // warp M offset in tile
    const int wn   = (wid >> 1) * 32;   // warp N offset in tile
    const int r    = lane >> 2;         // 0..7
    const int c    = lane & 3;          // 0..3
    const int mBase = blockIdx.y * 128;
    const int nBase = blockIdx.x * 128;

    float4 aReg[4], bReg[4];

    // ---- stage loaders: gmem -> regs, regs -> smem (rounded to tf32) ----
    #define LDG_SLAB(k0)                                                      \
        {                                                                     \
            _Pragma("unroll")                                                 \
            for (int i = 0; i < 4; ++i) {                                     \
                const int idx = tid + 256 * i;                                \
                aReg[i] = *(const float4*)&A[(size_t)(mBase + (idx >> 3)) * K \
                                             + (k0) + (idx & 7) * 4];         \
                bReg[i] = *(const float4*)&B[(size_t)((k0) + (idx >> 5)) * N  \
                                             + nBase + (idx & 31) * 4];       \
            }                                                                 \
        }
    #define STS_SLAB(buf)                                                     \
        {                                                                     \
            float* ap = As + (buf) * AS_SZ;                                   \
            float* bp = Bs + (buf) * BS_SZ;                                   \
            _Pragma("unroll")                                                 \
            for (int i = 0; i < 4; ++i) {                                     \
                const int idx = tid + 256 * i;                                \
                *(float4*)&ap[(idx >> 3) * APAD + (idx & 7) * 4] =            \
                    f4_tf32(aReg[i]);                                         \
                *(float4*)&bp[(idx >> 5) * BPAD + (idx & 31) * 4] =           \
                    f4_tf32(bReg[i]);                                         \
            }                                                                 \
        }

    float acc[4][4][4];
    #pragma unroll
    for (int mi = 0; mi < 4; ++mi)
        #pragma unroll
        for (int ni = 0; ni < 4; ++ni)
            #pragma unroll
            for (int q = 0; q < 4; ++q) acc[mi][ni][q] = 0.f;

    LDG_SLAB(0);
    STS_SLAB(0);
    __syncthreads();

    const int KT = K / GK;
    for (int kt = 0; kt < KT; ++kt) {
        if (kt + 1 < KT) LDG_SLAB((kt + 1) * GK);

        const float* a = As + (kt & 1) * AS_SZ;
        const float* b = Bs + (kt & 1) * BS_SZ;
        #pragma unroll
        for (int ks = 0; ks < 4; ++ks) {
            const int k0 = ks * 8;
            uint32_t af[4][4], bf[4][2];
            #pragma unroll
            for (int mi = 0; mi < 4; ++mi) {
                const float* p = a + (wm + mi * 16 + r) * APAD + k0 + c;
                af[mi][0] = __float_as_uint(p[0]);
                af[mi][1] = __float_as_uint(p[8 * APAD]);
                af[mi][2] = __float_as_uint(p[4]);
                af[mi][3] = __float_as_uint(p[8 * APAD + 4]);
            }
            #pragma unroll
            for (int ni = 0; ni < 4; ++ni) {
                const float* p = b + (k0 + c) * BPAD + wn + ni * 8 + r;
                bf[ni][0] = __float_as_uint(p[0]);
                bf[ni][1] = __float_as_uint(p[4 * BPAD]);
            }
            #pragma unroll
            for (int mi = 0; mi < 4; ++mi)
                #pragma unroll
                for (int ni = 0; ni < 4; ++ni)
                    asm volatile(
                        "mma.sync.aligned.m16n8k8.row.col.f32.tf32.tf32.f32 "
                        "{%0,%1,%2,%3}, {%4,%5,%6,%7}, {%8,%9}, {%0,%1,%2,%3};"
                        : "+f"(acc[mi][ni][0]), "+f"(acc[mi][ni][1]),
                          "+f"(acc[mi][ni][2]), "+f"(acc[mi][ni][3])
                        : "r"(af[mi][0]), "r"(af[mi][1]),
                          "r"(af[mi][2]), "r"(af[mi][3]),
                          "r"(bf[ni][0]), "r"(bf[ni][1]));
        }

        if (kt + 1 < KT) {
            STS_SLAB((kt + 1) & 1);
            __syncthreads();
        }
    }

    // ---- epilogue ----
    #pragma unroll
    for (int mi = 0; mi < 4; ++mi) {
        const int row0 = mBase + wm + mi * 16 + r;
        #pragma unroll
        for (int ni = 0; ni < 4; ++ni) {
            const int col = nBase + wn + ni * 8 + c * 2;
            float2 v0 = make_float2(acc[mi][ni][0], acc[mi][ni][1]);
            float2 v1 = make_float2(acc[mi][ni][2], acc[mi][ni][3]);
            if (HAS_BIAS) {
                const float2 bb = *(const float2*)&bias[col];
                v0.x += bb.x; v0.y += bb.y;
                v1.x += bb.x; v1.y += bb.y;
            }
            *(float2*)&C[(size_t)row0 * N + col] = v0;
            *(float2*)&C[(size_t)(row0 + 8) * N + col] = v1;
        }
    }
    #undef LDG_SLAB
    #undef STS_SLAB
}

// =======================================================================
// RoPE (interleaved pairs), applied in-place to Q and K slices of g_qkv.
// =======================================================================
__global__ void rope_kernel(const int* __restrict__ positions)
{
    const int totalQ = T_SEQ * NUM_HEADS * 32;
    const int totalK = T_SEQ * KV_GROUPS * 32;
    int idx = blockIdx.x * blockDim.x + threadIdx.x;

    int t, p, col0;
    if (idx < totalQ) {
        p = idx & 31;
        int h = (idx >> 5) & (NUM_HEADS - 1);
        t = idx >> 10;
        col0 = h * HEAD_DIM + 2 * p;
    } else {
        int r = idx - totalQ;
        if (r >= totalK) return;
        p = r & 31;
        int g = (r >> 5) & (KV_GROUPS - 1);
        t = r >> 6;
        col0 = Q_SZ + g * HEAD_DIM + 2 * p;
    }

    const float pos   = (float)positions[t];
    const float theta = powf(10000.0f, -(float)p * (1.0f / 32.0f));
    float sn, cs;
    sincosf(pos * theta, &sn, &cs);

    float* b = g_qkv + (size_t)t * QKV_DIM + col0;
    const float x0 = b[0], x1 = b[1];
    b[0] = x0 * cs - x1 * sn;
    b[1] = x1 * cs + x0 * sn;
}

// =======================================================================
// Flash attention, fp32 (known-good round-1 version).
// =======================================================================
#define BM 64
#define BN 64

struct AttnSmem {
    float Q[BM][132];
    float K[BN][132];
    float V[BN][132];
    float P[BM][BN];
};

__global__ __launch_bounds__(256)
void attn_kernel()
{
    extern __shared__ char smem_raw[];
    AttnSmem& sm = *reinterpret_cast<AttnSmem*>(smem_raw);

    const int head = blockIdx.y;
    const int mb   = blockIdx.x;
    const int tid  = threadIdx.x;
    const int tx   = tid & 15;
    const int ty   = tid >> 4;
    const int g    = head / GQA_REP;
    const float scale = 0.08838834764831845f;

    for (int i = tid; i < BM * 32; i += 256) {
        const int r = i >> 5, c4 = (i & 31) * 4;
        float4 v = *(const float4*)(g_qkv + (size_t)(mb * BM + r) * QKV_DIM +
                                    head * HEAD_DIM + c4);
        v.x *= scale; v.y *= scale; v.z *= scale; v.w *= scale;
        *(float4*)&sm.Q[r][c4] = v;
    }

    float m[4], l[4], o[4][8];
    #pragma unroll
    for (int i = 0; i < 4; ++i) {
        m[i] = -1e30f; l[i] = 0.f;
        #pragma unroll
        for (int c = 0; c < 8; ++c) o[i][c] = 0.f;
    }

    for (int nb = 0; nb <= mb; ++nb) {
        __syncthreads();
        for (int i = tid; i < BN * 32; i += 256) {
            const int r = i >> 5, c4 = (i & 31) * 4;
            const size_t rowOff = (size_t)(nb * BN + r) * QKV_DIM;
            *(float4*)&sm.K[r][c4] =
                *(const float4*)(g_qkv + rowOff + Q_SZ + g * HEAD_DIM + c4);
            *(float4*)&sm.V[r][c4] =
                *(const float4*)(g_qkv + rowOff + Q_SZ + KV_SZ + g * HEAD_DIM + c4);
        }
        __syncthreads();

        float s[4][4];
        #pragma unroll
        for (int i = 0; i < 4; ++i)
            #pragma unroll
            for (int j = 0; j < 4; ++j) s[i][j] = 0.f;

        #pragma unroll 4
        for (int d = 0; d < HEAD_DIM; d += 4) {
            float4 q4[4], k4[4];
            #pragma unroll
            for (int i = 0; i < 4; ++i) q4[i] = *(const float4*)&sm.Q[ty * 4 + i][d];
            #pragma unroll
            for (int j = 0; j < 4; ++j) k4[j] = *(const float4*)&sm.K[tx + 16 * j][d];
            #pragma unroll
            for (int i = 0; i < 4; ++i)
                #pragma unroll
                for (int j = 0; j < 4; ++j) {
                    s[i][j] = fmaf(q4[i].x, k4[j].x, s[i][j]);
                    s[i][j] = fmaf(q4[i].y, k4[j].y, s[i][j]);
                    s[i][j] = fmaf(q4[i].z, k4[j].z, s[i][j]);
                    s[i][j] = fmaf(q4[i].w, k4[j].w, s[i][j]);
                }
        }

        if (nb == mb) {
            #pragma unroll
            for (int i = 0; i < 4; ++i)
                #pragma unroll
                for (int j = 0; j < 4; ++j)
                    if (tx + 16 * j > ty * 4 + i) s[i][j] = -1e30f;
        }

        float mnew[4];
        #pragma unroll
        for (int i = 0; i < 4; ++i) {
            float v = fmaxf(fmaxf(s[i][0], s[i][1]), fmaxf(s[i][2], s[i][3]));
            #pragma unroll
            for (int off = 8; off >= 1; off >>= 1)
                v = fmaxf(v, __shfl_xor_sync(0xffffffffu, v, off));
            mnew[i] = fmaxf(m[i], v);
        }
        #pragma unroll
        for (int i = 0; i < 4; ++i) {
            float rs = 0.f;
            #pragma unroll
            for (int j = 0; j < 4; ++j) {
                const float p = __expf(s[i][j] - mnew[i]);
                s[i][j] = p;
                rs += p;
            }
            #pragma unroll
            for (int off = 8; off >= 1; off >>= 1)
                rs += __shfl_xor_sync(0xffffffffu, rs, off);
            const float alpha = __expf(m[i] - mnew[i]);
            l[i] = l[i] * alpha + rs;
            m[i] = mnew[i];
            #pragma unroll
            for (int c = 0; c < 8; ++c) o[i][c] *= alpha;
        }

        #pragma unroll
        for (int i = 0; i < 4; ++i)
            #pragma unroll
            for (int j = 0; j < 4; ++j)
                sm.P[ty * 4 + i][tx + 16 * j] = s[i][j];
        __syncthreads();

        #pragma unroll 2
        for (int n = 0; n < BN; ++n) {
            const float4 v0 = *(const float4*)&sm.V[n][tx * 8];
            const float4 v1 = *(const float4*)&sm.V[n][tx * 8 + 4];
            #pragma unroll
            for (int i = 0; i < 4; ++i) {
                const float p = sm.P[ty * 4 + i][n];
                o[i][0] = fmaf(p, v0.x, o[i][0]);
                o[i][1] = fmaf(p, v0.y, o[i][1]);
                o[i][2] = fmaf(p, v0.z, o[i][2]);
                o[i][3] = fmaf(p, v0.w, o[i][3]);
                o[i][4] = fmaf(p, v1.x, o[i][4]);
                o[i][5] = fmaf(p, v1.y, o[i][5]);
                o[i][6] = fmaf(p, v1.z, o[i][6]);
                o[i][7] = fmaf(p, v1.w, o[i][7]);
            }
        }
    }

    #pragma unroll
    for (int i = 0; i < 4; ++i) {
        const float inv = 1.0f / l[i];
        const int t = mb * BM + ty * 4 + i;
        float* dst = g_ctx + (size_t)t * HIDDEN + head * HEAD_DIM + tx * 8;
        float4 w0, w1;
        w0.x = o[i][0] * inv; w0.y = o[i][1] * inv;
        w0.z = o[i][2] * inv; w0.w = o[i][3] * inv;
        w1.x = o[i][4] * inv; w1.y = o[i][5] * inv;
        w1.z = o[i][6] * inv; w1.w = o[i][7] * inv;
        *(float4*)dst = w0;
        *(float4*)(dst + 4) = w1;
    }
}

// =======================================================================
// launch
// =======================================================================
extern "C" void kernel_launch(void* const* d_in, const int* in_sizes, int n_in,
                              void* d_out, int out_size)
{
    const int*   positions = (const int*)d_in[0];
    const float* hidden    = (const float*)d_in[1];
    const float* w_qkv     = (const float*)d_in[2];
    const float* b_qkv     = (const float*)d_in[3];
    const float* w_dense   = (const float*)d_in[4];
    float*       out       = (float*)d_out;

    float *qkv_p, *ctx_p;
    cudaGetSymbolAddress((void**)&qkv_p, g_qkv);
    cudaGetSymbolAddress((void**)&ctx_p, g_ctx);

    cudaFuncSetAttribute(gemm_tc<true>,
                         cudaFuncAttributeMaxDynamicSharedMemorySize, GEMM_SMEM);
    cudaFuncSetAttribute(gemm_tc<false>,
                         cudaFuncAttributeMaxDynamicSharedMemorySize, GEMM_SMEM);

    // 1) QKV = hidden @ w_qkv + b_qkv   (tf32 mma.sync)
    gemm_tc<true><<<dim3(QKV_DIM / 128, T_SEQ / 128), 256, GEMM_SMEM>>>(
        hidden, w_qkv, b_qkv, qkv_p, T_SEQ, QKV_DIM, HIDDEN);

    // 2) RoPE in place
    const int totalRope = T_SEQ * NUM_HEADS * 32 + T_SEQ * KV_GROUPS * 32;
    rope_kernel<<<(totalRope + 255) / 256, 256>>>(positions);

    // 3) causal GQA flash attention -> g_ctx
    const int smemBytes = (int)sizeof(AttnSmem);
    cudaFuncSetAttribute(attn_kernel,
                         cudaFuncAttributeMaxDynamicSharedMemorySize, smemBytes);
    attn_kernel<<<dim3(T_SEQ / BM, NUM_HEADS), 256, smemBytes>>>();

    // 4) out = ctx @ w_dense   (tf32 mma.sync)
    gemm_tc<false><<<dim3(HIDDEN / 128, T_SEQ / 128), 256, GEMM_SMEM>>>(
        ctx_p, w_dense, nullptr, out, T_SEQ, HIDDEN, HIDDEN);
}

// round 4
// speedup vs baseline: 2.1621x; 1.3571x over previous
#include <cuda_runtime.h>
#include <math.h>
#include <stdint.h>

// ---------------- problem constants ----------------
#define T_SEQ      2048
#define HIDDEN     4096
#define NUM_HEADS  32
#define HEAD_DIM   128
#define KV_GROUPS  2
#define Q_SZ       (NUM_HEADS * HEAD_DIM)              // 4096
#define KV_SZ      (KV_GROUPS * HEAD_DIM)              // 256
#define QKV_DIM    (Q_SZ + 2 * KV_SZ)                  // 4608
#define GQA_REP    (NUM_HEADS / KV_GROUPS)             // 16

// ---------------- scratch (static device memory; no allocs allowed) ----
__device__ float g_qkv[(size_t)T_SEQ * QKV_DIM];   // ~37.7 MB
__device__ float g_ctx[(size_t)T_SEQ * HIDDEN];    // ~33.6 MB

// =======================================================================
// helpers
// =======================================================================
__device__ __forceinline__ float f_tf32(float x) {
    uint32_t r;
    asm("cvt.rna.tf32.f32 %0, %1;" : "=r"(r) : "f"(x));
    return __uint_as_float(r);
}
__device__ __forceinline__ float4 f4_tf32(float4 v) {
    v.x = f_tf32(v.x); v.y = f_tf32(v.y);
    v.z = f_tf32(v.z); v.w = f_tf32(v.w);
    return v;
}
// split (x0,x1) into packed bf16 hi pair and lo (residual) pair; x0 in low half
__device__ __forceinline__ void bsplit(float x0, float x1,
                                       uint32_t& hi, uint32_t& lo) {
    uint32_t h;
    asm("cvt.rn.bf16x2.f32 %0, %1, %2;" : "=r"(h) : "f"(x1), "f"(x0));
    const float h0 = __uint_as_float(h << 16);
    const float h1 = __uint_as_float(h & 0xffff0000u);
    asm("cvt.rn.bf16x2.f32 %0, %1, %2;" : "=r"(lo) : "f"(x1 - h1), "f"(x0 - h0));
    hi = h;
}

#define MMA_TF32(d, a0, a1, a2, a3, b0, b1)                                   \
    asm volatile(                                                             \
        "mma.sync.aligned.m16n8k8.row.col.f32.tf32.tf32.f32 "                 \
        "{%0,%1,%2,%3}, {%4,%5,%6,%7}, {%8,%9}, {%0,%1,%2,%3};"               \
        : "+f"((d)[0]), "+f"((d)[1]), "+f"((d)[2]), "+f"((d)[3])              \
        : "r"(a0), "r"(a1), "r"(a2), "r"(a3), "r"(b0), "r"(b1))

#define MMA_BF16(d, a0, a1, a2, a3, b0, b1)                                   \
    asm volatile(                                                             \
        "mma.sync.aligned.m16n8k16.row.col.f32.bf16.bf16.f32 "                \
        "{%0,%1,%2,%3}, {%4,%5,%6,%7}, {%8,%9}, {%0,%1,%2,%3};"               \
        : "+f"((d)[0]), "+f"((d)[1]), "+f"((d)[2]), "+f"((d)[3])              \
        : "r"(a0), "r"(a1), "r"(a2), "r"(a3), "r"(b0), "r"(b1))

// =======================================================================
// bf16x3 tensor-core GEMM (fp32-accurate): C = A[M,K] @ B[K,N] (+bias).
// CTA tile 128x128, K-slab 32, 8 warps -> warp tile 64x32.
// A/B split into bf16 hi+lo planes in smem (packed k-pairs, uint32).
// acc += Ahi*Bhi + Ahi*Blo + Alo*Bhi   (lo*lo dropped, ~2^-18)
// =======================================================================
#define GK      32
#define AP      20                        // A plane pitch (uint32): 16 pairs + 4
#define BP      132                       // B plane pitch (uint32): 128 + 4
#define A_PLANE (128 * AP)                // 2560 words
#define B_PLANE (16 * BP)                 // 2112 words
#define GEMM_SMEM ((4 * A_PLANE + 4 * B_PLANE) * 4)   // 74752 B

template <bool HAS_BIAS>
__global__ void __launch_bounds__(256)
gemm_tc(const float* __restrict__ A, const float* __restrict__ B,
        const float* __restrict__ bias, float* __restrict__ C,
        int M, int N, int K)
{
    extern __shared__ uint32_t smw[];
    uint32_t* AHi = smw;                       // [2][128][AP]
    uint32_t* ALo = smw + 2 * A_PLANE;
    uint32_t* BHi = smw + 4 * A_PLANE;         // [2][16][BP]
    uint32_t* BLo = smw + 4 * A_PLANE + 2 * B_PLANE;

    const int tid  = threadIdx.x;
    const int lane = tid & 31;
    const int wid  = tid >> 5;
    const int wm   = (wid & 1) * 64;
    const int wn   = (wid >> 1) * 32;
    const int r    = lane >> 2;
    const int c    = lane & 3;
    const int mBase = blockIdx.y * 128;
    const int nBase = blockIdx.x * 128;

    float4 aReg[4], b0Reg[2], b1Reg[2];

    #define LDG_SLAB(k0)                                                       \
        {                                                                      \
            _Pragma("unroll")                                                  \
            for (int i = 0; i < 4; ++i) {                                      \
                const int idx = tid + 256 * i;                                 \
                aReg[i] = *(const float4*)&A[(size_t)(mBase + (idx >> 3)) * K  \
                                             + (k0) + (idx & 7) * 4];          \
            }                                                                  \
            _Pragma("unroll")                                                  \
            for (int i = 0; i < 2; ++i) {                                      \
                const int it = tid + 256 * i;                                  \
                const int pr = it >> 5, n4 = (it & 31) * 4;                    \
                b0Reg[i] = *(const float4*)&B[(size_t)((k0) + 2 * pr) * N      \
                                              + nBase + n4];                   \
                b1Reg[i] = *(const float4*)&B[(size_t)((k0) + 2 * pr + 1) * N  \
                                              + nBase + n4];                   \
            }                                                                  \
        }
    #define STS_SLAB(buf)                                                      \
        {                                                                      \
            _Pragma("unroll")                                                  \
            for (int i = 0; i < 4; ++i) {                                      \
                const int idx = tid + 256 * i;                                 \
                const int row = idx >> 3, kq = idx & 7;                        \
                uint32_t h0, l0, h1, l1;                                       \
                bsplit(aReg[i].x, aReg[i].y, h0, l0);                          \
                bsplit(aReg[i].z, aReg[i].w, h1, l1);                          \
                uint32_t* ph = AHi + (buf) * A_PLANE + row * AP + 2 * kq;      \
                uint32_t* pl = ALo + (buf) * A_PLANE + row * AP + 2 * kq;      \
                ph[0] = h0; ph[1] = h1;                                        \
                pl[0] = l0; pl[1] = l1;                                        \
            }                                                                  \
            _Pragma("unroll")                                                  \
            for (int i = 0; i < 2; ++i) {                                      \
                const int it = tid + 256 * i;                                  \
                const int pr = it >> 5, n4 = (it & 31) * 4;                    \
                const float u[4] = {b0Reg[i].x, b0Reg[i].y,                    \
                                    b0Reg[i].z, b0Reg[i].w};                   \
                const float w[4] = {b1Reg[i].x, b1Reg[i].y,                    \
                                    b1Reg[i].z, b1Reg[i].w};                   \
                _Pragma("unroll")                                              \
                for (int jj = 0; jj < 4; ++jj) {                               \
                    uint32_t h, l;                                             \
                    bsplit(u[jj], w[jj], h, l);                                \
                    BHi[(buf) * B_PLANE + pr * BP + n4 + jj] = h;              \
                    BLo[(buf) * B_PLANE + pr * BP + n4 + jj] = l;              \
                }                                                              \
            }                                                                  \
        }

    float acc[4][4][4];
    #pragma unroll
    for (int mi = 0; mi < 4; ++mi)
        #pragma unroll
        for (int ni = 0; ni < 4; ++ni)
            #pragma unroll
            for (int q = 0; q < 4; ++q) acc[mi][ni][q] = 0.f;

    LDG_SLAB(0);
    STS_SLAB(0);
    __syncthreads();

    const int KT = K / GK;
    for (int kt = 0; kt < KT; ++kt) {
        if (kt + 1 < KT) LDG_SLAB((kt + 1) * GK);

        const uint32_t* ah = AHi + (kt & 1) * A_PLANE;
        const uint32_t* al = ALo + (kt & 1) * A_PLANE;
        const uint32_t* bh = BHi + (kt & 1) * B_PLANE;
        const uint32_t* bl = BLo + (kt & 1) * B_PLANE;

        #pragma unroll
        for (int t = 0; t < 2; ++t) {
            uint32_t afh[4][4], afl[4][4];
            #pragma unroll
            for (int mi = 0; mi < 4; ++mi) {
                const int ro = (wm + mi * 16 + r) * AP + 8 * t + c;
                afh[mi][0] = ah[ro];          afh[mi][1] = ah[ro + 8 * AP];
                afh[mi][2] = ah[ro + 4];      afh[mi][3] = ah[ro + 8 * AP + 4];
                afl[mi][0] = al[ro];          afl[mi][1] = al[ro + 8 * AP];
                afl[mi][2] = al[ro + 4];      afl[mi][3] = al[ro + 8 * AP + 4];
            }
            #pragma unroll
            for (int ni = 0; ni < 4; ++ni) {
                const int n = wn + ni * 8 + r;
                const uint32_t bh0 = bh[(8 * t + c) * BP + n];
                const uint32_t bh1 = bh[(8 * t + c + 4) * BP + n];
                const uint32_t bl0 = bl[(8 * t + c) * BP + n];
                const uint32_t bl1 = bl[(8 * t + c + 4) * BP + n];
                #pragma unroll
                for (int mi = 0; mi < 4; ++mi) {
                    MMA_BF16(acc[mi][ni], afh[mi][0], afh[mi][1], afh[mi][2],
                             afh[mi][3], bh0, bh1);
                    MMA_BF16(acc[mi][ni], afh[mi][0], afh[mi][1], afh[mi][2],
                             afh[mi][3], bl0, bl1);
                    MMA_BF16(acc[mi][ni], afl[mi][0], afl[mi][1], afl[mi][2],
                             afl[mi][3], bh0, bh1);
                }
            }
        }

        if (kt + 1 < KT) {
            STS_SLAB((kt + 1) & 1);
            __syncthreads();
        }
    }

    // ---- epilogue ----
    #pragma unroll
    for (int mi = 0; mi < 4; ++mi) {
        const int row0 = mBase + wm + mi * 16 + r;
        #pragma unroll
        for (int ni = 0; ni < 4; ++ni) {
            const int col = nBase + wn + ni * 8 + c * 2;
            float2 v0 = make_float2(acc[mi][ni][0], acc[mi][ni][1]);
            float2 v1 = make_float2(acc[mi][ni][2], acc[mi][ni][3]);
            if (HAS_BIAS) {
                const float2 bb = *(const float2*)&bias[col];
                v0.x += bb.x; v0.y += bb.y;
                v1.x += bb.x; v1.y += bb.y;
            }
            *(float2*)&C[(size_t)row0 * N + col] = v0;
            *(float2*)&C[(size_t)(row0 + 8) * N + col] = v1;
        }
    }
    #undef LDG_SLAB
    #undef STS_SLAB
}

// =======================================================================
// RoPE (interleaved pairs), in-place on Q and K slices of g_qkv.
// =======================================================================
__global__ void rope_kernel(const int* __restrict__ positions)
{
    const int totalQ = T_SEQ * NUM_HEADS * 32;
    const int totalK = T_SEQ * KV_GROUPS * 32;
    int idx = blockIdx.x * blockDim.x + threadIdx.x;

    int t, p, col0;
    if (idx < totalQ) {
        p = idx & 31;
        int h = (idx >> 5) & (NUM_HEADS - 1);
        t = idx >> 10;
        col0 = h * HEAD_DIM + 2 * p;
    } else {
        int rr = idx - totalQ;
        if (rr >= totalK) return;
        p = rr & 31;
        int g = (rr >> 5) & (KV_GROUPS - 1);
        t = rr >> 6;
        col0 = Q_SZ + g * HEAD_DIM + 2 * p;
    }

    const float pos   = (float)positions[t];
    const float theta = powf(10000.0f, -(float)p * (1.0f / 32.0f));
    float sn, cs;
    sincosf(pos * theta, &sn, &cs);

    float* b = g_qkv + (size_t)t * QKV_DIM + col0;
    const float x0 = b[0], x1 = b[1];
    b[0] = x0 * cs - x1 * sn;
    b[1] = x1 * cs + x0 * sn;
}

// =======================================================================
// Flash attention on tf32 mma.sync.
// CTA: 128 q-rows x 1 head; 8 warps, warp w owns m16 stripe rows 16w..16w+15.
// S = QK^T via m16n8k8 (K=128 -> 16 k-steps, 8 n8 frags over BN=64);
// online softmax on accumulator frags (4-lane shfl row reduce);
// P staged in warp-private smem (tf32-rounded, sums match PV exactly);
// O += P@V via m16n8k8 (16 d-frags). K/V gmem loads double-buffered in regs.
// =======================================================================
#define ABM 128
#define ABN 64

struct AttnSmem {
    float Q[ABM][132];
    float K[ABN][132];
    float V[ABN][132];
    float P[ABM][68];
};   // 169984 B

__global__ __launch_bounds__(256)
void attn_tc()
{
    extern __shared__ char sraw[];
    AttnSmem& sm = *reinterpret_cast<AttnSmem*>(sraw);

    const int head = blockIdx.y;
    const int mb   = blockIdx.x;
    const int tid  = threadIdx.x;
    const int lane = tid & 31;
    const int wid  = tid >> 5;
    const int r    = lane >> 2;
    const int c    = lane & 3;
    const int rb   = wid * 16;
    const int g    = head / GQA_REP;
    const float scale = 0.08838834764831845f;   // 1/sqrt(128)

    // ---- load Q tile (scaled, tf32-RN) ----
    for (int i = tid; i < ABM * 32; i += 256) {
        const int row = i >> 5, c4 = (i & 31) << 2;
        float4 v = *(const float4*)&g_qkv[(size_t)(mb * ABM + row) * QKV_DIM +
                                          head * HEAD_DIM + c4];
        v.x = f_tf32(v.x * scale); v.y = f_tf32(v.y * scale);
        v.z = f_tf32(v.z * scale); v.w = f_tf32(v.w * scale);
        *(float4*)&sm.Q[row][c4] = v;
    }

    // ---- prefetch K/V block 0 into registers ----
    float4 kr[8], vr[8];
    #pragma unroll
    for (int q = 0; q < 8; ++q) {
        const int i = tid + 256 * q;
        const int row = i >> 5, c4 = (i & 31) << 2;
        const size_t ro = (size_t)row * QKV_DIM + Q_SZ + g * HEAD_DIM;
        kr[q] = *(const float4*)&g_qkv[ro + c4];
        vr[q] = *(const float4*)&g_qkv[ro + KV_SZ + c4];
    }

    float o[16][4];
    #pragma unroll
    for (int j = 0; j < 16; ++j)
        #pragma unroll
        for (int q = 0; q < 4; ++q) o[j][q] = 0.f;
    float mst0 = -1e30f, mst1 = -1e30f, lst0 = 0.f, lst1 = 0.f;

    const int nbEnd = 2 * mb + 1;
    for (int nb = 0; nb <= nbEnd; ++nb) {
        __syncthreads();     // all warps done with previous K/V
        #pragma unroll
        for (int q = 0; q < 8; ++q) {
            const int i = tid + 256 * q;
            const int row = i >> 5, c4 = (i & 31) << 2;
            *(float4*)&sm.K[row][c4] = f4_tf32(kr[q]);
            *(float4*)&sm.V[row][c4] = f4_tf32(vr[q]);
        }
        __syncthreads();

        if (nb < nbEnd) {    // prefetch next block (hidden under MMA work)
            #pragma unroll
            for (int q = 0; q < 8; ++q) {
                const int i = tid + 256 * q;
                const int row = i >> 5, c4 = (i & 31) << 2;
                const size_t ro = (size_t)((nb + 1) * ABN + row) * QKV_DIM +
                                  Q_SZ + g * HEAD_DIM;
                kr[q] = *(const float4*)&g_qkv[ro + c4];
                vr[q] = *(const float4*)&g_qkv[ro + KV_SZ + c4];
            }
        }

        // ---- S = Q K^T ----
        float s[8][4];
        #pragma unroll
        for (int j = 0; j < 8; ++j)
            #pragma unroll
            for (int q = 0; q < 4; ++q) s[j][q] = 0.f;

        #pragma unroll 4
        for (int k0 = 0; k0 < 16; ++k0) {
            const uint32_t a0 = __float_as_uint(sm.Q[rb + r][8 * k0 + c]);
            const uint32_t a1 = __float_as_uint(sm.Q[rb + r + 8][8 * k0 + c]);
            const uint32_t a2 = __float_as_uint(sm.Q[rb + r][8 * k0 + c + 4]);
            const uint32_t a3 = __float_as_uint(sm.Q[rb + r + 8][8 * k0 + c + 4]);
            #pragma unroll
            for (int j = 0; j < 8; ++j) {
                const uint32_t b0 = __float_as_uint(sm.K[8 * j + r][8 * k0 + c]);
                const uint32_t b1 = __float_as_uint(sm.K[8 * j + r][8 * k0 + c + 4]);
                MMA_TF32(s[j], a0, a1, a2, a3, b0, b1);
            }
        }

        // ---- causal mask (only the last two kv blocks can clip) ----
        if (nb >= 2 * mb) {
            const int row0 = mb * ABM + rb + r;
            #pragma unroll
            for (int j = 0; j < 8; ++j) {
                const int col = nb * ABN + 8 * j + 2 * c;
                if (col     > row0)     s[j][0] = -1e30f;
                if (col + 1 > row0)     s[j][1] = -1e30f;
                if (col     > row0 + 8) s[j][2] = -1e30f;
                if (col + 1 > row0 + 8) s[j][3] = -1e30f;
            }
        }

        // ---- online softmax (rows r and r+8; reduce over 4-lane c-group) --
        float mx0 = -1e30f, mx1 = -1e30f;
        #pragma unroll
        for (int j = 0; j < 8; ++j) {
            mx0 = fmaxf(mx0, fmaxf(s[j][0], s[j][1]));
            mx1 = fmaxf(mx1, fmaxf(s[j][2], s[j][3]));
        }
        mx0 = fmaxf(mx0, __shfl_xor_sync(0xffffffffu, mx0, 1));
        mx0 = fmaxf(mx0, __shfl_xor_sync(0xffffffffu, mx0, 2));
        mx1 = fmaxf(mx1, __shfl_xor_sync(0xffffffffu, mx1, 1));
        mx1 = fmaxf(mx1, __shfl_xor_sync(0xffffffffu, mx1, 2));
        const float mn0 = fmaxf(mst0, mx0), mn1 = fmaxf(mst1, mx1);
        const float al0 = __expf(mst0 - mn0), al1 = __expf(mst1 - mn1);
        float sum0 = 0.f, sum1 = 0.f;
        #pragma unroll
        for (int j = 0; j < 8; ++j) {
            s[j][0] = f_tf32(__expf(s[j][0] - mn0)); sum0 += s[j][0];
            s[j][1] = f_tf32(__expf(s[j][1] - mn0)); sum0 += s[j][1];
            s[j][2] = f_tf32(__expf(s[j][2] - mn1)); sum1 += s[j][2];
            s[j][3] = f_tf32(__expf(s[j][3] - mn1)); sum1 += s[j][3];
        }
        sum0 += __shfl_xor_sync(0xffffffffu, sum0, 1);
        sum0 += __shfl_xor_sync(0xffffffffu, sum0, 2);
        sum1 += __shfl_xor_sync(0xffffffffu, sum1, 1);
        sum1 += __shfl_xor_sync(0xffffffffu, sum1, 2);
        lst0 = lst0 * al0 + sum0;  mst0 = mn0;
        lst1 = lst1 * al1 + sum1;  mst1 = mn1;
        #pragma unroll
        for (int j = 0; j < 16; ++j) {
            o[j][0] *= al0; o[j][1] *= al0;
            o[j][2] *= al1; o[j][3] *= al1;
        }

        // ---- stage P (warp-private rows; no block sync needed) ----
        #pragma unroll
        for (int j = 0; j < 8; ++j) {
            *(float2*)&sm.P[rb + r][8 * j + 2 * c]     = make_float2(s[j][0], s[j][1]);
            *(float2*)&sm.P[rb + r + 8][8 * j + 2 * c] = make_float2(s[j][2], s[j][3]);
        }
        __syncwarp();

        // ---- O += P @ V ----
        #pragma unroll 4
        for (int kk = 0; kk < 8; ++kk) {
            const uint32_t a0 = __float_as_uint(sm.P[rb + r][8 * kk + c]);
            const uint32_t a1 = __float_as_uint(sm.P[rb + r + 8][8 * kk + c]);
            const uint32_t a2 = __float_as_uint(sm.P[rb + r][8 * kk + c + 4]);
            const uint32_t a3 = __float_as_uint(sm.P[rb + r + 8][8 * kk + c + 4]);
            #pragma unroll
            for (int j = 0; j < 16; ++j) {
                const uint32_t b0 = __float_as_uint(sm.V[8 * kk + c][8 * j + r]);
                const uint32_t b1 = __float_as_uint(sm.V[8 * kk + c + 4][8 * j + r]);
                MMA_TF32(o[j], a0, a1, a2, a3, b0, b1);
            }
        }
        __syncwarp();
    }

    // ---- normalize + write ctx (plain fp32; dense GEMM re-splits) ----
    const float il0 = 1.0f / lst0, il1 = 1.0f / lst1;
    const int trow = mb * ABM + rb + r;
    #pragma unroll
    for (int j = 0; j < 16; ++j) {
        const int col = head * HEAD_DIM + 8 * j + 2 * c;
        *(float2*)&g_ctx[(size_t)trow * HIDDEN + col] =
            make_float2(o[j][0] * il0, o[j][1] * il0);
        *(float2*)&g_ctx[(size_t)(trow + 8) * HIDDEN + col] =
            make_float2(o[j][2] * il1, o[j][3] * il1);
    }
}

// =======================================================================
// launch
// =======================================================================
extern "C" void kernel_launch(void* const* d_in, const int* in_sizes, int n_in,
                              void* d_out, int out_size)
{
    const int*   positions = (const int*)d_in[0];
    const float* hidden    = (const float*)d_in[1];
    const float* w_qkv     = (const float*)d_in[2];
    const float* b_qkv     = (const float*)d_in[3];
    const float* w_dense   = (const float*)d_in[4];
    float*       out       = (float*)d_out;

    float *qkv_p, *ctx_p;
    cudaGetSymbolAddress((void**)&qkv_p, g_qkv);
    cudaGetSymbolAddress((void**)&ctx_p, g_ctx);

    cudaFuncSetAttribute(gemm_tc<true>,
                         cudaFuncAttributeMaxDynamicSharedMemorySize, GEMM_SMEM);
    cudaFuncSetAttribute(gemm_tc<false>,
                         cudaFuncAttributeMaxDynamicSharedMemorySize, GEMM_SMEM);
    cudaFuncSetAttribute(attn_tc,
                         cudaFuncAttributeMaxDynamicSharedMemorySize,
                         (int)sizeof(AttnSmem));

    // 1) QKV = hidden @ w_qkv + b_qkv   (bf16x3 tensor cores)
    gemm_tc<true><<<dim3(QKV_DIM / 128, T_SEQ / 128), 256, GEMM_SMEM>>>(
        hidden, w_qkv, b_qkv, qkv_p, T_SEQ, QKV_DIM, HIDDEN);

    // 2) RoPE in place
    const int totalRope = T_SEQ * NUM_HEADS * 32 + T_SEQ * KV_GROUPS * 32;
    rope_kernel<<<(totalRope + 255) / 256, 256>>>(positions);

    // 3) causal GQA flash attention (tf32 tensor cores) -> g_ctx
    attn_tc<<<dim3(T_SEQ / ABM, NUM_HEADS), 256, sizeof(AttnSmem)>>>();

    // 4) out = ctx @ w_dense   (bf16x3 tensor cores)
    gemm_tc<false><<<dim3(HIDDEN / 128, T_SEQ / 128), 256, GEMM_SMEM>>>(
        ctx_p, w_dense, nullptr, out, T_SEQ, HIDDEN, HIDDEN);
}

// round 5
// speedup vs baseline: 2.3129x; 1.0697x over previous
#include <cuda_runtime.h>
#include <math.h>
#include <stdint.h>

// ---------------- problem constants ----------------
#define T_SEQ      2048
#define HIDDEN     4096
#define NUM_HEADS  32
#define HEAD_DIM   128
#define KV_GROUPS  2
#define Q_SZ       (NUM_HEADS * HEAD_DIM)              // 4096
#define KV_SZ      (KV_GROUPS * HEAD_DIM)              // 256
#define QKV_DIM    (Q_SZ + 2 * KV_SZ)                  // 4608
#define GQA_REP    (NUM_HEADS / KV_GROUPS)             // 16

// ---------------- scratch (static device memory; no allocs allowed) ----
__device__ float    g_qkv[(size_t)T_SEQ * QKV_DIM];         // ~37.7 MB
__device__ float    g_ctx[(size_t)T_SEQ * HIDDEN];          // ~33.6 MB
__device__ uint32_t g_ahi[(size_t)T_SEQ * HIDDEN / 2];      // A hi plane (bf16 pairs)
__device__ uint32_t g_alo[(size_t)T_SEQ * HIDDEN / 2];
__device__ uint32_t g_bhi[(size_t)(HIDDEN / 2) * QKV_DIM];  // B hi plane (k-pair packed)
__device__ uint32_t g_blo[(size_t)(HIDDEN / 2) * QKV_DIM];

// =======================================================================
// helpers
// =======================================================================
__device__ __forceinline__ uint32_t smem_u32(const void* p) {
    uint32_t a;
    asm("{ .reg .u64 t; cvta.to.shared.u64 t, %1; cvt.u32.u64 %0, t; }"
        : "=r"(a) : "l"(p));
    return a;
}
__device__ __forceinline__ float f_tf32(float x) {
    uint32_t r;
    asm("cvt.rna.tf32.f32 %0, %1;" : "=r"(r) : "f"(x));
    return __uint_as_float(r);
}
__device__ __forceinline__ float4 f4_tf32(float4 v) {
    v.x = f_tf32(v.x); v.y = f_tf32(v.y);
    v.z = f_tf32(v.z); v.w = f_tf32(v.w);
    return v;
}
// split (x0,x1) into packed bf16 hi pair and lo (residual) pair; x0 low half
__device__ __forceinline__ void bsplit(float x0, float x1,
                                       uint32_t& hi, uint32_t& lo) {
    uint32_t h;
    asm("cvt.rn.bf16x2.f32 %0, %1, %2;" : "=r"(h) : "f"(x1), "f"(x0));
    const float h0 = __uint_as_float(h << 16);
    const float h1 = __uint_as_float(h & 0xffff0000u);
    asm("cvt.rn.bf16x2.f32 %0, %1, %2;" : "=r"(lo) : "f"(x1 - h1), "f"(x0 - h0));
    hi = h;
}
__device__ __forceinline__ void cp16(uint32_t dst, const void* src) {
    asm volatile("cp.async.cg.shared.global [%0], [%1], 16;"
                 :: "r"(dst), "l"(src));
}
__device__ __forceinline__ void cp_commit() {
    asm volatile("cp.async.commit_group;" ::: "memory");
}
template <int NREM> __device__ __forceinline__ void cp_wait() {
    asm volatile("cp.async.wait_group %0;" :: "n"(NREM) : "memory");
}

#define MMA_TF32(d, a0, a1, a2, a3, b0, b1)                                   \
    asm volatile(                                                             \
        "mma.sync.aligned.m16n8k8.row.col.f32.tf32.tf32.f32 "                 \
        "{%0,%1,%2,%3}, {%4,%5,%6,%7}, {%8,%9}, {%0,%1,%2,%3};"               \
        : "+f"((d)[0]), "+f"((d)[1]), "+f"((d)[2]), "+f"((d)[3])              \
        : "r"(a0), "r"(a1), "r"(a2), "r"(a3), "r"(b0), "r"(b1))

#define MMA_BF16(d, a0, a1, a2, a3, b0, b1)                                   \
    asm volatile(                                                             \
        "mma.sync.aligned.m16n8k16.row.col.f32.bf16.bf16.f32 "                \
        "{%0,%1,%2,%3}, {%4,%5,%6,%7}, {%8,%9}, {%0,%1,%2,%3};"               \
        : "+f"((d)[0]), "+f"((d)[1]), "+f"((d)[2]), "+f"((d)[3])              \
        : "r"(a0), "r"(a1), "r"(a2), "r"(a3), "r"(b0), "r"(b1))

// =======================================================================
// split passes
// =======================================================================
// row-major pairs (A planes): hi/lo[i] = bsplit(src[2i], src[2i+1])
__global__ void split_pairs(const float2* __restrict__ src,
                            uint32_t* __restrict__ hi,
                            uint32_t* __restrict__ lo, int total2)
{
    const int i = blockIdx.x * blockDim.x + threadIdx.x;
    if (i >= total2) return;
    const float2 v = src[i];
    uint32_t h, l;
    bsplit(v.x, v.y, h, l);
    hi[i] = h;
    lo[i] = l;
}
// B planes: pack k-pairs. out[k2*N + n] = bsplit(B[2k2][n], B[2k2+1][n])
__global__ void split_bmat(const float* __restrict__ B,
                           uint32_t* __restrict__ hi,
                           uint32_t* __restrict__ lo, int K2, int N)
{
    const int i = blockIdx.x * blockDim.x + threadIdx.x;
    if (i >= K2 * N) return;
    const int k2 = i / N, n = i - k2 * N;
    const float x0 = B[(size_t)(2 * k2) * N + n];
    const float x1 = B[(size_t)(2 * k2 + 1) * N + n];
    uint32_t h, l;
    bsplit(x0, x1, h, l);
    hi[i] = h;
    lo[i] = l;
}

// =======================================================================
// bf16x3 tensor-core GEMM on pre-split planes.
// C[M,N] = A @ B (+bias);  acc += AhiBhi + AhiBlo + AloBhi.
// CTA 128x128, K-slab 32 (16 k-pairs), 8 warps (64x32 each),
// cp.async 4-stage pipeline, zero conversion math in the mainloop.
// =======================================================================
#define NSTAGE  4
#define GKP     16                         // k-pairs per slab
#define APW     20                         // A pitch (words): 16 + 4 pad
#define BPW     136                        // B pitch (words): 128 + 8 pad
#define A_PL    (128 * APW)                // 2560 words
#define B_PL    (GKP * BPW)                // 2176 words
#define STG_W   (2 * A_PL + 2 * B_PL)      // 9472 words
#define GEMM_SMEM (NSTAGE * STG_W * 4)     // 151552 B

template <bool HAS_BIAS>
__global__ void __launch_bounds__(256)
gemm_tc(const uint32_t* __restrict__ Ahi, const uint32_t* __restrict__ Alo,
        const uint32_t* __restrict__ Bhi, const uint32_t* __restrict__ Blo,
        const float* __restrict__ bias, float* __restrict__ C,
        int M, int N, int K)
{
    extern __shared__ uint32_t smw[];
    const uint32_t sbase = smem_u32(smw);

    const int tid  = threadIdx.x;
    const int lane = tid & 31;
    const int wid  = tid >> 5;
    const int wm   = (wid & 1) * 64;
    const int wn   = (wid >> 1) * 32;
    const int r    = lane >> 2;
    const int c    = lane & 3;
    const int mBase = blockIdx.y * 128;
    const int nBase = blockIdx.x * 128;
    const int K2    = K >> 1;

    auto load_slab = [&](int s, int kt) {
        const int k2_0 = kt * GKP;
        const uint32_t st = sbase + (uint32_t)(s * STG_W) * 4u;
        #pragma unroll
        for (int i = 0; i < 2; ++i) {                 // A: 512 16B chunks/plane
            const int id  = tid + 256 * i;
            const int row = id >> 2, ch = (id & 3) * 4;
            const size_t go = (size_t)(mBase + row) * K2 + k2_0 + ch;
            cp16(st + (uint32_t)(row * APW + ch) * 4u, Ahi + go);
            cp16(st + (uint32_t)(A_PL + row * APW + ch) * 4u, Alo + go);
        }
        #pragma unroll
        for (int i = 0; i < 2; ++i) {                 // B: 512 16B chunks/plane
            const int id  = tid + 256 * i;
            const int row = id >> 5, ch = (id & 31) * 4;
            const size_t go = (size_t)(k2_0 + row) * N + nBase + ch;
            cp16(st + (uint32_t)(2 * A_PL + row * BPW + ch) * 4u, Bhi + go);
            cp16(st + (uint32_t)(2 * A_PL + B_PL + row * BPW + ch) * 4u, Blo + go);
        }
    };

    float acc[4][4][4];
    #pragma unroll
    for (int mi = 0; mi < 4; ++mi)
        #pragma unroll
        for (int ni = 0; ni < 4; ++ni)
            #pragma unroll
            for (int q = 0; q < 4; ++q) acc[mi][ni][q] = 0.f;

    // prologue: fill NSTAGE-1 stages
    #pragma unroll
    for (int s = 0; s < NSTAGE - 1; ++s) {
        load_slab(s, s);
        cp_commit();
    }

    const int KT = K2 / GKP;
    for (int kt = 0; kt < KT; ++kt) {
        cp_wait<NSTAGE - 2>();
        __syncthreads();

        const int s = kt & (NSTAGE - 1);
        const uint32_t* ah = smw + s * STG_W;
        const uint32_t* al = ah + A_PL;
        const uint32_t* bh = ah + 2 * A_PL;
        const uint32_t* bl = bh + B_PL;

        #pragma unroll
        for (int t = 0; t < 2; ++t) {
            const int tp = t * 8;
            uint32_t afh[4][4], afl[4][4];
            #pragma unroll
            for (int mi = 0; mi < 4; ++mi) {
                const int ro = (wm + mi * 16 + r) * APW + tp + c;
                afh[mi][0] = ah[ro];     afh[mi][1] = ah[ro + 8 * APW];
                afh[mi][2] = ah[ro + 4]; afh[mi][3] = ah[ro + 8 * APW + 4];
                afl[mi][0] = al[ro];     afl[mi][1] = al[ro + 8 * APW];
                afl[mi][2] = al[ro + 4]; afl[mi][3] = al[ro + 8 * APW + 4];
            }
            #pragma unroll
            for (int ni = 0; ni < 4; ++ni) {
                const int n = wn + ni * 8 + r;
                const uint32_t bh0 = bh[(tp + c) * BPW + n];
                const uint32_t bh1 = bh[(tp + c + 4) * BPW + n];
                const uint32_t bl0 = bl[(tp + c) * BPW + n];
                const uint32_t bl1 = bl[(tp + c + 4) * BPW + n];
                #pragma unroll
                for (int mi = 0; mi < 4; ++mi) {
                    MMA_BF16(acc[mi][ni], afh[mi][0], afh[mi][1], afh[mi][2],
                             afh[mi][3], bh0, bh1);
                    MMA_BF16(acc[mi][ni], afh[mi][0], afh[mi][1], afh[mi][2],
                             afh[mi][3], bl0, bl1);
                    MMA_BF16(acc[mi][ni], afl[mi][0], afl[mi][1], afl[mi][2],
                             afl[mi][3], bh0, bh1);
                }
            }
        }

        const int nk = kt + NSTAGE - 1;
        if (nk < KT) load_slab(nk & (NSTAGE - 1), nk);
        cp_commit();
    }

    // ---- epilogue ----
    #pragma unroll
    for (int mi = 0; mi < 4; ++mi) {
        const int row0 = mBase + wm + mi * 16 + r;
        #pragma unroll
        for (int ni = 0; ni < 4; ++ni) {
            const int col = nBase + wn + ni * 8 + c * 2;
            float2 v0 = make_float2(acc[mi][ni][0], acc[mi][ni][1]);
            float2 v1 = make_float2(acc[mi][ni][2], acc[mi][ni][3]);
            if (HAS_BIAS) {
                const float2 bb = *(const float2*)&bias[col];
                v0.x += bb.x; v0.y += bb.y;
                v1.x += bb.x; v1.y += bb.y;
            }
            *(float2*)&C[(size_t)row0 * N + col] = v0;
            *(float2*)&C[(size_t)(row0 + 8) * N + col] = v1;
        }
    }
}

// =======================================================================
// RoPE (interleaved pairs), in-place on Q and K slices of g_qkv.
// =======================================================================
__global__ void rope_kernel(const int* __restrict__ positions)
{
    const int totalQ = T_SEQ * NUM_HEADS * 32;
    const int totalK = T_SEQ * KV_GROUPS * 32;
    int idx = blockIdx.x * blockDim.x + threadIdx.x;

    int t, p, col0;
    if (idx < totalQ) {
        p = idx & 31;
        int h = (idx >> 5) & (NUM_HEADS - 1);
        t = idx >> 10;
        col0 = h * HEAD_DIM + 2 * p;
    } else {
        int rr = idx - totalQ;
        if (rr >= totalK) return;
        p = rr & 31;
        int g = (rr >> 5) & (KV_GROUPS - 1);
        t = rr >> 6;
        col0 = Q_SZ + g * HEAD_DIM + 2 * p;
    }

    const float pos   = (float)positions[t];
    const float theta = powf(10000.0f, -(float)p * (1.0f / 32.0f));
    float sn, cs;
    sincosf(pos * theta, &sn, &cs);

    float* b = g_qkv + (size_t)t * QKV_DIM + col0;
    const float x0 = b[0], x1 = b[1];
    b[0] = x0 * cs - x1 * sn;
    b[1] = x1 * cs + x0 * sn;
}

// =======================================================================
// Flash attention on tf32 mma.sync (unchanged from round 4, passing).
// =======================================================================
#define ABM 128
#define ABN 64

struct AttnSmem {
    float Q[ABM][132];
    float K[ABN][132];
    float V[ABN][132];
    float P[ABM][68];
};

__global__ __launch_bounds__(256)
void attn_tc()
{
    extern __shared__ char sraw[];
    AttnSmem& sm = *reinterpret_cast<AttnSmem*>(sraw);

    const int head = blockIdx.y;
    const int mb   = blockIdx.x;
    const int tid  = threadIdx.x;
    const int lane = tid & 31;
    const int wid  = tid >> 5;
    const int r    = lane >> 2;
    const int c    = lane & 3;
    const int rb   = wid * 16;
    const int g    = head / GQA_REP;
    const float scale = 0.08838834764831845f;   // 1/sqrt(128)

    for (int i = tid; i < ABM * 32; i += 256) {
        const int row = i >> 5, c4 = (i & 31) << 2;
        float4 v = *(const float4*)&g_qkv[(size_t)(mb * ABM + row) * QKV_DIM +
                                          head * HEAD_DIM + c4];
        v.x = f_tf32(v.x * scale); v.y = f_tf32(v.y * scale);
        v.z = f_tf32(v.z * scale); v.w = f_tf32(v.w * scale);
        *(float4*)&sm.Q[row][c4] = v;
    }

    float4 kr[8], vr[8];
    #pragma unroll
    for (int q = 0; q < 8; ++q) {
        const int i = tid + 256 * q;
        const int row = i >> 5, c4 = (i & 31) << 2;
        const size_t ro = (size_t)row * QKV_DIM + Q_SZ + g * HEAD_DIM;
        kr[q] = *(const float4*)&g_qkv[ro + c4];
        vr[q] = *(const float4*)&g_qkv[ro + KV_SZ + c4];
    }

    float o[16][4];
    #pragma unroll
    for (int j = 0; j < 16; ++j)
        #pragma unroll
        for (int q = 0; q < 4; ++q) o[j][q] = 0.f;
    float mst0 = -1e30f, mst1 = -1e30f, lst0 = 0.f, lst1 = 0.f;

    const int nbEnd = 2 * mb + 1;
    for (int nb = 0; nb <= nbEnd; ++nb) {
        __syncthreads();
        #pragma unroll
        for (int q = 0; q < 8; ++q) {
            const int i = tid + 256 * q;
            const int row = i >> 5, c4 = (i & 31) << 2;
            *(float4*)&sm.K[row][c4] = f4_tf32(kr[q]);
            *(float4*)&sm.V[row][c4] = f4_tf32(vr[q]);
        }
        __syncthreads();

        if (nb < nbEnd) {
            #pragma unroll
            for (int q = 0; q < 8; ++q) {
                const int i = tid + 256 * q;
                const int row = i >> 5, c4 = (i & 31) << 2;
                const size_t ro = (size_t)((nb + 1) * ABN + row) * QKV_DIM +
                                  Q_SZ + g * HEAD_DIM;
                kr[q] = *(const float4*)&g_qkv[ro + c4];
                vr[q] = *(const float4*)&g_qkv[ro + KV_SZ + c4];
            }
        }

        float s[8][4];
        #pragma unroll
        for (int j = 0; j < 8; ++j)
            #pragma unroll
            for (int q = 0; q < 4; ++q) s[j][q] = 0.f;

        #pragma unroll 4
        for (int k0 = 0; k0 < 16; ++k0) {
            const uint32_t a0 = __float_as_uint(sm.Q[rb + r][8 * k0 + c]);
            const uint32_t a1 = __float_as_uint(sm.Q[rb + r + 8][8 * k0 + c]);
            const uint32_t a2 = __float_as_uint(sm.Q[rb + r][8 * k0 + c + 4]);
            const uint32_t a3 = __float_as_uint(sm.Q[rb + r + 8][8 * k0 + c + 4]);
            #pragma unroll
            for (int j = 0; j < 8; ++j) {
                const uint32_t b0 = __float_as_uint(sm.K[8 * j + r][8 * k0 + c]);
                const uint32_t b1 = __float_as_uint(sm.K[8 * j + r][8 * k0 + c + 4]);
                MMA_TF32(s[j], a0, a1, a2, a3, b0, b1);
            }
        }

        if (nb >= 2 * mb) {
            const int row0 = mb * ABM + rb + r;
            #pragma unroll
            for (int j = 0; j < 8; ++j) {
                const int col = nb * ABN + 8 * j + 2 * c;
                if (col     > row0)     s[j][0] = -1e30f;
                if (col + 1 > row0)     s[j][1] = -1e30f;
                if (col     > row0 + 8) s[j][2] = -1e30f;
                if (col + 1 > row0 + 8) s[j][3] = -1e30f;
            }
        }

        float mx0 = -1e30f, mx1 = -1e30f;
        #pragma unroll
        for (int j = 0; j < 8; ++j) {
            mx0 = fmaxf(mx0, fmaxf(s[j][0], s[j][1]));
            mx1 = fmaxf(mx1, fmaxf(s[j][2], s[j][3]));
        }
        mx0 = fmaxf(mx0, __shfl_xor_sync(0xffffffffu, mx0, 1));
        mx0 = fmaxf(mx0, __shfl_xor_sync(0xffffffffu, mx0, 2));
        mx1 = fmaxf(mx1, __shfl_xor_sync(0xffffffffu, mx1, 1));
        mx1 = fmaxf(mx1, __shfl_xor_sync(0xffffffffu, mx1, 2));
        const float mn0 = fmaxf(mst0, mx0), mn1 = fmaxf(mst1, mx1);
        const float al0 = __expf(mst0 - mn0), al1 = __expf(mst1 - mn1);
        float sum0 = 0.f, sum1 = 0.f;
        #pragma unroll
        for (int j = 0; j < 8; ++j) {
            s[j][0] = f_tf32(__expf(s[j][0] - mn0)); sum0 += s[j][0];
            s[j][1] = f_tf32(__expf(s[j][1] - mn0)); sum0 += s[j][1];
            s[j][2] = f_tf32(__expf(s[j][2] - mn1)); sum1 += s[j][2];
            s[j][3] = f_tf32(__expf(s[j][3] - mn1)); sum1 += s[j][3];
        }
        sum0 += __shfl_xor_sync(0xffffffffu, sum0, 1);
        sum0 += __shfl_xor_sync(0xffffffffu, sum0, 2);
        sum1 += __shfl_xor_sync(0xffffffffu, sum1, 1);
        sum1 += __shfl_xor_sync(0xffffffffu, sum1, 2);
        lst0 = lst0 * al0 + sum0;  mst0 = mn0;
        lst1 = lst1 * al1 + sum1;  mst1 = mn1;
        #pragma unroll
        for (int j = 0; j < 16; ++j) {
            o[j][0] *= al0; o[j][1] *= al0;
            o[j][2] *= al1; o[j][3] *= al1;
        }

        #pragma unroll
        for (int j = 0; j < 8; ++j) {
            *(float2*)&sm.P[rb + r][8 * j + 2 * c]     = make_float2(s[j][0], s[j][1]);
            *(float2*)&sm.P[rb + r + 8][8 * j + 2 * c] = make_float2(s[j][2], s[j][3]);
        }
        __syncwarp();

        #pragma unroll 4
        for (int kk = 0; kk < 8; ++kk) {
            const uint32_t a0 = __float_as_uint(sm.P[rb + r][8 * kk + c]);
            const uint32_t a1 = __float_as_uint(sm.P[rb + r + 8][8 * kk + c]);
            const uint32_t a2 = __float_as_uint(sm.P[rb + r][8 * kk + c + 4]);
            const uint32_t a3 = __float_as_uint(sm.P[rb + r + 8][8 * kk + c + 4]);
            #pragma unroll
            for (int j = 0; j < 16; ++j) {
                const uint32_t b0 = __float_as_uint(sm.V[8 * kk + c][8 * j + r]);
                const uint32_t b1 = __float_as_uint(sm.V[8 * kk + c + 4][8 * j + r]);
                MMA_TF32(o[j], a0, a1, a2, a3, b0, b1);
            }
        }
        __syncwarp();
    }

    const float il0 = 1.0f / lst0, il1 = 1.0f / lst1;
    const int trow = mb * ABM + rb + r;
    #pragma unroll
    for (int j = 0; j < 16; ++j) {
        const int col = head * HEAD_DIM + 8 * j + 2 * c;
        *(float2*)&g_ctx[(size_t)trow * HIDDEN + col] =
            make_float2(o[j][0] * il0, o[j][1] * il0);
        *(float2*)&g_ctx[(size_t)(trow + 8) * HIDDEN + col] =
            make_float2(o[j][2] * il1, o[j][3] * il1);
    }
}

// =======================================================================
// launch
// =======================================================================
extern "C" void kernel_launch(void* const* d_in, const int* in_sizes, int n_in,
                              void* d_out, int out_size)
{
    const int*   positions = (const int*)d_in[0];
    const float* hidden    = (const float*)d_in[1];
    const float* w_qkv     = (const float*)d_in[2];
    const float* b_qkv     = (const float*)d_in[3];
    const float* w_dense   = (const float*)d_in[4];
    float*       out       = (float*)d_out;

    float *qkv_p, *ctx_p;
    uint32_t *ahi, *alo, *bhi, *blo;
    cudaGetSymbolAddress((void**)&qkv_p, g_qkv);
    cudaGetSymbolAddress((void**)&ctx_p, g_ctx);
    cudaGetSymbolAddress((void**)&ahi,   g_ahi);
    cudaGetSymbolAddress((void**)&alo,   g_alo);
    cudaGetSymbolAddress((void**)&bhi,   g_bhi);
    cudaGetSymbolAddress((void**)&blo,   g_blo);

    cudaFuncSetAttribute(gemm_tc<true>,
                         cudaFuncAttributeMaxDynamicSharedMemorySize, GEMM_SMEM);
    cudaFuncSetAttribute(gemm_tc<false>,
                         cudaFuncAttributeMaxDynamicSharedMemorySize, GEMM_SMEM);
    cudaFuncSetAttribute(attn_tc,
                         cudaFuncAttributeMaxDynamicSharedMemorySize,
                         (int)sizeof(AttnSmem));

    const int aPairs = T_SEQ * HIDDEN / 2;

    // 1) split inputs, then QKV = hidden @ w_qkv + b_qkv
    split_pairs<<<(aPairs + 255) / 256, 256>>>(
        (const float2*)hidden, ahi, alo, aPairs);
    split_bmat<<<((HIDDEN / 2) * QKV_DIM + 255) / 256, 256>>>(
        w_qkv, bhi, blo, HIDDEN / 2, QKV_DIM);
    gemm_tc<true><<<dim3(QKV_DIM / 128, T_SEQ / 128), 256, GEMM_SMEM>>>(
        ahi, alo, bhi, blo, b_qkv, qkv_p, T_SEQ, QKV_DIM, HIDDEN);

    // 2) RoPE in place
    const int totalRope = T_SEQ * NUM_HEADS * 32 + T_SEQ * KV_GROUPS * 32;
    rope_kernel<<<(totalRope + 255) / 256, 256>>>(positions);

    // 3) causal GQA flash attention (tf32 tensor cores) -> g_ctx
    attn_tc<<<dim3(T_SEQ / ABM, NUM_HEADS), 256, sizeof(AttnSmem)>>>();

    // 4) split ctx / w_dense, then out = ctx @ w_dense
    split_pairs<<<(aPairs + 255) / 256, 256>>>(
        (const float2*)ctx_p, ahi, alo, aPairs);
    split_bmat<<<((HIDDEN / 2) * HIDDEN + 255) / 256, 256>>>(
        w_dense, bhi, blo, HIDDEN / 2, HIDDEN);
    gemm_tc<false><<<dim3(HIDDEN / 128, T_SEQ / 128), 256, GEMM_SMEM>>>(
        ahi, alo, bhi, blo, nullptr, out, T_SEQ, HIDDEN, HIDDEN);
}

// round 6
// speedup vs baseline: 2.5134x; 1.0867x over previous
#include <cuda_runtime.h>
#include <math.h>
#include <stdint.h>

// ---------------- problem constants ----------------
#define T_SEQ      2048
#define HIDDEN     4096
#define NUM_HEADS  32
#define HEAD_DIM   128
#define KV_GROUPS  2
#define Q_SZ       (NUM_HEADS * HEAD_DIM)              // 4096
#define KV_SZ      (KV_GROUPS * HEAD_DIM)              // 256
#define QKV_DIM    (Q_SZ + 2 * KV_SZ)                  // 4608
#define GQA_REP    (NUM_HEADS / KV_GROUPS)             // 16

// ---------------- scratch (static device memory; no allocs allowed) ----
__device__ float    g_qkv[(size_t)T_SEQ * QKV_DIM];         // ~37.7 MB
__device__ uint32_t g_ahi[(size_t)T_SEQ * HIDDEN / 2];      // A hi plane (bf16 pairs)
__device__ uint32_t g_alo[(size_t)T_SEQ * HIDDEN / 2];
__device__ uint32_t g_bhi[(size_t)(HIDDEN / 2) * QKV_DIM];  // B hi plane (k-pair packed)
__device__ uint32_t g_blo[(size_t)(HIDDEN / 2) * QKV_DIM];

// =======================================================================
// helpers
// =======================================================================
__device__ __forceinline__ uint32_t smem_u32(const void* p) {
    uint32_t a;
    asm("{ .reg .u64 t; cvta.to.shared.u64 t, %1; cvt.u32.u64 %0, t; }"
        : "=r"(a) : "l"(p));
    return a;
}
__device__ __forceinline__ float f_tf32(float x) {
    uint32_t r;
    asm("cvt.rna.tf32.f32 %0, %1;" : "=r"(r) : "f"(x));
    return __uint_as_float(r);
}
__device__ __forceinline__ float4 f4_tf32(float4 v) {
    v.x = f_tf32(v.x); v.y = f_tf32(v.y);
    v.z = f_tf32(v.z); v.w = f_tf32(v.w);
    return v;
}
// split (x0,x1) into packed bf16 hi pair and lo (residual) pair; x0 low half
__device__ __forceinline__ void bsplit(float x0, float x1,
                                       uint32_t& hi, uint32_t& lo) {
    uint32_t h;
    asm("cvt.rn.bf16x2.f32 %0, %1, %2;" : "=r"(h) : "f"(x1), "f"(x0));
    const float h0 = __uint_as_float(h << 16);
    const float h1 = __uint_as_float(h & 0xffff0000u);
    asm("cvt.rn.bf16x2.f32 %0, %1, %2;" : "=r"(lo) : "f"(x1 - h1), "f"(x0 - h0));
    hi = h;
}
__device__ __forceinline__ void cp16(uint32_t dst, const void* src) {
    asm volatile("cp.async.cg.shared.global [%0], [%1], 16;"
                 :: "r"(dst), "l"(src));
}
__device__ __forceinline__ void cp_commit() {
    asm volatile("cp.async.commit_group;" ::: "memory");
}
template <int NREM> __device__ __forceinline__ void cp_wait() {
    asm volatile("cp.async.wait_group %0;" :: "n"(NREM) : "memory");
}
__device__ __forceinline__ void ldsm4(uint32_t* f, uint32_t addr) {
    asm volatile("ldmatrix.sync.aligned.m8n8.x4.shared.b16 {%0,%1,%2,%3}, [%4];"
                 : "=r"(f[0]), "=r"(f[1]), "=r"(f[2]), "=r"(f[3]) : "r"(addr));
}

#define MMA_TF32(d, a0, a1, a2, a3, b0, b1)                                   \
    asm volatile(                                                             \
        "mma.sync.aligned.m16n8k8.row.col.f32.tf32.tf32.f32 "                 \
        "{%0,%1,%2,%3}, {%4,%5,%6,%7}, {%8,%9}, {%0,%1,%2,%3};"               \
        : "+f"((d)[0]), "+f"((d)[1]), "+f"((d)[2]), "+f"((d)[3])              \
        : "r"(a0), "r"(a1), "r"(a2), "r"(a3), "r"(b0), "r"(b1))

#define MMA_BF16(d, a0, a1, a2, a3, b0, b1)                                   \
    asm volatile(                                                             \
        "mma.sync.aligned.m16n8k16.row.col.f32.bf16.bf16.f32 "                \
        "{%0,%1,%2,%3}, {%4,%5,%6,%7}, {%8,%9}, {%0,%1,%2,%3};"               \
        : "+f"((d)[0]), "+f"((d)[1]), "+f"((d)[2]), "+f"((d)[3])              \
        : "r"(a0), "r"(a1), "r"(a2), "r"(a3), "r"(b0), "r"(b1))

// =======================================================================
// split passes
// =======================================================================
__global__ void split_pairs(const float2* __restrict__ src,
                            uint32_t* __restrict__ hi,
                            uint32_t* __restrict__ lo, int total2)
{
    const int i = blockIdx.x * blockDim.x + threadIdx.x;
    if (i >= total2) return;
    const float2 v = src[i];
    uint32_t h, l;
    bsplit(v.x, v.y, h, l);
    hi[i] = h;
    lo[i] = l;
}
// B planes: out[k2*N + n] = bsplit(B[2k2][n], B[2k2+1][n])
__global__ void split_bmat(const float* __restrict__ B,
                           uint32_t* __restrict__ hi,
                           uint32_t* __restrict__ lo, int K2, int N)
{
    const int i = blockIdx.x * blockDim.x + threadIdx.x;
    if (i >= K2 * N) return;
    const int k2 = i / N, n = i - k2 * N;
    const float x0 = B[(size_t)(2 * k2) * N + n];
    const float x1 = B[(size_t)(2 * k2 + 1) * N + n];
    uint32_t h, l;
    bsplit(x0, x1, h, l);
    hi[i] = h;
    lo[i] = l;
}

// =======================================================================
// bf16x3 tensor-core GEMM on pre-split planes.
// CTA 128x128, K-slab 64 (32 k-pairs), 3 cp.async stages, 8 warps (64x32).
// A frags via ldmatrix.x4; acc += AhiBhi + AhiBlo + AloBhi.
// =======================================================================
#define NSTAGE  3
#define GKP     32                         // k-pairs per slab (64 K-elems)
#define APW     36                         // A pitch (words): 32 + 4 pad
#define BPW     136                        // B pitch (words): 128 + 8 pad
#define A_PL    (128 * APW)                // 4608 words
#define B_PL    (GKP * BPW)                // 4352 words
#define STG_W   (2 * A_PL + 2 * B_PL)      // 17920 words
#define GEMM_SMEM (NSTAGE * STG_W * 4)     // 215040 B

template <bool HAS_BIAS>
__global__ void __launch_bounds__(256)
gemm_tc(const uint32_t* __restrict__ Ahi, const uint32_t* __restrict__ Alo,
        const uint32_t* __restrict__ Bhi, const uint32_t* __restrict__ Blo,
        const float* __restrict__ bias, float* __restrict__ C,
        int M, int N, int K)
{
    extern __shared__ uint32_t smw[];
    const uint32_t sbase = smem_u32(smw);

    const int tid  = threadIdx.x;
    const int lane = tid & 31;
    const int wid  = tid >> 5;
    const int wm   = (wid & 1) * 64;
    const int wn   = (wid >> 1) * 32;
    const int r    = lane >> 2;
    const int c    = lane & 3;
    const int mBase = blockIdx.y * 128;
    const int nBase = blockIdx.x * 128;
    const int K2    = K >> 1;

    // ldmatrix lane addressing for A frags
    const uint32_t lrow   = lane & 15;
    const uint32_t lchunk = (lane >> 4) * 16;   // byte offset (k8-15 half)

    auto load_slab = [&](int s, int kt) {
        const int k2_0 = kt * GKP;
        const uint32_t st = sbase + (uint32_t)(s * STG_W) * 4u;
        #pragma unroll
        for (int i = 0; i < 4; ++i) {                 // A: 1024 chunks/plane
            const int id  = tid + 256 * i;
            const int row = id >> 3, ch = (id & 7) * 4;
            const size_t go = (size_t)(mBase + row) * K2 + k2_0 + ch;
            cp16(st + (uint32_t)(row * APW + ch) * 4u, Ahi + go);
            cp16(st + (uint32_t)(A_PL + row * APW + ch) * 4u, Alo + go);
        }
        #pragma unroll
        for (int i = 0; i < 4; ++i) {                 // B: 1024 chunks/plane
            const int id  = tid + 256 * i;
            const int row = id >> 5, ch = (id & 31) * 4;
            const size_t go = (size_t)(k2_0 + row) * N + nBase + ch;
            cp16(st + (uint32_t)(2 * A_PL + row * BPW + ch) * 4u, Bhi + go);
            cp16(st + (uint32_t)(2 * A_PL + B_PL + row * BPW + ch) * 4u, Blo + go);
        }
    };

    float acc[4][4][4];
    #pragma unroll
    for (int mi = 0; mi < 4; ++mi)
        #pragma unroll
        for (int ni = 0; ni < 4; ++ni)
            #pragma unroll
            for (int q = 0; q < 4; ++q) acc[mi][ni][q] = 0.f;

    load_slab(0, 0); cp_commit();
    load_slab(1, 1); cp_commit();

    const int KT = K2 / GKP;   // 64
    int s = 0;
    for (int kt = 0; kt < KT; ++kt) {
        cp_wait<NSTAGE - 2>();
        __syncthreads();

        const uint32_t stA = sbase + (uint32_t)(s * STG_W) * 4u;
        const uint32_t* bh = smw + s * STG_W + 2 * A_PL;
        const uint32_t* bl = bh + B_PL;

        #pragma unroll
        for (int t = 0; t < 4; ++t) {
            const int tp = t * 8;
            uint32_t afh[4][4], afl[4][4];
            #pragma unroll
            for (int mi = 0; mi < 4; ++mi) {
                const uint32_t a = stA +
                    (uint32_t)(((wm + mi * 16 + lrow) * APW) + tp) * 4u + lchunk;
                ldsm4(afh[mi], a);
                ldsm4(afl[mi], a + A_PL * 4u);
            }
            #pragma unroll
            for (int ni = 0; ni < 4; ++ni) {
                const int n = wn + ni * 8 + r;
                const uint32_t bh0 = bh[(tp + c) * BPW + n];
                const uint32_t bh1 = bh[(tp + c + 4) * BPW + n];
                const uint32_t bl0 = bl[(tp + c) * BPW + n];
                const uint32_t bl1 = bl[(tp + c + 4) * BPW + n];
                #pragma unroll
                for (int mi = 0; mi < 4; ++mi) {
                    MMA_BF16(acc[mi][ni], afh[mi][0], afh[mi][1], afh[mi][2],
                             afh[mi][3], bh0, bh1);
                    MMA_BF16(acc[mi][ni], afh[mi][0], afh[mi][1], afh[mi][2],
                             afh[mi][3], bl0, bl1);
                    MMA_BF16(acc[mi][ni], afl[mi][0], afl[mi][1], afl[mi][2],
                             afl[mi][3], bh0, bh1);
                }
            }
        }

        const int nk = kt + NSTAGE - 1;
        if (nk < KT) {
            int sn = s + (NSTAGE - 1);
            if (sn >= NSTAGE) sn -= NSTAGE;
            load_slab(sn, nk);
        }
        cp_commit();
        if (++s == NSTAGE) s = 0;
    }

    // ---- epilogue ----
    #pragma unroll
    for (int mi = 0; mi < 4; ++mi) {
        const int row0 = mBase + wm + mi * 16 + r;
        #pragma unroll
        for (int ni = 0; ni < 4; ++ni) {
            const int col = nBase + wn + ni * 8 + c * 2;
            float2 v0 = make_float2(acc[mi][ni][0], acc[mi][ni][1]);
            float2 v1 = make_float2(acc[mi][ni][2], acc[mi][ni][3]);
            if (HAS_BIAS) {
                const float2 bb = *(const float2*)&bias[col];
                v0.x += bb.x; v0.y += bb.y;
                v1.x += bb.x; v1.y += bb.y;
            }
            *(float2*)&C[(size_t)row0 * N + col] = v0;
            *(float2*)&C[(size_t)(row0 + 8) * N + col] = v1;
        }
    }
}

// =======================================================================
// RoPE (interleaved pairs), in-place on Q and K slices of g_qkv.
// =======================================================================
__global__ void rope_kernel(const int* __restrict__ positions)
{
    const int totalQ = T_SEQ * NUM_HEADS * 32;
    const int totalK = T_SEQ * KV_GROUPS * 32;
    int idx = blockIdx.x * blockDim.x + threadIdx.x;

    int t, p, col0;
    if (idx < totalQ) {
        p = idx & 31;
        int h = (idx >> 5) & (NUM_HEADS - 1);
        t = idx >> 10;
        col0 = h * HEAD_DIM + 2 * p;
    } else {
        int rr = idx - totalQ;
        if (rr >= totalK) return;
        p = rr & 31;
        int g = (rr >> 5) & (KV_GROUPS - 1);
        t = rr >> 6;
        col0 = Q_SZ + g * HEAD_DIM + 2 * p;
    }

    const float pos   = (float)positions[t];
    const float theta = powf(10000.0f, -(float)p * (1.0f / 32.0f));
    float sn, cs;
    sincosf(pos * theta, &sn, &cs);

    float* b = g_qkv + (size_t)t * QKV_DIM + col0;
    const float x0 = b[0], x1 = b[1];
    b[0] = x0 * cs - x1 * sn;
    b[1] = x1 * cs + x0 * sn;
}

// =======================================================================
// Flash attention on tf32 mma.sync; epilogue writes ctx directly as
// bf16 hi/lo planes (feeds the dense GEMM, no separate split pass).
// =======================================================================
#define ABM 128
#define ABN 64

struct AttnSmem {
    float Q[ABM][132];
    float K[ABN][132];
    float V[ABN][132];
    float P[ABM][68];
};

__global__ __launch_bounds__(256)
void attn_tc(uint32_t* __restrict__ chi, uint32_t* __restrict__ clo)
{
    extern __shared__ char sraw[];
    AttnSmem& sm = *reinterpret_cast<AttnSmem*>(sraw);

    const int head = blockIdx.y;
    const int mb   = blockIdx.x;
    const int tid  = threadIdx.x;
    const int lane = tid & 31;
    const int wid  = tid >> 5;
    const int r    = lane >> 2;
    const int c    = lane & 3;
    const int rb   = wid * 16;
    const int g    = head / GQA_REP;
    const float scale = 0.08838834764831845f;   // 1/sqrt(128)

    for (int i = tid; i < ABM * 32; i += 256) {
        const int row = i >> 5, c4 = (i & 31) << 2;
        float4 v = *(const float4*)&g_qkv[(size_t)(mb * ABM + row) * QKV_DIM +
                                          head * HEAD_DIM + c4];
        v.x = f_tf32(v.x * scale); v.y = f_tf32(v.y * scale);
        v.z = f_tf32(v.z * scale); v.w = f_tf32(v.w * scale);
        *(float4*)&sm.Q[row][c4] = v;
    }

    float4 kr[8], vr[8];
    #pragma unroll
    for (int q = 0; q < 8; ++q) {
        const int i = tid + 256 * q;
        const int row = i >> 5, c4 = (i & 31) << 2;
        const size_t ro = (size_t)row * QKV_DIM + Q_SZ + g * HEAD_DIM;
        kr[q] = *(const float4*)&g_qkv[ro + c4];
        vr[q] = *(const float4*)&g_qkv[ro + KV_SZ + c4];
    }

    float o[16][4];
    #pragma unroll
    for (int j = 0; j < 16; ++j)
        #pragma unroll
        for (int q = 0; q < 4; ++q) o[j][q] = 0.f;
    float mst0 = -1e30f, mst1 = -1e30f, lst0 = 0.f, lst1 = 0.f;

    const int nbEnd = 2 * mb + 1;
    for (int nb = 0; nb <= nbEnd; ++nb) {
        __syncthreads();
        #pragma unroll
        for (int q = 0; q < 8; ++q) {
            const int i = tid + 256 * q;
            const int row = i >> 5, c4 = (i & 31) << 2;
            *(float4*)&sm.K[row][c4] = f4_tf32(kr[q]);
            *(float4*)&sm.V[row][c4] = f4_tf32(vr[q]);
        }
        __syncthreads();

        if (nb < nbEnd) {
            #pragma unroll
            for (int q = 0; q < 8; ++q) {
                const int i = tid + 256 * q;
                const int row = i >> 5, c4 = (i & 31) << 2;
                const size_t ro = (size_t)((nb + 1) * ABN + row) * QKV_DIM +
                                  Q_SZ + g * HEAD_DIM;
                kr[q] = *(const float4*)&g_qkv[ro + c4];
                vr[q] = *(const float4*)&g_qkv[ro + KV_SZ + c4];
            }
        }

        float s[8][4];
        #pragma unroll
        for (int j = 0; j < 8; ++j)
            #pragma unroll
            for (int q = 0; q < 4; ++q) s[j][q] = 0.f;

        #pragma unroll 4
        for (int k0 = 0; k0 < 16; ++k0) {
            const uint32_t a0 = __float_as_uint(sm.Q[rb + r][8 * k0 + c]);
            const uint32_t a1 = __float_as_uint(sm.Q[rb + r + 8][8 * k0 + c]);
            const uint32_t a2 = __float_as_uint(sm.Q[rb + r][8 * k0 + c + 4]);
            const uint32_t a3 = __float_as_uint(sm.Q[rb + r + 8][8 * k0 + c + 4]);
            #pragma unroll
            for (int j = 0; j < 8; ++j) {
                const uint32_t b0 = __float_as_uint(sm.K[8 * j + r][8 * k0 + c]);
                const uint32_t b1 = __float_as_uint(sm.K[8 * j + r][8 * k0 + c + 4]);
                MMA_TF32(s[j], a0, a1, a2, a3, b0, b1);
            }
        }

        if (nb >= 2 * mb) {
            const int row0 = mb * ABM + rb + r;
            #pragma unroll
            for (int j = 0; j < 8; ++j) {
                const int col = nb * ABN + 8 * j + 2 * c;
                if (col     > row0)     s[j][0] = -1e30f;
                if (col + 1 > row0)     s[j][1] = -1e30f;
                if (col     > row0 + 8) s[j][2] = -1e30f;
                if (col + 1 > row0 + 8) s[j][3] = -1e30f;
            }
        }

        float mx0 = -1e30f, mx1 = -1e30f;
        #pragma unroll
        for (int j = 0; j < 8; ++j) {
            mx0 = fmaxf(mx0, fmaxf(s[j][0], s[j][1]));
            mx1 = fmaxf(mx1, fmaxf(s[j][2], s[j][3]));
        }
        mx0 = fmaxf(mx0, __shfl_xor_sync(0xffffffffu, mx0, 1));
        mx0 = fmaxf(mx0, __shfl_xor_sync(0xffffffffu, mx0, 2));
        mx1 = fmaxf(mx1, __shfl_xor_sync(0xffffffffu, mx1, 1));
        mx1 = fmaxf(mx1, __shfl_xor_sync(0xffffffffu, mx1, 2));
        const float mn0 = fmaxf(mst0, mx0), mn1 = fmaxf(mst1, mx1);
        const float al0 = __expf(mst0 - mn0), al1 = __expf(mst1 - mn1);
        float sum0 = 0.f, sum1 = 0.f;
        #pragma unroll
        for (int j = 0; j < 8; ++j) {
            s[j][0] = f_tf32(__expf(s[j][0] - mn0)); sum0 += s[j][0];
            s[j][1] = f_tf32(__expf(s[j][1] - mn0)); sum0 += s[j][1];
            s[j][2] = f_tf32(__expf(s[j][2] - mn1)); sum1 += s[j][2];
            s[j][3] = f_tf32(__expf(s[j][3] - mn1)); sum1 += s[j][3];
        }
        sum0 += __shfl_xor_sync(0xffffffffu, sum0, 1);
        sum0 += __shfl_xor_sync(0xffffffffu, sum0, 2);
        sum1 += __shfl_xor_sync(0xffffffffu, sum1, 1);
        sum1 += __shfl_xor_sync(0xffffffffu, sum1, 2);
        lst0 = lst0 * al0 + sum0;  mst0 = mn0;
        lst1 = lst1 * al1 + sum1;  mst1 = mn1;
        #pragma unroll
        for (int j = 0; j < 16; ++j) {
            o[j][0] *= al0; o[j][1] *= al0;
            o[j][2] *= al1; o[j][3] *= al1;
        }

        #pragma unroll
        for (int j = 0; j < 8; ++j) {
            *(float2*)&sm.P[rb + r][8 * j + 2 * c]     = make_float2(s[j][0], s[j][1]);
            *(float2*)&sm.P[rb + r + 8][8 * j + 2 * c] = make_float2(s[j][2], s[j][3]);
        }
        __syncwarp();

        #pragma unroll 4
        for (int kk = 0; kk < 8; ++kk) {
            const uint32_t a0 = __float_as_uint(sm.P[rb + r][8 * kk + c]);
            const uint32_t a1 = __float_as_uint(sm.P[rb + r + 8][8 * kk + c]);
            const uint32_t a2 = __float_as_uint(sm.P[rb + r][8 * kk + c + 4]);
            const uint32_t a3 = __float_as_uint(sm.P[rb + r + 8][8 * kk + c + 4]);
            #pragma unroll
            for (int j = 0; j < 16; ++j) {
                const uint32_t b0 = __float_as_uint(sm.V[8 * kk + c][8 * j + r]);
                const uint32_t b1 = __float_as_uint(sm.V[8 * kk + c + 4][8 * j + r]);
                MMA_TF32(o[j], a0, a1, a2, a3, b0, b1);
            }
        }
        __syncwarp();
    }

    // ---- normalize + write ctx as pre-split bf16 hi/lo planes ----
    const float il0 = 1.0f / lst0, il1 = 1.0f / lst1;
    const int trow = mb * ABM + rb + r;
    #pragma unroll
    for (int j = 0; j < 16; ++j) {
        const int col = head * HEAD_DIM + 8 * j + 2 * c;    // even
        uint32_t h, l;
        bsplit(o[j][0] * il0, o[j][1] * il0, h, l);
        const size_t p0 = ((size_t)trow * HIDDEN + col) >> 1;
        chi[p0] = h; clo[p0] = l;
        bsplit(o[j][2] * il1, o[j][3] * il1, h, l);
        const size_t p1 = ((size_t)(trow + 8) * HIDDEN + col) >> 1;
        chi[p1] = h; clo[p1] = l;
    }
}

// =======================================================================
// launch
// =======================================================================
extern "C" void kernel_launch(void* const* d_in, const int* in_sizes, int n_in,
                              void* d_out, int out_size)
{
    const int*   positions = (const int*)d_in[0];
    const float* hidden    = (const float*)d_in[1];
    const float* w_qkv     = (const float*)d_in[2];
    const float* b_qkv     = (const float*)d_in[3];
    const float* w_dense   = (const float*)d_in[4];
    float*       out       = (float*)d_out;

    float *qkv_p;
    uint32_t *ahi, *alo, *bhi, *blo;
    cudaGetSymbolAddress((void**)&qkv_p, g_qkv);
    cudaGetSymbolAddress((void**)&ahi,   g_ahi);
    cudaGetSymbolAddress((void**)&alo,   g_alo);
    cudaGetSymbolAddress((void**)&bhi,   g_bhi);
    cudaGetSymbolAddress((void**)&blo,   g_blo);

    cudaFuncSetAttribute(gemm_tc<true>,
                         cudaFuncAttributeMaxDynamicSharedMemorySize, GEMM_SMEM);
    cudaFuncSetAttribute(gemm_tc<false>,
                         cudaFuncAttributeMaxDynamicSharedMemorySize, GEMM_SMEM);
    cudaFuncSetAttribute(attn_tc,
                         cudaFuncAttributeMaxDynamicSharedMemorySize,
                         (int)sizeof(AttnSmem));

    const int aPairs = T_SEQ * HIDDEN / 2;

    // 1) split inputs, then QKV = hidden @ w_qkv + b_qkv
    split_pairs<<<(aPairs + 255) / 256, 256>>>(
        (const float2*)hidden, ahi, alo, aPairs);
    split_bmat<<<((HIDDEN / 2) * QKV_DIM + 255) / 256, 256>>>(
        w_qkv, bhi, blo, HIDDEN / 2, QKV_DIM);
    gemm_tc<true><<<dim3(QKV_DIM / 128, T_SEQ / 128), 256, GEMM_SMEM>>>(
        ahi, alo, bhi, blo, b_qkv, qkv_p, T_SEQ, QKV_DIM, HIDDEN);

    // 2) RoPE in place
    const int totalRope = T_SEQ * NUM_HEADS * 32 + T_SEQ * KV_GROUPS * 32;
    rope_kernel<<<(totalRope + 255) / 256, 256>>>(positions);

    // 3) attention -> ctx hi/lo planes (overwrites ahi/alo after QKV's last use)
    attn_tc<<<dim3(T_SEQ / ABM, NUM_HEADS), 256, sizeof(AttnSmem)>>>(ahi, alo);

    // 4) split w_dense, then out = ctx @ w_dense
    split_bmat<<<((HIDDEN / 2) * HIDDEN + 255) / 256, 256>>>(
        w_dense, bhi, blo, HIDDEN / 2, HIDDEN);
    gemm_tc<false><<<dim3(HIDDEN / 128, T_SEQ / 128), 256, GEMM_SMEM>>>(
        ahi, alo, bhi, blo, nullptr, out, T_SEQ, HIDDEN, HIDDEN);
}

// round 7
// speedup vs baseline: 2.8949x; 1.1518x over previous
#include <cuda_runtime.h>
#include <cuda.h>
#include <math.h>
#include <stdint.h>

// ---------------- problem constants ----------------
#define T_SEQ      2048
#define HIDDEN     4096
#define NUM_HEADS  32
#define HEAD_DIM   128
#define KV_GROUPS  2
#define Q_SZ       (NUM_HEADS * HEAD_DIM)              // 4096
#define KV_SZ      (KV_GROUPS * HEAD_DIM)              // 256
#define QKV_DIM    (Q_SZ + 2 * KV_SZ)                  // 4608
#define GQA_REP    (NUM_HEADS / KV_GROUPS)             // 16
#define K2DIM      (HIDDEN / 2)                        // 2048 k-pairs

// ---------------- scratch (static device memory; no allocs allowed) ----
__device__ float    g_qkv[(size_t)T_SEQ * QKV_DIM];         // ~37.7 MB
__device__ uint32_t g_ahi[(size_t)T_SEQ * K2DIM];           // A hi plane [T][K2]
__device__ uint32_t g_alo[(size_t)T_SEQ * K2DIM];
__device__ uint32_t g_bhi[(size_t)QKV_DIM * K2DIM];         // B^T hi plane [N][K2]
__device__ uint32_t g_blo[(size_t)QKV_DIM * K2DIM];

// =======================================================================
// helpers
// =======================================================================
__device__ __forceinline__ uint32_t smem_u32(const void* p) {
    uint32_t a;
    asm("{ .reg .u64 t; cvta.to.shared.u64 t, %1; cvt.u32.u64 %0, t; }"
        : "=r"(a) : "l"(p));
    return a;
}
__device__ __forceinline__ float f_tf32(float x) {
    uint32_t r;
    asm("cvt.rna.tf32.f32 %0, %1;" : "=r"(r) : "f"(x));
    return __uint_as_float(r);
}
__device__ __forceinline__ float4 f4_tf32(float4 v) {
    v.x = f_tf32(v.x); v.y = f_tf32(v.y);
    v.z = f_tf32(v.z); v.w = f_tf32(v.w);
    return v;
}
// split (x0,x1) into packed bf16 hi pair and lo (residual) pair; x0 low half
__device__ __forceinline__ void bsplit(float x0, float x1,
                                       uint32_t& hi, uint32_t& lo) {
    uint32_t h;
    asm("cvt.rn.bf16x2.f32 %0, %1, %2;" : "=r"(h) : "f"(x1), "f"(x0));
    const float h0 = __uint_as_float(h << 16);
    const float h1 = __uint_as_float(h & 0xffff0000u);
    asm("cvt.rn.bf16x2.f32 %0, %1, %2;" : "=r"(lo) : "f"(x1 - h1), "f"(x0 - h0));
    hi = h;
}
__device__ __forceinline__ void ldsm4(uint32_t* f, uint32_t addr) {
    asm volatile("ldmatrix.sync.aligned.m8n8.x4.shared.b16 {%0,%1,%2,%3}, [%4];"
                 : "=r"(f[0]), "=r"(f[1]), "=r"(f[2]), "=r"(f[3]) : "r"(addr));
}
__device__ __forceinline__ uint32_t sw128(uint32_t off) {
    return off ^ ((off >> 3) & 0x70);
}
__device__ __forceinline__ void mbar_init(uint32_t a, uint32_t cnt) {
    asm volatile("mbarrier.init.shared.b64 [%0], %1;" :: "r"(a), "r"(cnt) : "memory");
}
__device__ __forceinline__ void mbar_expect_tx(uint32_t a, uint32_t bytes) {
    asm volatile("mbarrier.arrive.expect_tx.shared.b64 _, [%0], %1;"
                 :: "r"(a), "r"(bytes) : "memory");
}
__device__ __forceinline__ void mbar_arrive(uint32_t a) {
    asm volatile("mbarrier.arrive.shared.b64 _, [%0];" :: "r"(a) : "memory");
}
__device__ __forceinline__ void mbar_wait(uint32_t a, uint32_t parity) {
    asm volatile(
        "{\n\t.reg .pred P;\n\t"
        "W_%=:\n\t"
        "mbarrier.try_wait.parity.shared.b64 P, [%0], %1;\n\t"
        "@!P bra W_%=;\n\t}"
        :: "r"(a), "r"(parity) : "memory");
}
__device__ __forceinline__ void tma2d(uint32_t dst, const CUtensorMap* m,
                                      int x, int y, uint32_t mbar) {
    asm volatile(
        "cp.async.bulk.tensor.2d.shared::cta.global.tile.mbarrier::complete_tx::bytes "
        "[%0], [%1, {%2, %3}], [%4];"
        :: "r"(dst), "l"(m), "r"(x), "r"(y), "r"(mbar) : "memory");
}

#define MMA_TF32(d, a0, a1, a2, a3, b0, b1)                                   \
    asm volatile(                                                             \
        "mma.sync.aligned.m16n8k8.row.col.f32.tf32.tf32.f32 "                 \
        "{%0,%1,%2,%3}, {%4,%5,%6,%7}, {%8,%9}, {%0,%1,%2,%3};"               \
        : "+f"((d)[0]), "+f"((d)[1]), "+f"((d)[2]), "+f"((d)[3])              \
        : "r"(a0), "r"(a1), "r"(a2), "r"(a3), "r"(b0), "r"(b1))

#define MMA_BF16(d, a0, a1, a2, a3, b0, b1)                                   \
    asm volatile(                                                             \
        "mma.sync.aligned.m16n8k16.row.col.f32.bf16.bf16.f32 "                \
        "{%0,%1,%2,%3}, {%4,%5,%6,%7}, {%8,%9}, {%0,%1,%2,%3};"               \
        : "+f"((d)[0]), "+f"((d)[1]), "+f"((d)[2]), "+f"((d)[3])              \
        : "r"(a0), "r"(a1), "r"(a2), "r"(a3), "r"(b0), "r"(b1))

// =======================================================================
// split passes
// =======================================================================
// A planes (row-major k-pairs): hi/lo[i] = bsplit(src[2i], src[2i+1])
__global__ void split_pairs(const float2* __restrict__ src,
                            uint32_t* __restrict__ hi,
                            uint32_t* __restrict__ lo, int total2)
{
    const int i = blockIdx.x * blockDim.x + threadIdx.x;
    if (i >= total2) return;
    const float2 v = src[i];
    uint32_t h, l;
    bsplit(v.x, v.y, h, l);
    hi[i] = h;
    lo[i] = l;
}
// B^T planes: BT[n][k2] = bsplit(B[2k2][n], B[2k2+1][n]); smem transpose.
__global__ void split_bmat_t(const float* __restrict__ B,
                             uint32_t* __restrict__ hiT,
                             uint32_t* __restrict__ loT, int K2, int N)
{
    __shared__ uint32_t th[32][33], tl[32][33];
    const int n0 = blockIdx.x * 32, k20 = blockIdx.y * 32;
    const int tx = threadIdx.x, ty = threadIdx.y;   // 32 x 8
    #pragma unroll
    for (int i = 0; i < 4; ++i) {
        const int k2 = ty + 8 * i;
        const float x0 = B[(size_t)(2 * (k20 + k2)) * N + n0 + tx];
        const float x1 = B[(size_t)(2 * (k20 + k2) + 1) * N + n0 + tx];
        uint32_t h, l;
        bsplit(x0, x1, h, l);
        th[k2][tx] = h;
        tl[k2][tx] = l;
    }
    __syncthreads();
    #pragma unroll
    for (int i = 0; i < 4; ++i) {
        const int n = ty + 8 * i;
        hiT[(size_t)(n0 + n) * K2 + k20 + tx] = th[tx][n];
        loT[(size_t)(n0 + n) * K2 + k20 + tx] = tl[tx][n];
    }
}

// =======================================================================
// bf16x3 tensor-core GEMM, TMA-fed.
// CTA 128x128, K-slab 64 elems (32 k-pairs), 3-stage mbarrier pipeline.
// Stage = 4 planes (Ahi, Alo, Bhi, Blo), each 128 rows x 128B, SW128.
// 8 warps (64x32 each); all frags via ldmatrix; acc += AhBh + AhBl + AlBh.
// =======================================================================
#define NS        3
#define PLANE_B   16384
#define STAGE_B   (4 * PLANE_B)               // 65536
#define GEMM_SMEM (NS * STAGE_B + 64)         // 196672
#define KT_SLABS  (K2DIM / 32)                // 64

template <bool HAS_BIAS>
__global__ void __launch_bounds__(256)
gemm_tma(const __grid_constant__ CUtensorMap mAhi,
         const __grid_constant__ CUtensorMap mAlo,
         const __grid_constant__ CUtensorMap mBhi,
         const __grid_constant__ CUtensorMap mBlo,
         const float* __restrict__ bias, float* __restrict__ C, int N)
{
    extern __shared__ __align__(1024) uint32_t smw[];
    const uint32_t sbase = smem_u32(smw);
    const uint32_t full0  = sbase + NS * STAGE_B;        // 3 x 8B
    const uint32_t empty0 = full0 + 24;                  // 3 x 8B

    const int tid  = threadIdx.x;
    const int lane = tid & 31;
    const int wid  = tid >> 5;
    const int wm   = (wid & 1) * 64;
    const int wn   = (wid >> 1) * 32;
    const int r    = lane >> 2;
    const int c    = lane & 3;
    const int mBase = blockIdx.y * 128;
    const int nBase = blockIdx.x * 128;

    // ldmatrix lane addressing
    const int arow = ((lane >> 3) & 1) * 8 + (lane & 7);
    const int achk = (lane >> 4) * 16;
    const int brow = ((lane >> 3) & 2) * 4 + (lane & 7);
    const int bchk = ((lane >> 3) & 1) * 16;

    if (tid == 0) {
        #pragma unroll
        for (int s = 0; s < NS; ++s) {
            mbar_init(full0 + 8 * s, 1);
            mbar_init(empty0 + 8 * s, 8);
        }
    }
    __syncthreads();

    auto issue_slab = [&](int s, int kt) {
        const uint32_t st = sbase + (uint32_t)s * STAGE_B;
        const uint32_t fb = full0 + 8 * s;
        mbar_expect_tx(fb, STAGE_B);
        tma2d(st,               &mAhi, kt * 32, mBase, fb);
        tma2d(st + PLANE_B,     &mAlo, kt * 32, mBase, fb);
        tma2d(st + 2 * PLANE_B, &mBhi, kt * 32, nBase, fb);
        tma2d(st + 3 * PLANE_B, &mBlo, kt * 32, nBase, fb);
    };

    if (tid == 0) {
        issue_slab(0, 0);
        issue_slab(1, 1);
    }

    float acc[4][4][4];
    #pragma unroll
    for (int mi = 0; mi < 4; ++mi)
        #pragma unroll
        for (int ni = 0; ni < 4; ++ni)
            #pragma unroll
            for (int q = 0; q < 4; ++q) acc[mi][ni][q] = 0.f;

    for (int kt = 0; kt < KT_SLABS; ++kt) {
        const int s = kt % NS;
        mbar_wait(full0 + 8 * s, (kt / NS) & 1);

        const uint32_t stg = sbase + (uint32_t)s * STAGE_B;
        #pragma unroll
        for (int t = 0; t < 4; ++t) {
            uint32_t afh[4][4], afl[4][4];
            #pragma unroll
            for (int mi = 0; mi < 4; ++mi) {
                const uint32_t a = stg +
                    sw128((uint32_t)((wm + mi * 16 + arow) * 128 + t * 32 + achk));
                ldsm4(afh[mi], a);
                ldsm4(afl[mi], a + PLANE_B);
            }
            uint32_t bfh[4][2], bfl[4][2];
            #pragma unroll
            for (int p = 0; p < 2; ++p) {
                const uint32_t b = stg + 2 * PLANE_B +
                    sw128((uint32_t)((wn + p * 16 + brow) * 128 + t * 32 + bchk));
                uint32_t tm[4];
                ldsm4(tm, b);
                bfh[2 * p][0] = tm[0]; bfh[2 * p][1] = tm[1];
                bfh[2 * p + 1][0] = tm[2]; bfh[2 * p + 1][1] = tm[3];
                ldsm4(tm, b + PLANE_B);
                bfl[2 * p][0] = tm[0]; bfl[2 * p][1] = tm[1];
                bfl[2 * p + 1][0] = tm[2]; bfl[2 * p + 1][1] = tm[3];
            }
            #pragma unroll
            for (int ni = 0; ni < 4; ++ni)
                #pragma unroll
                for (int mi = 0; mi < 4; ++mi) {
                    MMA_BF16(acc[mi][ni], afh[mi][0], afh[mi][1], afh[mi][2],
                             afh[mi][3], bfh[ni][0], bfh[ni][1]);
                    MMA_BF16(acc[mi][ni], afh[mi][0], afh[mi][1], afh[mi][2],
                             afh[mi][3], bfl[ni][0], bfl[ni][1]);
                    MMA_BF16(acc[mi][ni], afl[mi][0], afl[mi][1], afl[mi][2],
                             afl[mi][3], bfh[ni][0], bfh[ni][1]);
                }
        }

        __syncwarp();
        if (lane == 0) mbar_arrive(empty0 + 8 * s);

        if (tid == 0) {
            const int nk = kt + NS - 1;
            if (nk < KT_SLABS) {
                const int sn = nk % NS;
                if (nk >= NS) mbar_wait(empty0 + 8 * sn, (nk / NS - 1) & 1);
                issue_slab(sn, nk);
            }
        }
    }

    // ---- epilogue ----
    #pragma unroll
    for (int mi = 0; mi < 4; ++mi) {
        const int row0 = mBase + wm + mi * 16 + r;
        #pragma unroll
        for (int ni = 0; ni < 4; ++ni) {
            const int col = nBase + wn + ni * 8 + c * 2;
            float2 v0 = make_float2(acc[mi][ni][0], acc[mi][ni][1]);
            float2 v1 = make_float2(acc[mi][ni][2], acc[mi][ni][3]);
            if (HAS_BIAS) {
                const float2 bb = *(const float2*)&bias[col];
                v0.x += bb.x; v0.y += bb.y;
                v1.x += bb.x; v1.y += bb.y;
            }
            *(float2*)&C[(size_t)row0 * N + col] = v0;
            *(float2*)&C[(size_t)(row0 + 8) * N + col] = v1;
        }
    }
}

// =======================================================================
// RoPE (interleaved pairs), in-place on Q and K slices of g_qkv.
// =======================================================================
__global__ void rope_kernel(const int* __restrict__ positions)
{
    const int totalQ = T_SEQ * NUM_HEADS * 32;
    const int totalK = T_SEQ * KV_GROUPS * 32;
    int idx = blockIdx.x * blockDim.x + threadIdx.x;

    int t, p, col0;
    if (idx < totalQ) {
        p = idx & 31;
        int h = (idx >> 5) & (NUM_HEADS - 1);
        t = idx >> 10;
        col0 = h * HEAD_DIM + 2 * p;
    } else {
        int rr = idx - totalQ;
        if (rr >= totalK) return;
        p = rr & 31;
        int g = (rr >> 5) & (KV_GROUPS - 1);
        t = rr >> 6;
        col0 = Q_SZ + g * HEAD_DIM + 2 * p;
    }

    const float pos   = (float)positions[t];
    const float theta = powf(10000.0f, -(float)p * (1.0f / 32.0f));
    float sn, cs;
    sincosf(pos * theta, &sn, &cs);

    float* b = g_qkv + (size_t)t * QKV_DIM + col0;
    const float x0 = b[0], x1 = b[1];
    b[0] = x0 * cs - x1 * sn;
    b[1] = x1 * cs + x0 * sn;
}

// =======================================================================
// Flash attention on tf32 mma.sync; epilogue writes ctx directly as
// bf16 hi/lo planes (feeds the dense GEMM, no separate split pass).
// =======================================================================
#define ABM 128
#define ABN 64

struct AttnSmem {
    float Q[ABM][132];
    float K[ABN][132];
    float V[ABN][132];
    float P[ABM][68];
};

__global__ __launch_bounds__(256)
void attn_tc(uint32_t* __restrict__ chi, uint32_t* __restrict__ clo)
{
    extern __shared__ char sraw[];
    AttnSmem& sm = *reinterpret_cast<AttnSmem*>(sraw);

    const int head = blockIdx.y;
    const int mb   = blockIdx.x;
    const int tid  = threadIdx.x;
    const int lane = tid & 31;
    const int wid  = tid >> 5;
    const int r    = lane >> 2;
    const int c    = lane & 3;
    const int rb   = wid * 16;
    const int g    = head / GQA_REP;
    const float scale = 0.08838834764831845f;   // 1/sqrt(128)

    for (int i = tid; i < ABM * 32; i += 256) {
        const int row = i >> 5, c4 = (i & 31) << 2;
        float4 v = *(const float4*)&g_qkv[(size_t)(mb * ABM + row) * QKV_DIM +
                                          head * HEAD_DIM + c4];
        v.x = f_tf32(v.x * scale); v.y = f_tf32(v.y * scale);
        v.z = f_tf32(v.z * scale); v.w = f_tf32(v.w * scale);
        *(float4*)&sm.Q[row][c4] = v;
    }

    float4 kr[8], vr[8];
    #pragma unroll
    for (int q = 0; q < 8; ++q) {
        const int i = tid + 256 * q;
        const int row = i >> 5, c4 = (i & 31) << 2;
        const size_t ro = (size_t)row * QKV_DIM + Q_SZ + g * HEAD_DIM;
        kr[q] = *(const float4*)&g_qkv[ro + c4];
        vr[q] = *(const float4*)&g_qkv[ro + KV_SZ + c4];
    }

    float o[16][4];
    #pragma unroll
    for (int j = 0; j < 16; ++j)
        #pragma unroll
        for (int q = 0; q < 4; ++q) o[j][q] = 0.f;
    float mst0 = -1e30f, mst1 = -1e30f, lst0 = 0.f, lst1 = 0.f;

    const int nbEnd = 2 * mb + 1;
    for (int nb = 0; nb <= nbEnd; ++nb) {
        __syncthreads();
        #pragma unroll
        for (int q = 0; q < 8; ++q) {
            const int i = tid + 256 * q;
            const int row = i >> 5, c4 = (i & 31) << 2;
            *(float4*)&sm.K[row][c4] = f4_tf32(kr[q]);
            *(float4*)&sm.V[row][c4] = f4_tf32(vr[q]);
        }
        __syncthreads();

        if (nb < nbEnd) {
            #pragma unroll
            for (int q = 0; q < 8; ++q) {
                const int i = tid + 256 * q;
                const int row = i >> 5, c4 = (i & 31) << 2;
                const size_t ro = (size_t)((nb + 1) * ABN + row) * QKV_DIM +
                                  Q_SZ + g * HEAD_DIM;
                kr[q] = *(const float4*)&g_qkv[ro + c4];
                vr[q] = *(const float4*)&g_qkv[ro + KV_SZ + c4];
            }
        }

        float s[8][4];
        #pragma unroll
        for (int j = 0; j < 8; ++j)
            #pragma unroll
            for (int q = 0; q < 4; ++q) s[j][q] = 0.f;

        #pragma unroll 4
        for (int k0 = 0; k0 < 16; ++k0) {
            const uint32_t a0 = __float_as_uint(sm.Q[rb + r][8 * k0 + c]);
            const uint32_t a1 = __float_as_uint(sm.Q[rb + r + 8][8 * k0 + c]);
            const uint32_t a2 = __float_as_uint(sm.Q[rb + r][8 * k0 + c + 4]);
            const uint32_t a3 = __float_as_uint(sm.Q[rb + r + 8][8 * k0 + c + 4]);
            #pragma unroll
            for (int j = 0; j < 8; ++j) {
                const uint32_t b0 = __float_as_uint(sm.K[8 * j + r][8 * k0 + c]);
                const uint32_t b1 = __float_as_uint(sm.K[8 * j + r][8 * k0 + c + 4]);
                MMA_TF32(s[j], a0, a1, a2, a3, b0, b1);
            }
        }

        if (nb >= 2 * mb) {
            const int row0 = mb * ABM + rb + r;
            #pragma unroll
            for (int j = 0; j < 8; ++j) {
                const int col = nb * ABN + 8 * j + 2 * c;
                if (col     > row0)     s[j][0] = -1e30f;
                if (col + 1 > row0)     s[j][1] = -1e30f;
                if (col     > row0 + 8) s[j][2] = -1e30f;
                if (col + 1 > row0 + 8) s[j][3] = -1e30f;
            }
        }

        float mx0 = -1e30f, mx1 = -1e30f;
        #pragma unroll
        for (int j = 0; j < 8; ++j) {
            mx0 = fmaxf(mx0, fmaxf(s[j][0], s[j][1]));
            mx1 = fmaxf(mx1, fmaxf(s[j][2], s[j][3]));
        }
        mx0 = fmaxf(mx0, __shfl_xor_sync(0xffffffffu, mx0, 1));
        mx0 = fmaxf(mx0, __shfl_xor_sync(0xffffffffu, mx0, 2));
        mx1 = fmaxf(mx1, __shfl_xor_sync(0xffffffffu, mx1, 1));
        mx1 = fmaxf(mx1, __shfl_xor_sync(0xffffffffu, mx1, 2));
        const float mn0 = fmaxf(mst0, mx0), mn1 = fmaxf(mst1, mx1);
        const float al0 = __expf(mst0 - mn0), al1 = __expf(mst1 - mn1);
        float sum0 = 0.f, sum1 = 0.f;
        #pragma unroll
        for (int j = 0; j < 8; ++j) {
            s[j][0] = f_tf32(__expf(s[j][0] - mn0)); sum0 += s[j][0];
            s[j][1] = f_tf32(__expf(s[j][1] - mn0)); sum0 += s[j][1];
            s[j][2] = f_tf32(__expf(s[j][2] - mn1)); sum1 += s[j][2];
            s[j][3] = f_tf32(__expf(s[j][3] - mn1)); sum1 += s[j][3];
        }
        sum0 += __shfl_xor_sync(0xffffffffu, sum0, 1);
        sum0 += __shfl_xor_sync(0xffffffffu, sum0, 2);
        sum1 += __shfl_xor_sync(0xffffffffu, sum1, 1);
        sum1 += __shfl_xor_sync(0xffffffffu, sum1, 2);
        lst0 = lst0 * al0 + sum0;  mst0 = mn0;
        lst1 = lst1 * al1 + sum1;  mst1 = mn1;
        #pragma unroll
        for (int j = 0; j < 16; ++j) {
            o[j][0] *= al0; o[j][1] *= al0;
            o[j][2] *= al1; o[j][3] *= al1;
        }

        #pragma unroll
        for (int j = 0; j < 8; ++j) {
            *(float2*)&sm.P[rb + r][8 * j + 2 * c]     = make_float2(s[j][0], s[j][1]);
            *(float2*)&sm.P[rb + r + 8][8 * j + 2 * c] = make_float2(s[j][2], s[j][3]);
        }
        __syncwarp();

        #pragma unroll 4
        for (int kk = 0; kk < 8; ++kk) {
            const uint32_t a0 = __float_as_uint(sm.P[rb + r][8 * kk + c]);
            const uint32_t a1 = __float_as_uint(sm.P[rb + r + 8][8 * kk + c]);
            const uint32_t a2 = __float_as_uint(sm.P[rb + r][8 * kk + c + 4]);
            const uint32_t a3 = __float_as_uint(sm.P[rb + r + 8][8 * kk + c + 4]);
            #pragma unroll
            for (int j = 0; j < 16; ++j) {
                const uint32_t b0 = __float_as_uint(sm.V[8 * kk + c][8 * j + r]);
                const uint32_t b1 = __float_as_uint(sm.V[8 * kk + c + 4][8 * j + r]);
                MMA_TF32(o[j], a0, a1, a2, a3, b0, b1);
            }
        }
        __syncwarp();
    }

    // ---- normalize + write ctx as pre-split bf16 hi/lo planes ----
    const float il0 = 1.0f / lst0, il1 = 1.0f / lst1;
    const int trow = mb * ABM + rb + r;
    #pragma unroll
    for (int j = 0; j < 16; ++j) {
        const int col = head * HEAD_DIM + 8 * j + 2 * c;    // even
        uint32_t h, l;
        bsplit(o[j][0] * il0, o[j][1] * il0, h, l);
        const size_t p0 = ((size_t)trow * HIDDEN + col) >> 1;
        chi[p0] = h; clo[p0] = l;
        bsplit(o[j][2] * il1, o[j][3] * il1, h, l);
        const size_t p1 = ((size_t)(trow + 8) * HIDDEN + col) >> 1;
        chi[p1] = h; clo[p1] = l;
    }
}

// =======================================================================
// host side: tensormaps via runtime-resolved driver entry point
// =======================================================================
typedef CUresult (*tmap_encode_fn)(
    CUtensorMap*, CUtensorMapDataType, cuuint32_t, void*,
    const cuuint64_t*, const cuuint64_t*, const cuuint32_t*, const cuuint32_t*,
    CUtensorMapInterleave, CUtensorMapSwizzle, CUtensorMapL2promotion,
    CUtensorMapFloatOOBfill);

static tmap_encode_fn get_encoder()
{
    void* p = nullptr;
    cudaDriverEntryPointQueryResult qr;
#if CUDART_VERSION >= 12050
    cudaGetDriverEntryPointByVersion("cuTensorMapEncodeTiled", &p, 12000,
                                     cudaEnableDefault, &qr);
#else
    cudaGetDriverEntryPoint("cuTensorMapEncodeTiled", &p, cudaEnableDefault, &qr);
#endif
    return (tmap_encode_fn)p;
}

static void make_map(tmap_encode_fn enc, CUtensorMap* m, void* ptr,
                     uint64_t rows)
{
    cuuint64_t dims[2]    = {K2DIM, rows};
    cuuint64_t strides[1] = {K2DIM * sizeof(uint32_t)};
    cuuint32_t box[2]     = {32, 128};           // 128B inner = SW128 atom
    cuuint32_t es[2]      = {1, 1};
    enc(m, CU_TENSOR_MAP_DATA_TYPE_UINT32, 2, ptr, dims, strides, box, es,
        CU_TENSOR_MAP_INTERLEAVE_NONE, CU_TENSOR_MAP_SWIZZLE_128B,
        CU_TENSOR_MAP_L2_PROMOTION_L2_128B, CU_TENSOR_MAP_FLOAT_OOB_FILL_NONE);
}

extern "C" void kernel_launch(void* const* d_in, const int* in_sizes, int n_in,
                              void* d_out, int out_size)
{
    const int*   positions = (const int*)d_in[0];
    const float* hidden    = (const float*)d_in[1];
    const float* w_qkv     = (const float*)d_in[2];
    const float* b_qkv     = (const float*)d_in[3];
    const float* w_dense   = (const float*)d_in[4];
    float*       out       = (float*)d_out;

    float* qkv_p;
    uint32_t *ahi, *alo, *bhi, *blo;
    cudaGetSymbolAddress((void**)&qkv_p, g_qkv);
    cudaGetSymbolAddress((void**)&ahi,   g_ahi);
    cudaGetSymbolAddress((void**)&alo,   g_alo);
    cudaGetSymbolAddress((void**)&bhi,   g_bhi);
    cudaGetSymbolAddress((void**)&blo,   g_blo);

    tmap_encode_fn enc = get_encoder();
    CUtensorMap mAhi, mAlo, mBhi, mBlo;
    make_map(enc, &mAhi, ahi, T_SEQ);
    make_map(enc, &mAlo, alo, T_SEQ);
    make_map(enc, &mBhi, bhi, QKV_DIM);
    make_map(enc, &mBlo, blo, QKV_DIM);

    cudaFuncSetAttribute(gemm_tma<true>,
                         cudaFuncAttributeMaxDynamicSharedMemorySize, GEMM_SMEM);
    cudaFuncSetAttribute(gemm_tma<false>,
                         cudaFuncAttributeMaxDynamicSharedMemorySize, GEMM_SMEM);
    cudaFuncSetAttribute(attn_tc,
                         cudaFuncAttributeMaxDynamicSharedMemorySize,
                         (int)sizeof(AttnSmem));

    const int aPairs = T_SEQ * HIDDEN / 2;

    // 1) split inputs, then QKV = hidden @ w_qkv + b_qkv
    split_pairs<<<(aPairs + 255) / 256, 256>>>(
        (const float2*)hidden, ahi, alo, aPairs);
    split_bmat_t<<<dim3(QKV_DIM / 32, K2DIM / 32), dim3(32, 8)>>>(
        w_qkv, bhi, blo, K2DIM, QKV_DIM);
    gemm_tma<true><<<dim3(QKV_DIM / 128, T_SEQ / 128), 256, GEMM_SMEM>>>(
        mAhi, mAlo, mBhi, mBlo, b_qkv, qkv_p, QKV_DIM);

    // 2) RoPE in place
    const int totalRope = T_SEQ * NUM_HEADS * 32 + T_SEQ * KV_GROUPS * 32;
    rope_kernel<<<(totalRope + 255) / 256, 256>>>(positions);

    // 3) attention -> ctx hi/lo planes (reuses g_ahi/g_alo)
    attn_tc<<<dim3(T_SEQ / ABM, NUM_HEADS), 256, sizeof(AttnSmem)>>>(ahi, alo);

    // 4) split w_dense (transposed), then out = ctx @ w_dense
    split_bmat_t<<<dim3(HIDDEN / 32, K2DIM / 32), dim3(32, 8)>>>(
        w_dense, bhi, blo, K2DIM, HIDDEN);
    gemm_tma<false><<<dim3(HIDDEN / 128, T_SEQ / 128), 256, GEMM_SMEM>>>(
        mAhi, mAlo, mBhi, mBlo, nullptr, out, HIDDEN);
}

// round 8
// speedup vs baseline: 2.9704x; 1.0261x over previous
#include <cuda_runtime.h>
#include <cuda.h>
#include <math.h>
#include <stdint.h>

// ---------------- problem constants ----------------
#define T_SEQ      2048
#define HIDDEN     4096
#define NUM_HEADS  32
#define HEAD_DIM   128
#define KV_GROUPS  2
#define Q_SZ       (NUM_HEADS * HEAD_DIM)              // 4096
#define KV_SZ      (KV_GROUPS * HEAD_DIM)              // 256
#define QKV_DIM    (Q_SZ + 2 * KV_SZ)                  // 4608
#define GQA_REP    (NUM_HEADS / KV_GROUPS)             // 16
#define K2DIM      (HIDDEN / 2)                        // 2048 k-pairs

// ---------------- scratch (static device memory; no allocs allowed) ----
__device__ float    g_qkv[(size_t)T_SEQ * QKV_DIM];         // ~37.7 MB
__device__ uint32_t g_ahi[(size_t)T_SEQ * K2DIM];           // A hi plane [T][K2]
__device__ uint32_t g_alo[(size_t)T_SEQ * K2DIM];
__device__ uint32_t g_bhi[(size_t)QKV_DIM * K2DIM];         // B^T hi plane [N][K2]
__device__ uint32_t g_blo[(size_t)QKV_DIM * K2DIM];

// =======================================================================
// helpers
// =======================================================================
__device__ __forceinline__ uint32_t smem_u32(const void* p) {
    uint32_t a;
    asm("{ .reg .u64 t; cvta.to.shared.u64 t, %1; cvt.u32.u64 %0, t; }"
        : "=r"(a) : "l"(p));
    return a;
}
__device__ __forceinline__ float f_tf32(float x) {
    uint32_t r;
    asm("cvt.rna.tf32.f32 %0, %1;" : "=r"(r) : "f"(x));
    return __uint_as_float(r);
}
__device__ __forceinline__ float4 f4_tf32(float4 v) {
    v.x = f_tf32(v.x); v.y = f_tf32(v.y);
    v.z = f_tf32(v.z); v.w = f_tf32(v.w);
    return v;
}
// split (x0,x1) into packed bf16 hi pair and lo (residual) pair; x0 low half
__device__ __forceinline__ void bsplit(float x0, float x1,
                                       uint32_t& hi, uint32_t& lo) {
    uint32_t h;
    asm("cvt.rn.bf16x2.f32 %0, %1, %2;" : "=r"(h) : "f"(x1), "f"(x0));
    const float h0 = __uint_as_float(h << 16);
    const float h1 = __uint_as_float(h & 0xffff0000u);
    asm("cvt.rn.bf16x2.f32 %0, %1, %2;" : "=r"(lo) : "f"(x1 - h1), "f"(x0 - h0));
    hi = h;
}
__device__ __forceinline__ void ldsm4(uint32_t* f, uint32_t addr) {
    asm volatile("ldmatrix.sync.aligned.m8n8.x4.shared.b16 {%0,%1,%2,%3}, [%4];"
                 : "=r"(f[0]), "=r"(f[1]), "=r"(f[2]), "=r"(f[3]) : "r"(addr));
}
__device__ __forceinline__ uint32_t sw128(uint32_t off) {
    return off ^ ((off >> 3) & 0x70);
}
__device__ __forceinline__ void mbar_init(uint32_t a, uint32_t cnt) {
    asm volatile("mbarrier.init.shared.b64 [%0], %1;" :: "r"(a), "r"(cnt) : "memory");
}
__device__ __forceinline__ void mbar_expect_tx(uint32_t a, uint32_t bytes) {
    asm volatile("mbarrier.arrive.expect_tx.shared.b64 _, [%0], %1;"
                 :: "r"(a), "r"(bytes) : "memory");
}
__device__ __forceinline__ void mbar_arrive(uint32_t a) {
    asm volatile("mbarrier.arrive.shared.b64 _, [%0];" :: "r"(a) : "memory");
}
__device__ __forceinline__ void mbar_wait(uint32_t a, uint32_t parity) {
    asm volatile(
        "{\n\t.reg .pred P;\n\t"
        "W_%=:\n\t"
        "mbarrier.try_wait.parity.shared.b64 P, [%0], %1;\n\t"
        "@!P bra W_%=;\n\t}"
        :: "r"(a), "r"(parity) : "memory");
}
__device__ __forceinline__ void tma2d(uint32_t dst, const CUtensorMap* m,
                                      int x, int y, uint32_t mbar) {
    asm volatile(
        "cp.async.bulk.tensor.2d.shared::cta.global.tile.mbarrier::complete_tx::bytes "
        "[%0], [%1, {%2, %3}], [%4];"
        :: "r"(dst), "l"(m), "r"(x), "r"(y), "r"(mbar) : "memory");
}

#define MMA_TF32(d, a0, a1, a2, a3, b0, b1)                                   \
    asm volatile(                                                             \
        "mma.sync.aligned.m16n8k8.row.col.f32.tf32.tf32.f32 "                 \
        "{%0,%1,%2,%3}, {%4,%5,%6,%7}, {%8,%9}, {%0,%1,%2,%3};"               \
        : "+f"((d)[0]), "+f"((d)[1]), "+f"((d)[2]), "+f"((d)[3])              \
        : "r"(a0), "r"(a1), "r"(a2), "r"(a3), "r"(b0), "r"(b1))

#define MMA_BF16(d, a0, a1, a2, a3, b0, b1)                                   \
    asm volatile(                                                             \
        "mma.sync.aligned.m16n8k16.row.col.f32.bf16.bf16.f32 "                \
        "{%0,%1,%2,%3}, {%4,%5,%6,%7}, {%8,%9}, {%0,%1,%2,%3};"               \
        : "+f"((d)[0]), "+f"((d)[1]), "+f"((d)[2]), "+f"((d)[3])              \
        : "r"(a0), "r"(a1), "r"(a2), "r"(a3), "r"(b0), "r"(b1))

// =======================================================================
// split passes
// =======================================================================
__global__ void split_pairs(const float2* __restrict__ src,
                            uint32_t* __restrict__ hi,
                            uint32_t* __restrict__ lo, int total2)
{
    const int i = blockIdx.x * blockDim.x + threadIdx.x;
    if (i >= total2) return;
    const float2 v = src[i];
    uint32_t h, l;
    bsplit(v.x, v.y, h, l);
    hi[i] = h;
    lo[i] = l;
}
// B^T planes: BT[n][k2] = bsplit(B[2k2][n], B[2k2+1][n]); smem transpose.
__global__ void split_bmat_t(const float* __restrict__ B,
                             uint32_t* __restrict__ hiT,
                             uint32_t* __restrict__ loT, int K2, int N)
{
    __shared__ uint32_t th[32][33], tl[32][33];
    const int n0 = blockIdx.x * 32, k20 = blockIdx.y * 32;
    const int tx = threadIdx.x, ty = threadIdx.y;   // 32 x 8
    #pragma unroll
    for (int i = 0; i < 4; ++i) {
        const int k2 = ty + 8 * i;
        const float x0 = B[(size_t)(2 * (k20 + k2)) * N + n0 + tx];
        const float x1 = B[(size_t)(2 * (k20 + k2) + 1) * N + n0 + tx];
        uint32_t h, l;
        bsplit(x0, x1, h, l);
        th[k2][tx] = h;
        tl[k2][tx] = l;
    }
    __syncthreads();
    #pragma unroll
    for (int i = 0; i < 4; ++i) {
        const int n = ty + 8 * i;
        hiT[(size_t)(n0 + n) * K2 + k20 + tx] = th[tx][n];
        loT[(size_t)(n0 + n) * K2 + k20 + tx] = tl[tx][n];
    }
}

// =======================================================================
// bf16x3 tensor-core GEMM, TMA-fed.
// CTA 128x256, K-slab 64 elems (32 k-pairs), 2-stage mbarrier pipeline
// (next slab's TMA issued BEFORE compute so it overlaps).
// Stage = Ahi/Alo (128x128B) + Bhi/Blo (256x128B), SW128.  8 warps, each
// 64x64; all frags via ldmatrix; acc += AhBh + AhBl + AlBh.
// =======================================================================
#define NS        2
#define PLANE_A   16384
#define PLANE_BB  32768
#define STAGE_B   (2 * PLANE_A + 2 * PLANE_BB)   // 98304
#define GEMM_SMEM (NS * STAGE_B + 64)            // 196672
#define KT_SLABS  (K2DIM / 32)                   // 64

template <bool HAS_BIAS>
__global__ void __launch_bounds__(256)
gemm_tma(const __grid_constant__ CUtensorMap mAhi,
         const __grid_constant__ CUtensorMap mAlo,
         const __grid_constant__ CUtensorMap mBhi,
         const __grid_constant__ CUtensorMap mBlo,
         const float* __restrict__ bias, float* __restrict__ C, int N)
{
    extern __shared__ __align__(1024) uint32_t smw[];
    const uint32_t sbase = smem_u32(smw);
    const uint32_t full0  = sbase + NS * STAGE_B;        // 2 x 8B
    const uint32_t empty0 = full0 + 16;                  // 2 x 8B

    const int tid  = threadIdx.x;
    const int lane = tid & 31;
    const int wid  = tid >> 5;
    const int wm   = (wid & 1) * 64;
    const int wn   = (wid >> 1) * 64;
    const int r    = lane >> 2;
    const int c    = lane & 3;
    const int mBase = blockIdx.y * 128;
    const int nBase = blockIdx.x * 256;

    // ldmatrix lane addressing
    const int arow = ((lane >> 3) & 1) * 8 + (lane & 7);
    const int achk = (lane >> 4) * 16;
    const int brow = ((lane >> 3) & 2) * 4 + (lane & 7);
    const int bchk = ((lane >> 3) & 1) * 16;

    if (tid == 0) {
        #pragma unroll
        for (int s = 0; s < NS; ++s) {
            mbar_init(full0 + 8 * s, 1);
            mbar_init(empty0 + 8 * s, 8);
        }
    }
    __syncthreads();

    auto issue_slab = [&](int s, int kt) {
        const uint32_t st = sbase + (uint32_t)s * STAGE_B;
        const uint32_t fb = full0 + 8 * s;
        mbar_expect_tx(fb, STAGE_B);
        tma2d(st,                          &mAhi, kt * 32, mBase, fb);
        tma2d(st + PLANE_A,                &mAlo, kt * 32, mBase, fb);
        tma2d(st + 2 * PLANE_A,            &mBhi, kt * 32, nBase, fb);
        tma2d(st + 2 * PLANE_A + 16384,    &mBhi, kt * 32, nBase + 128, fb);
        tma2d(st + 2 * PLANE_A + PLANE_BB, &mBlo, kt * 32, nBase, fb);
        tma2d(st + 2 * PLANE_A + PLANE_BB + 16384,
              &mBlo, kt * 32, nBase + 128, fb);
    };

    if (tid == 0) issue_slab(0, 0);

    float acc[4][8][4];
    #pragma unroll
    for (int mi = 0; mi < 4; ++mi)
        #pragma unroll
        for (int ni = 0; ni < 8; ++ni)
            #pragma unroll
            for (int q = 0; q < 4; ++q) acc[mi][ni][q] = 0.f;

    for (int kt = 0; kt < KT_SLABS; ++kt) {
        const int s = kt & 1;

        // issue next slab BEFORE compute so TMA overlaps this slab's math
        if (tid == 0) {
            const int nk = kt + 1;
            if (nk < KT_SLABS) {
                if (nk >= NS) mbar_wait(empty0 + 8 * (nk & 1), (nk / NS - 1) & 1);
                issue_slab(nk & 1, nk);
            }
        }

        mbar_wait(full0 + 8 * s, (kt / NS) & 1);

        const uint32_t stg = sbase + (uint32_t)s * STAGE_B;
        #pragma unroll
        for (int t = 0; t < 4; ++t) {
            uint32_t afh[4][4], afl[4][4];
            #pragma unroll
            for (int mi = 0; mi < 4; ++mi) {
                const uint32_t a = stg +
                    sw128((uint32_t)((wm + mi * 16 + arow) * 128 + t * 32 + achk));
                ldsm4(afh[mi], a);
                ldsm4(afl[mi], a + PLANE_A);
            }
            uint32_t bfh[8][2], bfl[8][2];
            #pragma unroll
            for (int p = 0; p < 4; ++p) {
                const uint32_t b = stg + 2 * PLANE_A +
                    sw128((uint32_t)((wn + p * 16 + brow) * 128 + t * 32 + bchk));
                uint32_t tm[4];
                ldsm4(tm, b);
                bfh[2 * p][0] = tm[0]; bfh[2 * p][1] = tm[1];
                bfh[2 * p + 1][0] = tm[2]; bfh[2 * p + 1][1] = tm[3];
                ldsm4(tm, b + PLANE_BB);
                bfl[2 * p][0] = tm[0]; bfl[2 * p][1] = tm[1];
                bfl[2 * p + 1][0] = tm[2]; bfl[2 * p + 1][1] = tm[3];
            }
            #pragma unroll
            for (int ni = 0; ni < 8; ++ni)
                #pragma unroll
                for (int mi = 0; mi < 4; ++mi) {
                    MMA_BF16(acc[mi][ni], afh[mi][0], afh[mi][1], afh[mi][2],
                             afh[mi][3], bfh[ni][0], bfh[ni][1]);
                    MMA_BF16(acc[mi][ni], afh[mi][0], afh[mi][1], afh[mi][2],
                             afh[mi][3], bfl[ni][0], bfl[ni][1]);
                    MMA_BF16(acc[mi][ni], afl[mi][0], afl[mi][1], afl[mi][2],
                             afl[mi][3], bfh[ni][0], bfh[ni][1]);
                }
        }

        __syncwarp();
        if (lane == 0) mbar_arrive(empty0 + 8 * s);
    }

    // ---- epilogue ----
    #pragma unroll
    for (int mi = 0; mi < 4; ++mi) {
        const int row0 = mBase + wm + mi * 16 + r;
        #pragma unroll
        for (int ni = 0; ni < 8; ++ni) {
            const int col = nBase + wn + ni * 8 + c * 2;
            float2 v0 = make_float2(acc[mi][ni][0], acc[mi][ni][1]);
            float2 v1 = make_float2(acc[mi][ni][2], acc[mi][ni][3]);
            if (HAS_BIAS) {
                const float2 bb = *(const float2*)&bias[col];
                v0.x += bb.x; v0.y += bb.y;
                v1.x += bb.x; v1.y += bb.y;
            }
            *(float2*)&C[(size_t)row0 * N + col] = v0;
            *(float2*)&C[(size_t)(row0 + 8) * N + col] = v1;
        }
    }
}

// =======================================================================
// RoPE (interleaved pairs), in-place on Q and K slices of g_qkv.
// =======================================================================
__global__ void rope_kernel(const int* __restrict__ positions)
{
    const int totalQ = T_SEQ * NUM_HEADS * 32;
    const int totalK = T_SEQ * KV_GROUPS * 32;
    int idx = blockIdx.x * blockDim.x + threadIdx.x;

    int t, p, col0;
    if (idx < totalQ) {
        p = idx & 31;
        int h = (idx >> 5) & (NUM_HEADS - 1);
        t = idx >> 10;
        col0 = h * HEAD_DIM + 2 * p;
    } else {
        int rr = idx - totalQ;
        if (rr >= totalK) return;
        p = rr & 31;
        int g = (rr >> 5) & (KV_GROUPS - 1);
        t = rr >> 6;
        col0 = Q_SZ + g * HEAD_DIM + 2 * p;
    }

    const float pos   = (float)positions[t];
    const float theta = powf(10000.0f, -(float)p * (1.0f / 32.0f));
    float sn, cs;
    sincosf(pos * theta, &sn, &cs);

    float* b = g_qkv + (size_t)t * QKV_DIM + col0;
    const float x0 = b[0], x1 = b[1];
    b[0] = x0 * cs - x1 * sn;
    b[1] = x1 * cs + x0 * sn;
}

// =======================================================================
// Flash attention on tf32 mma.sync; epilogue writes ctx directly as
// bf16 hi/lo planes (feeds the dense GEMM, no separate split pass).
// =======================================================================
#define ABM 128
#define ABN 64

struct AttnSmem {
    float Q[ABM][132];
    float K[ABN][132];
    float V[ABN][132];
    float P[ABM][68];
};

__global__ __launch_bounds__(256)
void attn_tc(uint32_t* __restrict__ chi, uint32_t* __restrict__ clo)
{
    extern __shared__ char sraw[];
    AttnSmem& sm = *reinterpret_cast<AttnSmem*>(sraw);

    const int head = blockIdx.y;
    const int mb   = blockIdx.x;
    const int tid  = threadIdx.x;
    const int lane = tid & 31;
    const int wid  = tid >> 5;
    const int r    = lane >> 2;
    const int c    = lane & 3;
    const int rb   = wid * 16;
    const int g    = head / GQA_REP;
    const float scale = 0.08838834764831845f;   // 1/sqrt(128)

    for (int i = tid; i < ABM * 32; i += 256) {
        const int row = i >> 5, c4 = (i & 31) << 2;
        float4 v = *(const float4*)&g_qkv[(size_t)(mb * ABM + row) * QKV_DIM +
                                          head * HEAD_DIM + c4];
        v.x = f_tf32(v.x * scale); v.y = f_tf32(v.y * scale);
        v.z = f_tf32(v.z * scale); v.w = f_tf32(v.w * scale);
        *(float4*)&sm.Q[row][c4] = v;
    }

    float4 kr[8], vr[8];
    #pragma unroll
    for (int q = 0; q < 8; ++q) {
        const int i = tid + 256 * q;
        const int row = i >> 5, c4 = (i & 31) << 2;
        const size_t ro = (size_t)row * QKV_DIM + Q_SZ + g * HEAD_DIM;
        kr[q] = *(const float4*)&g_qkv[ro + c4];
        vr[q] = *(const float4*)&g_qkv[ro + KV_SZ + c4];
    }

    float o[16][4];
    #pragma unroll
    for (int j = 0; j < 16; ++j)
        #pragma unroll
        for (int q = 0; q < 4; ++q) o[j][q] = 0.f;
    float mst0 = -1e30f, mst1 = -1e30f, lst0 = 0.f, lst1 = 0.f;

    const int nbEnd = 2 * mb + 1;
    for (int nb = 0; nb <= nbEnd; ++nb) {
        __syncthreads();
        #pragma unroll
        for (int q = 0; q < 8; ++q) {
            const int i = tid + 256 * q;
            const int row = i >> 5, c4 = (i & 31) << 2;
            *(float4*)&sm.K[row][c4] = f4_tf32(kr[q]);
            *(float4*)&sm.V[row][c4] = f4_tf32(vr[q]);
        }
        __syncthreads();

        if (nb < nbEnd) {
            #pragma unroll
            for (int q = 0; q < 8; ++q) {
                const int i = tid + 256 * q;
                const int row = i >> 5, c4 = (i & 31) << 2;
                const size_t ro = (size_t)((nb + 1) * ABN + row) * QKV_DIM +
                                  Q_SZ + g * HEAD_DIM;
                kr[q] = *(const float4*)&g_qkv[ro + c4];
                vr[q] = *(const float4*)&g_qkv[ro + KV_SZ + c4];
            }
        }

        float s[8][4];
        #pragma unroll
        for (int j = 0; j < 8; ++j)
            #pragma unroll
            for (int q = 0; q < 4; ++q) s[j][q] = 0.f;

        #pragma unroll 4
        for (int k0 = 0; k0 < 16; ++k0) {
            const uint32_t a0 = __float_as_uint(sm.Q[rb + r][8 * k0 + c]);
            const uint32_t a1 = __float_as_uint(sm.Q[rb + r + 8][8 * k0 + c]);
            const uint32_t a2 = __float_as_uint(sm.Q[rb + r][8 * k0 + c + 4]);
            const uint32_t a3 = __float_as_uint(sm.Q[rb + r + 8][8 * k0 + c + 4]);
            #pragma unroll
            for (int j = 0; j < 8; ++j) {
                const uint32_t b0 = __float_as_uint(sm.K[8 * j + r][8 * k0 + c]);
                const uint32_t b1 = __float_as_uint(sm.K[8 * j + r][8 * k0 + c + 4]);
                MMA_TF32(s[j], a0, a1, a2, a3, b0, b1);
            }
        }

        if (nb >= 2 * mb) {
            const int row0 = mb * ABM + rb + r;
            #pragma unroll
            for (int j = 0; j < 8; ++j) {
                const int col = nb * ABN + 8 * j + 2 * c;
                if (col     > row0)     s[j][0] = -1e30f;
                if (col + 1 > row0)     s[j][1] = -1e30f;
                if (col     > row0 + 8) s[j][2] = -1e30f;
                if (col + 1 > row0 + 8) s[j][3] = -1e30f;
            }
        }

        float mx0 = -1e30f, mx1 = -1e30f;
        #pragma unroll
        for (int j = 0; j < 8; ++j) {
            mx0 = fmaxf(mx0, fmaxf(s[j][0], s[j][1]));
            mx1 = fmaxf(mx1, fmaxf(s[j][2], s[j][3]));
        }
        mx0 = fmaxf(mx0, __shfl_xor_sync(0xffffffffu, mx0, 1));
        mx0 = fmaxf(mx0, __shfl_xor_sync(0xffffffffu, mx0, 2));
        mx1 = fmaxf(mx1, __shfl_xor_sync(0xffffffffu, mx1, 1));
        mx1 = fmaxf(mx1, __shfl_xor_sync(0xffffffffu, mx1, 2));
        const float mn0 = fmaxf(mst0, mx0), mn1 = fmaxf(mst1, mx1);
        const float al0 = __expf(mst0 - mn0), al1 = __expf(mst1 - mn1);
        float sum0 = 0.f, sum1 = 0.f;
        #pragma unroll
        for (int j = 0; j < 8; ++j) {
            s[j][0] = f_tf32(__expf(s[j][0] - mn0)); sum0 += s[j][0];
            s[j][1] = f_tf32(__expf(s[j][1] - mn0)); sum0 += s[j][1];
            s[j][2] = f_tf32(__expf(s[j][2] - mn1)); sum1 += s[j][2];
            s[j][3] = f_tf32(__expf(s[j][3] - mn1)); sum1 += s[j][3];
        }
        sum0 += __shfl_xor_sync(0xffffffffu, sum0, 1);
        sum0 += __shfl_xor_sync(0xffffffffu, sum0, 2);
        sum1 += __shfl_xor_sync(0xffffffffu, sum1, 1);
        sum1 += __shfl_xor_sync(0xffffffffu, sum1, 2);
        lst0 = lst0 * al0 + sum0;  mst0 = mn0;
        lst1 = lst1 * al1 + sum1;  mst1 = mn1;
        #pragma unroll
        for (int j = 0; j < 16; ++j) {
            o[j][0] *= al0; o[j][1] *= al0;
            o[j][2] *= al1; o[j][3] *= al1;
        }

        #pragma unroll
        for (int j = 0; j < 8; ++j) {
            *(float2*)&sm.P[rb + r][8 * j + 2 * c]     = make_float2(s[j][0], s[j][1]);
            *(float2*)&sm.P[rb + r + 8][8 * j + 2 * c] = make_float2(s[j][2], s[j][3]);
        }
        __syncwarp();

        #pragma unroll 4
        for (int kk = 0; kk < 8; ++kk) {
            const uint32_t a0 = __float_as_uint(sm.P[rb + r][8 * kk + c]);
            const uint32_t a1 = __float_as_uint(sm.P[rb + r + 8][8 * kk + c]);
            const uint32_t a2 = __float_as_uint(sm.P[rb + r][8 * kk + c + 4]);
            const uint32_t a3 = __float_as_uint(sm.P[rb + r + 8][8 * kk + c + 4]);
            #pragma unroll
            for (int j = 0; j < 16; ++j) {
                const uint32_t b0 = __float_as_uint(sm.V[8 * kk + c][8 * j + r]);
                const uint32_t b1 = __float_as_uint(sm.V[8 * kk + c + 4][8 * j + r]);
                MMA_TF32(o[j], a0, a1, a2, a3, b0, b1);
            }
        }
        __syncwarp();
    }

    // ---- normalize + write ctx as pre-split bf16 hi/lo planes ----
    const float il0 = 1.0f / lst0, il1 = 1.0f / lst1;
    const int trow = mb * ABM + rb + r;
    #pragma unroll
    for (int j = 0; j < 16; ++j) {
        const int col = head * HEAD_DIM + 8 * j + 2 * c;    // even
        uint32_t h, l;
        bsplit(o[j][0] * il0, o[j][1] * il0, h, l);
        const size_t p0 = ((size_t)trow * HIDDEN + col) >> 1;
        chi[p0] = h; clo[p0] = l;
        bsplit(o[j][2] * il1, o[j][3] * il1, h, l);
        const size_t p1 = ((size_t)(trow + 8) * HIDDEN + col) >> 1;
        chi[p1] = h; clo[p1] = l;
    }
}

// =======================================================================
// host side: tensormaps via runtime-resolved driver entry point
// =======================================================================
typedef CUresult (*tmap_encode_fn)(
    CUtensorMap*, CUtensorMapDataType, cuuint32_t, void*,
    const cuuint64_t*, const cuuint64_t*, const cuuint32_t*, const cuuint32_t*,
    CUtensorMapInterleave, CUtensorMapSwizzle, CUtensorMapL2promotion,
    CUtensorMapFloatOOBfill);

static tmap_encode_fn get_encoder()
{
    void* p = nullptr;
    cudaDriverEntryPointQueryResult qr;
#if CUDART_VERSION >= 12050
    cudaGetDriverEntryPointByVersion("cuTensorMapEncodeTiled", &p, 12000,
                                     cudaEnableDefault, &qr);
#else
    cudaGetDriverEntryPoint("cuTensorMapEncodeTiled", &p, cudaEnableDefault, &qr);
#endif
    return (tmap_encode_fn)p;
}

static void make_map(tmap_encode_fn enc, CUtensorMap* m, void* ptr,
                     uint64_t rows)
{
    cuuint64_t dims[2]    = {K2DIM, rows};
    cuuint64_t strides[1] = {K2DIM * sizeof(uint32_t)};
    cuuint32_t box[2]     = {32, 128};           // 128B inner = SW128 atom
    cuuint32_t es[2]      = {1, 1};
    enc(m, CU_TENSOR_MAP_DATA_TYPE_UINT32, 2, ptr, dims, strides, box, es,
        CU_TENSOR_MAP_INTERLEAVE_NONE, CU_TENSOR_MAP_SWIZZLE_128B,
        CU_TENSOR_MAP_L2_PROMOTION_L2_128B, CU_TENSOR_MAP_FLOAT_OOB_FILL_NONE);
}

extern "C" void kernel_launch(void* const* d_in, const int* in_sizes, int n_in,
                              void* d_out, int out_size)
{
    const int*   positions = (const int*)d_in[0];
    const float* hidden    = (const float*)d_in[1];
    const float* w_qkv     = (const float*)d_in[2];
    const float* b_qkv     = (const float*)d_in[3];
    const float* w_dense   = (const float*)d_in[4];
    float*       out       = (float*)d_out;

    float* qkv_p;
    uint32_t *ahi, *alo, *bhi, *blo;
    cudaGetSymbolAddress((void**)&qkv_p, g_qkv);
    cudaGetSymbolAddress((void**)&ahi,   g_ahi);
    cudaGetSymbolAddress((void**)&alo,   g_alo);
    cudaGetSymbolAddress((void**)&bhi,   g_bhi);
    cudaGetSymbolAddress((void**)&blo,   g_blo);

    tmap_encode_fn enc = get_encoder();
    CUtensorMap mAhi, mAlo, mBhi, mBlo;
    make_map(enc, &mAhi, ahi, T_SEQ);
    make_map(enc, &mAlo, alo, T_SEQ);
    make_map(enc, &mBhi, bhi, QKV_DIM);
    make_map(enc, &mBlo, blo, QKV_DIM);

    cudaFuncSetAttribute(gemm_tma<true>,
                         cudaFuncAttributeMaxDynamicSharedMemorySize, GEMM_SMEM);
    cudaFuncSetAttribute(gemm_tma<false>,
                         cudaFuncAttributeMaxDynamicSharedMemorySize, GEMM_SMEM);
    cudaFuncSetAttribute(attn_tc,
                         cudaFuncAttributeMaxDynamicSharedMemorySize,
                         (int)sizeof(AttnSmem));

    const int aPairs = T_SEQ * HIDDEN / 2;

    // 1) split inputs, then QKV = hidden @ w_qkv + b_qkv
    split_pairs<<<(aPairs + 255) / 256, 256>>>(
        (const float2*)hidden, ahi, alo, aPairs);
    split_bmat_t<<<dim3(QKV_DIM / 32, K2DIM / 32), dim3(32, 8)>>>(
        w_qkv, bhi, blo, K2DIM, QKV_DIM);
    gemm_tma<true><<<dim3(QKV_DIM / 256, T_SEQ / 128), 256, GEMM_SMEM>>>(
        mAhi, mAlo, mBhi, mBlo, b_qkv, qkv_p, QKV_DIM);

    // 2) RoPE in place
    const int totalRope = T_SEQ * NUM_HEADS * 32 + T_SEQ * KV_GROUPS * 32;
    rope_kernel<<<(totalRope + 255) / 256, 256>>>(positions);

    // 3) attention -> ctx hi/lo planes (reuses g_ahi/g_alo)
    attn_tc<<<dim3(T_SEQ / ABM, NUM_HEADS), 256, sizeof(AttnSmem)>>>(ahi, alo);

    // 4) split w_dense (transposed), then out = ctx @ w_dense
    split_bmat_t<<<dim3(HIDDEN / 32, K2DIM / 32), dim3(32, 8)>>>(
        w_dense, bhi, blo, K2DIM, HIDDEN);
    gemm_tma<false><<<dim3(HIDDEN / 256, T_SEQ / 128), 256, GEMM_SMEM>>>(
        mAhi, mAlo, mBhi, mBlo, nullptr, out, HIDDEN);
}

// round 9
// speedup vs baseline: 3.1454x; 1.0589x over previous
#include <cuda_runtime.h>
#include <cuda.h>
#include <math.h>
#include <stdint.h>

// ---------------- problem constants ----------------
#define T_SEQ      2048
#define HIDDEN     4096
#define NUM_HEADS  32
#define HEAD_DIM   128
#define KV_GROUPS  2
#define Q_SZ       (NUM_HEADS * HEAD_DIM)              // 4096
#define KV_SZ      (KV_GROUPS * HEAD_DIM)              // 256
#define QKV_DIM    (Q_SZ + 2 * KV_SZ)                  // 4608
#define GQA_REP    (NUM_HEADS / KV_GROUPS)             // 16
#define K2DIM      (HIDDEN / 2)                        // 2048 k-pairs

// ---------------- scratch (static device memory; no allocs allowed) ----
__device__ float    g_qkv[(size_t)T_SEQ * QKV_DIM];         // ~37.7 MB
__device__ uint32_t g_ahi[(size_t)T_SEQ * K2DIM];           // A hi plane [T][K2]
__device__ uint32_t g_alo[(size_t)T_SEQ * K2DIM];
__device__ uint32_t g_bhi[(size_t)QKV_DIM * K2DIM];         // B^T hi plane [N][K2]
__device__ uint32_t g_blo[(size_t)QKV_DIM * K2DIM];

// =======================================================================
// helpers
// =======================================================================
__device__ __forceinline__ uint32_t smem_u32(const void* p) {
    uint32_t a;
    asm("{ .reg .u64 t; cvta.to.shared.u64 t, %1; cvt.u32.u64 %0, t; }"
        : "=r"(a) : "l"(p));
    return a;
}
__device__ __forceinline__ float f_tf32(float x) {
    uint32_t r;
    asm("cvt.rna.tf32.f32 %0, %1;" : "=r"(r) : "f"(x));
    return __uint_as_float(r);
}
__device__ __forceinline__ float4 f4_tf32(float4 v) {
    v.x = f_tf32(v.x); v.y = f_tf32(v.y);
    v.z = f_tf32(v.z); v.w = f_tf32(v.w);
    return v;
}
// split (x0,x1) into packed bf16 hi pair and lo (residual) pair; x0 low half
__device__ __forceinline__ void bsplit(float x0, float x1,
                                       uint32_t& hi, uint32_t& lo) {
    uint32_t h;
    asm("cvt.rn.bf16x2.f32 %0, %1, %2;" : "=r"(h) : "f"(x1), "f"(x0));
    const float h0 = __uint_as_float(h << 16);
    const float h1 = __uint_as_float(h & 0xffff0000u);
    asm("cvt.rn.bf16x2.f32 %0, %1, %2;" : "=r"(lo) : "f"(x1 - h1), "f"(x0 - h0));
    hi = h;
}
__device__ __forceinline__ void ldsm4(uint32_t* f, uint32_t addr) {
    asm volatile("ldmatrix.sync.aligned.m8n8.x4.shared.b16 {%0,%1,%2,%3}, [%4];"
                 : "=r"(f[0]), "=r"(f[1]), "=r"(f[2]), "=r"(f[3]) : "r"(addr));
}
__device__ __forceinline__ uint32_t sw128(uint32_t off) {
    return off ^ ((off >> 3) & 0x70);
}
__device__ __forceinline__ void mbar_init(uint32_t a, uint32_t cnt) {
    asm volatile("mbarrier.init.shared.b64 [%0], %1;" :: "r"(a), "r"(cnt) : "memory");
}
__device__ __forceinline__ void mbar_expect_tx(uint32_t a, uint32_t bytes) {
    asm volatile("mbarrier.arrive.expect_tx.shared.b64 _, [%0], %1;"
                 :: "r"(a), "r"(bytes) : "memory");
}
__device__ __forceinline__ void mbar_arrive(uint32_t a) {
    asm volatile("mbarrier.arrive.shared.b64 _, [%0];" :: "r"(a) : "memory");
}
__device__ __forceinline__ void mbar_wait(uint32_t a, uint32_t parity) {
    asm volatile(
        "{\n\t.reg .pred P;\n\t"
        "W_%=:\n\t"
        "mbarrier.try_wait.parity.shared.b64 P, [%0], %1;\n\t"
        "@!P bra W_%=;\n\t}"
        :: "r"(a), "r"(parity) : "memory");
}
__device__ __forceinline__ void tma2d(uint32_t dst, const CUtensorMap* m,
                                      int x, int y, uint32_t mbar) {
    asm volatile(
        "cp.async.bulk.tensor.2d.shared::cta.global.tile.mbarrier::complete_tx::bytes "
        "[%0], [%1, {%2, %3}], [%4];"
        :: "r"(dst), "l"(m), "r"(x), "r"(y), "r"(mbar) : "memory");
}

#define MMA_TF32(d, a0, a1, a2, a3, b0, b1)                                   \
    asm volatile(                                                             \
        "mma.sync.aligned.m16n8k8.row.col.f32.tf32.tf32.f32 "                 \
        "{%0,%1,%2,%3}, {%4,%5,%6,%7}, {%8,%9}, {%0,%1,%2,%3};"               \
        : "+f"((d)[0]), "+f"((d)[1]), "+f"((d)[2]), "+f"((d)[3])              \
        : "r"(a0), "r"(a1), "r"(a2), "r"(a3), "r"(b0), "r"(b1))

#define MMA_BF16(d, a0, a1, a2, a3, b0, b1)                                   \
    asm volatile(                                                             \
        "mma.sync.aligned.m16n8k16.row.col.f32.bf16.bf16.f32 "                \
        "{%0,%1,%2,%3}, {%4,%5,%6,%7}, {%8,%9}, {%0,%1,%2,%3};"               \
        : "+f"((d)[0]), "+f"((d)[1]), "+f"((d)[2]), "+f"((d)[3])              \
        : "r"(a0), "r"(a1), "r"(a2), "r"(a3), "r"(b0), "r"(b1))

// =======================================================================
// split passes
// =======================================================================
__global__ void split_pairs(const float2* __restrict__ src,
                            uint32_t* __restrict__ hi,
                            uint32_t* __restrict__ lo, int total2)
{
    const int i = blockIdx.x * blockDim.x + threadIdx.x;
    if (i >= total2) return;
    const float2 v = src[i];
    uint32_t h, l;
    bsplit(v.x, v.y, h, l);
    hi[i] = h;
    lo[i] = l;
}
// B^T planes: BT[n][k2] = bsplit(B[2k2][n], B[2k2+1][n]); smem transpose.
__global__ void split_bmat_t(const float* __restrict__ B,
                             uint32_t* __restrict__ hiT,
                             uint32_t* __restrict__ loT, int K2, int N)
{
    __shared__ uint32_t th[32][33], tl[32][33];
    const int n0 = blockIdx.x * 32, k20 = blockIdx.y * 32;
    const int tx = threadIdx.x, ty = threadIdx.y;   // 32 x 8
    #pragma unroll
    for (int i = 0; i < 4; ++i) {
        const int k2 = ty + 8 * i;
        const float x0 = B[(size_t)(2 * (k20 + k2)) * N + n0 + tx];
        const float x1 = B[(size_t)(2 * (k20 + k2) + 1) * N + n0 + tx];
        uint32_t h, l;
        bsplit(x0, x1, h, l);
        th[k2][tx] = h;
        tl[k2][tx] = l;
    }
    __syncthreads();
    #pragma unroll
    for (int i = 0; i < 4; ++i) {
        const int n = ty + 8 * i;
        hiT[(size_t)(n0 + n) * K2 + k20 + tx] = th[tx][n];
        loT[(size_t)(n0 + n) * K2 + k20 + tx] = tl[tx][n];
    }
}

// =======================================================================
// bf16x3 tensor-core GEMM, TMA-fed (unchanged from round 8).
// =======================================================================
#define NS        2
#define PLANE_A   16384
#define PLANE_BB  32768
#define STAGE_B   (2 * PLANE_A + 2 * PLANE_BB)   // 98304
#define GEMM_SMEM (NS * STAGE_B + 64)            // 196672
#define KT_SLABS  (K2DIM / 32)                   // 64

template <bool HAS_BIAS>
__global__ void __launch_bounds__(256)
gemm_tma(const __grid_constant__ CUtensorMap mAhi,
         const __grid_constant__ CUtensorMap mAlo,
         const __grid_constant__ CUtensorMap mBhi,
         const __grid_constant__ CUtensorMap mBlo,
         const float* __restrict__ bias, float* __restrict__ C, int N)
{
    extern __shared__ __align__(1024) uint32_t smw[];
    const uint32_t sbase = smem_u32(smw);
    const uint32_t full0  = sbase + NS * STAGE_B;
    const uint32_t empty0 = full0 + 16;

    const int tid  = threadIdx.x;
    const int lane = tid & 31;
    const int wid  = tid >> 5;
    const int wm   = (wid & 1) * 64;
    const int wn   = (wid >> 1) * 64;
    const int r    = lane >> 2;
    const int c    = lane & 3;
    const int mBase = blockIdx.y * 128;
    const int nBase = blockIdx.x * 256;

    const int arow = ((lane >> 3) & 1) * 8 + (lane & 7);
    const int achk = (lane >> 4) * 16;
    const int brow = ((lane >> 3) & 2) * 4 + (lane & 7);
    const int bchk = ((lane >> 3) & 1) * 16;

    if (tid == 0) {
        #pragma unroll
        for (int s = 0; s < NS; ++s) {
            mbar_init(full0 + 8 * s, 1);
            mbar_init(empty0 + 8 * s, 8);
        }
    }
    __syncthreads();

    auto issue_slab = [&](int s, int kt) {
        const uint32_t st = sbase + (uint32_t)s * STAGE_B;
        const uint32_t fb = full0 + 8 * s;
        mbar_expect_tx(fb, STAGE_B);
        tma2d(st,                          &mAhi, kt * 32, mBase, fb);
        tma2d(st + PLANE_A,                &mAlo, kt * 32, mBase, fb);
        tma2d(st + 2 * PLANE_A,            &mBhi, kt * 32, nBase, fb);
        tma2d(st + 2 * PLANE_A + 16384,    &mBhi, kt * 32, nBase + 128, fb);
        tma2d(st + 2 * PLANE_A + PLANE_BB, &mBlo, kt * 32, nBase, fb);
        tma2d(st + 2 * PLANE_A + PLANE_BB + 16384,
              &mBlo, kt * 32, nBase + 128, fb);
    };

    if (tid == 0) issue_slab(0, 0);

    float acc[4][8][4];
    #pragma unroll
    for (int mi = 0; mi < 4; ++mi)
        #pragma unroll
        for (int ni = 0; ni < 8; ++ni)
            #pragma unroll
            for (int q = 0; q < 4; ++q) acc[mi][ni][q] = 0.f;

    for (int kt = 0; kt < KT_SLABS; ++kt) {
        const int s = kt & 1;

        if (tid == 0) {
            const int nk = kt + 1;
            if (nk < KT_SLABS) {
                if (nk >= NS) mbar_wait(empty0 + 8 * (nk & 1), (nk / NS - 1) & 1);
                issue_slab(nk & 1, nk);
            }
        }

        mbar_wait(full0 + 8 * s, (kt / NS) & 1);

        const uint32_t stg = sbase + (uint32_t)s * STAGE_B;
        #pragma unroll
        for (int t = 0; t < 4; ++t) {
            uint32_t afh[4][4], afl[4][4];
            #pragma unroll
            for (int mi = 0; mi < 4; ++mi) {
                const uint32_t a = stg +
                    sw128((uint32_t)((wm + mi * 16 + arow) * 128 + t * 32 + achk));
                ldsm4(afh[mi], a);
                ldsm4(afl[mi], a + PLANE_A);
            }
            uint32_t bfh[8][2], bfl[8][2];
            #pragma unroll
            for (int p = 0; p < 4; ++p) {
                const uint32_t b = stg + 2 * PLANE_A +
                    sw128((uint32_t)((wn + p * 16 + brow) * 128 + t * 32 + bchk));
                uint32_t tm[4];
                ldsm4(tm, b);
                bfh[2 * p][0] = tm[0]; bfh[2 * p][1] = tm[1];
                bfh[2 * p + 1][0] = tm[2]; bfh[2 * p + 1][1] = tm[3];
                ldsm4(tm, b + PLANE_BB);
                bfl[2 * p][0] = tm[0]; bfl[2 * p][1] = tm[1];
                bfl[2 * p + 1][0] = tm[2]; bfl[2 * p + 1][1] = tm[3];
            }
            #pragma unroll
            for (int ni = 0; ni < 8; ++ni)
                #pragma unroll
                for (int mi = 0; mi < 4; ++mi) {
                    MMA_BF16(acc[mi][ni], afh[mi][0], afh[mi][1], afh[mi][2],
                             afh[mi][3], bfh[ni][0], bfh[ni][1]);
                    MMA_BF16(acc[mi][ni], afh[mi][0], afh[mi][1], afh[mi][2],
                             afh[mi][3], bfl[ni][0], bfl[ni][1]);
                    MMA_BF16(acc[mi][ni], afl[mi][0], afl[mi][1], afl[mi][2],
                             afl[mi][3], bfh[ni][0], bfh[ni][1]);
                }
        }

        __syncwarp();
        if (lane == 0) mbar_arrive(empty0 + 8 * s);
    }

    #pragma unroll
    for (int mi = 0; mi < 4; ++mi) {
        const int row0 = mBase + wm + mi * 16 + r;
        #pragma unroll
        for (int ni = 0; ni < 8; ++ni) {
            const int col = nBase + wn + ni * 8 + c * 2;
            float2 v0 = make_float2(acc[mi][ni][0], acc[mi][ni][1]);
            float2 v1 = make_float2(acc[mi][ni][2], acc[mi][ni][3]);
            if (HAS_BIAS) {
                const float2 bb = *(const float2*)&bias[col];
                v0.x += bb.x; v0.y += bb.y;
                v1.x += bb.x; v1.y += bb.y;
            }
            *(float2*)&C[(size_t)row0 * N + col] = v0;
            *(float2*)&C[(size_t)(row0 + 8) * N + col] = v1;
        }
    }
}

// =======================================================================
// RoPE (interleaved pairs), in-place on Q and K slices of g_qkv.
// =======================================================================
__global__ void rope_kernel(const int* __restrict__ positions)
{
    const int totalQ = T_SEQ * NUM_HEADS * 32;
    const int totalK = T_SEQ * KV_GROUPS * 32;
    int idx = blockIdx.x * blockDim.x + threadIdx.x;

    int t, p, col0;
    if (idx < totalQ) {
        p = idx & 31;
        int h = (idx >> 5) & (NUM_HEADS - 1);
        t = idx >> 10;
        col0 = h * HEAD_DIM + 2 * p;
    } else {
        int rr = idx - totalQ;
        if (rr >= totalK) return;
        p = rr & 31;
        int g = (rr >> 5) & (KV_GROUPS - 1);
        t = rr >> 6;
        col0 = Q_SZ + g * HEAD_DIM + 2 * p;
    }

    const float pos   = (float)positions[t];
    const float theta = powf(10000.0f, -(float)p * (1.0f / 32.0f));
    float sn, cs;
    sincosf(pos * theta, &sn, &cs);

    float* b = g_qkv + (size_t)t * QKV_DIM + col0;
    const float x0 = b[0], x1 = b[1];
    b[0] = x0 * cs - x1 * sn;
    b[1] = x1 * cs + x0 * sn;
}

// =======================================================================
// Flash attention on tf32 mma.sync — ldmatrix fragment loads everywhere.
// Q/K/P row-major (pitch 132/132/68 floats -> conflict-free LDSM);
// V stored transposed as VT[d][k], 256B rows, XOR swizzle (d&7)<<4
// (conflict-free for both STS.128 fill and LDSM reads).
// Numerics identical to round 8 (same tf32 values, same MMA order).
// =======================================================================
#define ABM 128
#define ABN 64

struct AttnSmem {
    float   Q[ABM][132];
    float   K[ABN][132];
    float   P[ABM][68];
    uint8_t VT[ABM * 256];     // [d][k] swizzled, 32 KB
};

__global__ __launch_bounds__(256)
void attn_tc(uint32_t* __restrict__ chi, uint32_t* __restrict__ clo)
{
    extern __shared__ char sraw[];
    AttnSmem& sm = *reinterpret_cast<AttnSmem*>(sraw);

    const int head = blockIdx.y;
    const int mb   = blockIdx.x;
    const int tid  = threadIdx.x;
    const int lane = tid & 31;
    const int wid  = tid >> 5;
    const int r    = lane >> 2;
    const int c    = lane & 3;
    const int rb   = wid * 16;
    const int g    = head / GQA_REP;
    const float scale = 0.08838834764831845f;   // 1/sqrt(128)

    // ldmatrix lane addressing
    const int lrow  = ((lane >> 3) & 1) * 8 + (lane & 7);   // A-frag rows
    const int lchk  = (lane >> 4) * 16;                     // A-frag k-chunk
    const int brow  = ((lane >> 4) & 1) * 8 + (lane & 7);   // B-frag rows
    const int bchk  = ((lane >> 3) & 1) * 16;               // B-frag k-chunk

    const uint32_t qb  = smem_u32(&sm.Q[0][0]);
    const uint32_t kb  = smem_u32(&sm.K[0][0]);
    const uint32_t pb  = smem_u32(&sm.P[0][0]);
    const uint32_t vtb = smem_u32(&sm.VT[0]);

    // ---- load Q tile (scaled, tf32-RN) ----
    for (int i = tid; i < ABM * 32; i += 256) {
        const int row = i >> 5, c4 = (i & 31) << 2;
        float4 v = *(const float4*)&g_qkv[(size_t)(mb * ABM + row) * QKV_DIM +
                                          head * HEAD_DIM + c4];
        v.x = f_tf32(v.x * scale); v.y = f_tf32(v.y * scale);
        v.z = f_tf32(v.z * scale); v.w = f_tf32(v.w * scale);
        *(float4*)&sm.Q[row][c4] = v;
    }

    // prefetch unit mappings:
    //   K: unit q -> row = (tid+256q)>>5, d4 = ((tid+256q)&31)*4   (float4 along d)
    //   V: unit q -> d = (tid+256q)&127, kq = (tid+256q)>>7, k0 = 4*kq
    float4 kr[8], vr[8];
    {
        #pragma unroll
        for (int q = 0; q < 8; ++q) {
            const int i = tid + 256 * q;
            const int row = i >> 5, c4 = (i & 31) << 2;
            kr[q] = *(const float4*)&g_qkv[(size_t)row * QKV_DIM + Q_SZ +
                                           g * HEAD_DIM + c4];
            const int d = i & 127, k0 = (i >> 7) * 4;
            const float* vbase = g_qkv + Q_SZ + KV_SZ + g * HEAD_DIM + d;
            vr[q].x = vbase[(size_t)(k0 + 0) * QKV_DIM];
            vr[q].y = vbase[(size_t)(k0 + 1) * QKV_DIM];
            vr[q].z = vbase[(size_t)(k0 + 2) * QKV_DIM];
            vr[q].w = vbase[(size_t)(k0 + 3) * QKV_DIM];
        }
    }

    float o[16][4];
    #pragma unroll
    for (int j = 0; j < 16; ++j)
        #pragma unroll
        for (int q = 0; q < 4; ++q) o[j][q] = 0.f;
    float mst0 = -1e30f, mst1 = -1e30f, lst0 = 0.f, lst1 = 0.f;

    const int nbEnd = 2 * mb + 1;
    for (int nb = 0; nb <= nbEnd; ++nb) {
        __syncthreads();
        #pragma unroll
        for (int q = 0; q < 8; ++q) {
            const int i = tid + 256 * q;
            // K store (row-major, pitch 132)
            const int row = i >> 5, c4 = (i & 31) << 2;
            *(float4*)&sm.K[row][c4] = f4_tf32(kr[q]);
            // VT store: row d, 16B chunk at k0*4, swizzled
            const int d = i & 127, kq = i >> 7;
            const uint32_t off = (uint32_t)d * 256 +
                                 (((uint32_t)kq * 16) ^ (((uint32_t)d & 7) << 4));
            *(float4*)&sm.VT[off] = f4_tf32(vr[q]);
        }
        __syncthreads();

        if (nb < nbEnd) {
            #pragma unroll
            for (int q = 0; q < 8; ++q) {
                const int i = tid + 256 * q;
                const int row = i >> 5, c4 = (i & 31) << 2;
                kr[q] = *(const float4*)&g_qkv[(size_t)((nb + 1) * ABN + row) *
                                               QKV_DIM + Q_SZ + g * HEAD_DIM + c4];
                const int d = i & 127, k0 = (i >> 7) * 4;
                const float* vbase = g_qkv + (size_t)((nb + 1) * ABN) * QKV_DIM +
                                     Q_SZ + KV_SZ + g * HEAD_DIM + d;
                vr[q].x = vbase[(size_t)(k0 + 0) * QKV_DIM];
                vr[q].y = vbase[(size_t)(k0 + 1) * QKV_DIM];
                vr[q].z = vbase[(size_t)(k0 + 2) * QKV_DIM];
                vr[q].w = vbase[(size_t)(k0 + 3) * QKV_DIM];
            }
        }

        // ---- S = Q K^T (ldmatrix frags) ----
        float s[8][4];
        #pragma unroll
        for (int j = 0; j < 8; ++j)
            #pragma unroll
            for (int q = 0; q < 4; ++q) s[j][q] = 0.f;

        #pragma unroll 4
        for (int k0 = 0; k0 < 16; ++k0) {
            uint32_t aq[4];
            ldsm4(aq, qb + (uint32_t)((rb + lrow) * 132 + 8 * k0) * 4 + lchk);
            #pragma unroll
            for (int jp = 0; jp < 4; ++jp) {
                uint32_t kf[4];
                ldsm4(kf, kb + (uint32_t)((16 * jp + brow) * 132 + 8 * k0) * 4 + bchk);
                MMA_TF32(s[2 * jp],     aq[0], aq[1], aq[2], aq[3], kf[0], kf[1]);
                MMA_TF32(s[2 * jp + 1], aq[0], aq[1], aq[2], aq[3], kf[2], kf[3]);
            }
        }

        // ---- causal mask ----
        if (nb >= 2 * mb) {
            const int row0 = mb * ABM + rb + r;
            #pragma unroll
            for (int j = 0; j < 8; ++j) {
                const int col = nb * ABN + 8 * j + 2 * c;
                if (col     > row0)     s[j][0] = -1e30f;
                if (col + 1 > row0)     s[j][1] = -1e30f;
                if (col     > row0 + 8) s[j][2] = -1e30f;
                if (col + 1 > row0 + 8) s[j][3] = -1e30f;
            }
        }

        // ---- online softmax ----
        float mx0 = -1e30f, mx1 = -1e30f;
        #pragma unroll
        for (int j = 0; j < 8; ++j) {
            mx0 = fmaxf(mx0, fmaxf(s[j][0], s[j][1]));
            mx1 = fmaxf(mx1, fmaxf(s[j][2], s[j][3]));
        }
        mx0 = fmaxf(mx0, __shfl_xor_sync(0xffffffffu, mx0, 1));
        mx0 = fmaxf(mx0, __shfl_xor_sync(0xffffffffu, mx0, 2));
        mx1 = fmaxf(mx1, __shfl_xor_sync(0xffffffffu, mx1, 1));
        mx1 = fmaxf(mx1, __shfl_xor_sync(0xffffffffu, mx1, 2));
        const float mn0 = fmaxf(mst0, mx0), mn1 = fmaxf(mst1, mx1);
        const float al0 = __expf(mst0 - mn0), al1 = __expf(mst1 - mn1);
        float sum0 = 0.f, sum1 = 0.f;
        #pragma unroll
        for (int j = 0; j < 8; ++j) {
            s[j][0] = f_tf32(__expf(s[j][0] - mn0)); sum0 += s[j][0];
            s[j][1] = f_tf32(__expf(s[j][1] - mn0)); sum0 += s[j][1];
            s[j][2] = f_tf32(__expf(s[j][2] - mn1)); sum1 += s[j][2];
            s[j][3] = f_tf32(__expf(s[j][3] - mn1)); sum1 += s[j][3];
        }
        sum0 += __shfl_xor_sync(0xffffffffu, sum0, 1);
        sum0 += __shfl_xor_sync(0xffffffffu, sum0, 2);
        sum1 += __shfl_xor_sync(0xffffffffu, sum1, 1);
        sum1 += __shfl_xor_sync(0xffffffffu, sum1, 2);
        lst0 = lst0 * al0 + sum0;  mst0 = mn0;
        lst1 = lst1 * al1 + sum1;  mst1 = mn1;
        #pragma unroll
        for (int j = 0; j < 16; ++j) {
            o[j][0] *= al0; o[j][1] *= al0;
            o[j][2] *= al1; o[j][3] *= al1;
        }

        // ---- stage P (warp-private rows) ----
        #pragma unroll
        for (int j = 0; j < 8; ++j) {
            *(float2*)&sm.P[rb + r][8 * j + 2 * c]     = make_float2(s[j][0], s[j][1]);
            *(float2*)&sm.P[rb + r + 8][8 * j + 2 * c] = make_float2(s[j][2], s[j][3]);
        }
        __syncwarp();

        // ---- O += P @ V (ldmatrix frags; V via swizzled VT) ----
        #pragma unroll 4
        for (int kk = 0; kk < 8; ++kk) {
            uint32_t ap[4];
            ldsm4(ap, pb + (uint32_t)((rb + lrow) * 68 + 8 * kk) * 4 + lchk);
            #pragma unroll
            for (int jp = 0; jp < 8; ++jp) {
                const int vrow = 16 * jp + brow;
                const uint32_t addr = vtb + (uint32_t)vrow * 256 +
                    (((uint32_t)(kk * 32 + bchk)) ^ (((uint32_t)vrow & 7) << 4));
                uint32_t vf[4];
                ldsm4(vf, addr);
                MMA_TF32(o[2 * jp],     ap[0], ap[1], ap[2], ap[3], vf[0], vf[1]);
                MMA_TF32(o[2 * jp + 1], ap[0], ap[1], ap[2], ap[3], vf[2], vf[3]);
            }
        }
        __syncwarp();
    }

    // ---- normalize + write ctx as pre-split bf16 hi/lo planes ----
    const float il0 = 1.0f / lst0, il1 = 1.0f / lst1;
    const int trow = mb * ABM + rb + r;
    #pragma unroll
    for (int j = 0; j < 16; ++j) {
        const int col = head * HEAD_DIM + 8 * j + 2 * c;    // even
        uint32_t h, l;
        bsplit(o[j][0] * il0, o[j][1] * il0, h, l);
        const size_t p0 = ((size_t)trow * HIDDEN + col) >> 1;
        chi[p0] = h; clo[p0] = l;
        bsplit(o[j][2] * il1, o[j][3] * il1, h, l);
        const size_t p1 = ((size_t)(trow + 8) * HIDDEN + col) >> 1;
        chi[p1] = h; clo[p1] = l;
    }
}

// =======================================================================
// host side: tensormaps via runtime-resolved driver entry point
// =======================================================================
typedef CUresult (*tmap_encode_fn)(
    CUtensorMap*, CUtensorMapDataType, cuuint32_t, void*,
    const cuuint64_t*, const cuuint64_t*, const cuuint32_t*, const cuuint32_t*,
    CUtensorMapInterleave, CUtensorMapSwizzle, CUtensorMapL2promotion,
    CUtensorMapFloatOOBfill);

static tmap_encode_fn get_encoder()
{
    void* p = nullptr;
    cudaDriverEntryPointQueryResult qr;
#if CUDART_VERSION >= 12050
    cudaGetDriverEntryPointByVersion("cuTensorMapEncodeTiled", &p, 12000,
                                     cudaEnableDefault, &qr);
#else
    cudaGetDriverEntryPoint("cuTensorMapEncodeTiled", &p, cudaEnableDefault, &qr);
#endif
    return (tmap_encode_fn)p;
}

static void make_map(tmap_encode_fn enc, CUtensorMap* m, void* ptr,
                     uint64_t rows)
{
    cuuint64_t dims[2]    = {K2DIM, rows};
    cuuint64_t strides[1] = {K2DIM * sizeof(uint32_t)};
    cuuint32_t box[2]     = {32, 128};
    cuuint32_t es[2]      = {1, 1};
    enc(m, CU_TENSOR_MAP_DATA_TYPE_UINT32, 2, ptr, dims, strides, box, es,
        CU_TENSOR_MAP_INTERLEAVE_NONE, CU_TENSOR_MAP_SWIZZLE_128B,
        CU_TENSOR_MAP_L2_PROMOTION_L2_128B, CU_TENSOR_MAP_FLOAT_OOB_FILL_NONE);
}

extern "C" void kernel_launch(void* const* d_in, const int* in_sizes, int n_in,
                              void* d_out, int out_size)
{
    const int*   positions = (const int*)d_in[0];
    const float* hidden    = (const float*)d_in[1];
    const float* w_qkv     = (const float*)d_in[2];
    const float* b_qkv     = (const float*)d_in[3];
    const float* w_dense   = (const float*)d_in[4];
    float*       out       = (float*)d_out;

    float* qkv_p;
    uint32_t *ahi, *alo, *bhi, *blo;
    cudaGetSymbolAddress((void**)&qkv_p, g_qkv);
    cudaGetSymbolAddress((void**)&ahi,   g_ahi);
    cudaGetSymbolAddress((void**)&alo,   g_alo);
    cudaGetSymbolAddress((void**)&bhi,   g_bhi);
    cudaGetSymbolAddress((void**)&blo,   g_blo);

    tmap_encode_fn enc = get_encoder();
    CUtensorMap mAhi, mAlo, mBhi, mBlo;
    make_map(enc, &mAhi, ahi, T_SEQ);
    make_map(enc, &mAlo, alo, T_SEQ);
    make_map(enc, &mBhi, bhi, QKV_DIM);
    make_map(enc, &mBlo, blo, QKV_DIM);

    cudaFuncSetAttribute(gemm_tma<true>,
                         cudaFuncAttributeMaxDynamicSharedMemorySize, GEMM_SMEM);
    cudaFuncSetAttribute(gemm_tma<false>,
                         cudaFuncAttributeMaxDynamicSharedMemorySize, GEMM_SMEM);
    cudaFuncSetAttribute(attn_tc,
                         cudaFuncAttributeMaxDynamicSharedMemorySize,
                         (int)sizeof(AttnSmem));

    const int aPairs = T_SEQ * HIDDEN / 2;

    // 1) split inputs, then QKV = hidden @ w_qkv + b_qkv
    split_pairs<<<(aPairs + 255) / 256, 256>>>(
        (const float2*)hidden, ahi, alo, aPairs);
    split_bmat_t<<<dim3(QKV_DIM / 32, K2DIM / 32), dim3(32, 8)>>>(
        w_qkv, bhi, blo, K2DIM, QKV_DIM);
    gemm_tma<true><<<dim3(QKV_DIM / 256, T_SEQ / 128), 256, GEMM_SMEM>>>(
        mAhi, mAlo, mBhi, mBlo, b_qkv, qkv_p, QKV_DIM);

    // 2) RoPE in place
    const int totalRope = T_SEQ * NUM_HEADS * 32 + T_SEQ * KV_GROUPS * 32;
    rope_kernel<<<(totalRope + 255) / 256, 256>>>(positions);

    // 3) attention -> ctx hi/lo planes (reuses g_ahi/g_alo)
    attn_tc<<<dim3(T_SEQ / ABM, NUM_HEADS), 256, sizeof(AttnSmem)>>>(ahi, alo);

    // 4) split w_dense (transposed), then out = ctx @ w_dense
    split_bmat_t<<<dim3(HIDDEN / 32, K2DIM / 32), dim3(32, 8)>>>(
        w_dense, bhi, blo, K2DIM, HIDDEN);
    gemm_tma<false><<<dim3(HIDDEN / 256, T_SEQ / 128), 256, GEMM_SMEM>>>(
        mAhi, mAlo, mBhi, mBlo, nullptr, out, HIDDEN);
}

// round 10
// speedup vs baseline: 3.3155x; 1.0541x over previous
#include <cuda_runtime.h>
#include <cuda.h>
#include <math.h>
#include <stdint.h>

// ---------------- problem constants ----------------
#define T_SEQ      2048
#define HIDDEN     4096
#define NUM_HEADS  32
#define HEAD_DIM   128
#define KV_GROUPS  2
#define Q_SZ       (NUM_HEADS * HEAD_DIM)              // 4096
#define KV_SZ      (KV_GROUPS * HEAD_DIM)              // 256
#define QKV_DIM    (Q_SZ + 2 * KV_SZ)                  // 4608
#define GQA_REP    (NUM_HEADS / KV_GROUPS)             // 16
#define K2DIM      (HIDDEN / 2)                        // 2048 k-pairs

// ---------------- scratch (static device memory; no allocs allowed) ----
__device__ float    g_qkv[(size_t)T_SEQ * QKV_DIM];         // ~37.7 MB
__device__ uint32_t g_ahi[(size_t)T_SEQ * K2DIM];           // A hi plane [T][K2]
__device__ uint32_t g_alo[(size_t)T_SEQ * K2DIM];
__device__ uint32_t g_bhi[(size_t)QKV_DIM * K2DIM];         // B^T hi plane [N][K2]
__device__ uint32_t g_blo[(size_t)QKV_DIM * K2DIM];

// =======================================================================
// helpers
// =======================================================================
__device__ __forceinline__ uint32_t smem_u32(const void* p) {
    uint32_t a;
    asm("{ .reg .u64 t; cvta.to.shared.u64 t, %1; cvt.u32.u64 %0, t; }"
        : "=r"(a) : "l"(p));
    return a;
}
__device__ __forceinline__ float f_tf32(float x) {
    uint32_t r;
    asm("cvt.rna.tf32.f32 %0, %1;" : "=r"(r) : "f"(x));
    return __uint_as_float(r);
}
__device__ __forceinline__ float4 f4_tf32(float4 v) {
    v.x = f_tf32(v.x); v.y = f_tf32(v.y);
    v.z = f_tf32(v.z); v.w = f_tf32(v.w);
    return v;
}
// split (x0,x1) into packed bf16 hi pair and lo (residual) pair; x0 low half
__device__ __forceinline__ void bsplit(float x0, float x1,
                                       uint32_t& hi, uint32_t& lo) {
    uint32_t h;
    asm("cvt.rn.bf16x2.f32 %0, %1, %2;" : "=r"(h) : "f"(x1), "f"(x0));
    const float h0 = __uint_as_float(h << 16);
    const float h1 = __uint_as_float(h & 0xffff0000u);
    asm("cvt.rn.bf16x2.f32 %0, %1, %2;" : "=r"(lo) : "f"(x1 - h1), "f"(x0 - h0));
    hi = h;
}
__device__ __forceinline__ void ldsm4(uint32_t* f, uint32_t addr) {
    asm volatile("ldmatrix.sync.aligned.m8n8.x4.shared.b16 {%0,%1,%2,%3}, [%4];"
                 : "=r"(f[0]), "=r"(f[1]), "=r"(f[2]), "=r"(f[3]) : "r"(addr));
}
__device__ __forceinline__ uint32_t sw128(uint32_t off) {
    return off ^ ((off >> 3) & 0x70);
}
__device__ __forceinline__ void mbar_init(uint32_t a, uint32_t cnt) {
    asm volatile("mbarrier.init.shared.b64 [%0], %1;" :: "r"(a), "r"(cnt) : "memory");
}
__device__ __forceinline__ void mbar_expect_tx(uint32_t a, uint32_t bytes) {
    asm volatile("mbarrier.arrive.expect_tx.shared.b64 _, [%0], %1;"
                 :: "r"(a), "r"(bytes) : "memory");
}
__device__ __forceinline__ void mbar_arrive(uint32_t a) {
    asm volatile("mbarrier.arrive.shared.b64 _, [%0];" :: "r"(a) : "memory");
}
__device__ __forceinline__ void mbar_wait(uint32_t a, uint32_t parity) {
    asm volatile(
        "{\n\t.reg .pred P;\n\t"
        "W_%=:\n\t"
        "mbarrier.try_wait.parity.shared.b64 P, [%0], %1;\n\t"
        "@!P bra W_%=;\n\t}"
        :: "r"(a), "r"(parity) : "memory");
}
__device__ __forceinline__ void tma2d(uint32_t dst, const CUtensorMap* m,
                                      int x, int y, uint32_t mbar) {
    asm volatile(
        "cp.async.bulk.tensor.2d.shared::cta.global.tile.mbarrier::complete_tx::bytes "
        "[%0], [%1, {%2, %3}], [%4];"
        :: "r"(dst), "l"(m), "r"(x), "r"(y), "r"(mbar) : "memory");
}

#define MMA_TF32(d, a0, a1, a2, a3, b0, b1)                                   \
    asm volatile(                                                             \
        "mma.sync.aligned.m16n8k8.row.col.f32.tf32.tf32.f32 "                 \
        "{%0,%1,%2,%3}, {%4,%5,%6,%7}, {%8,%9}, {%0,%1,%2,%3};"               \
        : "+f"((d)[0]), "+f"((d)[1]), "+f"((d)[2]), "+f"((d)[3])              \
        : "r"(a0), "r"(a1), "r"(a2), "r"(a3), "r"(b0), "r"(b1))

#define MMA_BF16(d, a0, a1, a2, a3, b0, b1)                                   \
    asm volatile(                                                             \
        "mma.sync.aligned.m16n8k16.row.col.f32.bf16.bf16.f32 "                \
        "{%0,%1,%2,%3}, {%4,%5,%6,%7}, {%8,%9}, {%0,%1,%2,%3};"               \
        : "+f"((d)[0]), "+f"((d)[1]), "+f"((d)[2]), "+f"((d)[3])              \
        : "r"(a0), "r"(a1), "r"(a2), "r"(a3), "r"(b0), "r"(b1))

// =======================================================================
// split passes
// =======================================================================
__global__ void split_pairs(const float2* __restrict__ src,
                            uint32_t* __restrict__ hi,
                            uint32_t* __restrict__ lo, int total2)
{
    const int i = blockIdx.x * blockDim.x + threadIdx.x;
    if (i >= total2) return;
    const float2 v = src[i];
    uint32_t h, l;
    bsplit(v.x, v.y, h, l);
    hi[i] = h;
    lo[i] = l;
}
// B^T planes: BT[n][k2] = bsplit(B[2k2][n], B[2k2+1][n]); smem transpose.
__global__ void split_bmat_t(const float* __restrict__ B,
                             uint32_t* __restrict__ hiT,
                             uint32_t* __restrict__ loT, int K2, int N)
{
    __shared__ uint32_t th[32][33], tl[32][33];
    const int n0 = blockIdx.x * 32, k20 = blockIdx.y * 32;
    const int tx = threadIdx.x, ty = threadIdx.y;   // 32 x 8
    #pragma unroll
    for (int i = 0; i < 4; ++i) {
        const int k2 = ty + 8 * i;
        const float x0 = B[(size_t)(2 * (k20 + k2)) * N + n0 + tx];
        const float x1 = B[(size_t)(2 * (k20 + k2) + 1) * N + n0 + tx];
        uint32_t h, l;
        bsplit(x0, x1, h, l);
        th[k2][tx] = h;
        tl[k2][tx] = l;
    }
    __syncthreads();
    #pragma unroll
    for (int i = 0; i < 4; ++i) {
        const int n = ty + 8 * i;
        hiT[(size_t)(n0 + n) * K2 + k20 + tx] = th[tx][n];
        loT[(size_t)(n0 + n) * K2 + k20 + tx] = tl[tx][n];
    }
}

// =======================================================================
// bf16x3 tensor-core GEMM, TMA-fed.
// CTA 128x256, 512 threads (16 warps, warp tile 64x32 -> 4 warps/SMSP for
// latency hiding), K-slab 64 elems, 2-stage mbarrier pipeline.
// Same MMA K-order per output element as rounds 4-9 (bit-identical result).
// =======================================================================
#define NS        2
#define PLANE_A   16384
#define PLANE_BB  32768
#define STAGE_B   (2 * PLANE_A + 2 * PLANE_BB)   // 98304
#define GEMM_SMEM (NS * STAGE_B + 64)            // 196672
#define KT_SLABS  (K2DIM / 32)                   // 64

template <bool HAS_BIAS>
__global__ void __launch_bounds__(512)
gemm_tma(const __grid_constant__ CUtensorMap mAhi,
         const __grid_constant__ CUtensorMap mAlo,
         const __grid_constant__ CUtensorMap mBhi,
         const __grid_constant__ CUtensorMap mBlo,
         const float* __restrict__ bias, float* __restrict__ C, int N)
{
    extern __shared__ __align__(1024) uint32_t smw[];
    const uint32_t sbase = smem_u32(smw);
    const uint32_t full0  = sbase + NS * STAGE_B;
    const uint32_t empty0 = full0 + 16;

    const int tid  = threadIdx.x;
    const int lane = tid & 31;
    const int wid  = tid >> 5;                 // 0..15
    const int wm   = (wid & 1) * 64;           // 2 warps over M
    const int wn   = (wid >> 1) * 32;          // 8 warps over N
    const int r    = lane >> 2;
    const int c    = lane & 3;
    const int mBase = blockIdx.y * 128;
    const int nBase = blockIdx.x * 256;

    const int arow = ((lane >> 3) & 1) * 8 + (lane & 7);
    const int achk = (lane >> 4) * 16;
    const int brow = ((lane >> 3) & 2) * 4 + (lane & 7);
    const int bchk = ((lane >> 3) & 1) * 16;

    if (tid == 0) {
        #pragma unroll
        for (int s = 0; s < NS; ++s) {
            mbar_init(full0 + 8 * s, 1);
            mbar_init(empty0 + 8 * s, 16);
        }
    }
    __syncthreads();

    auto issue_slab = [&](int s, int kt) {
        const uint32_t st = sbase + (uint32_t)s * STAGE_B;
        const uint32_t fb = full0 + 8 * s;
        mbar_expect_tx(fb, STAGE_B);
        tma2d(st,                          &mAhi, kt * 32, mBase, fb);
        tma2d(st + PLANE_A,                &mAlo, kt * 32, mBase, fb);
        tma2d(st + 2 * PLANE_A,            &mBhi, kt * 32, nBase, fb);
        tma2d(st + 2 * PLANE_A + 16384,    &mBhi, kt * 32, nBase + 128, fb);
        tma2d(st + 2 * PLANE_A + PLANE_BB, &mBlo, kt * 32, nBase, fb);
        tma2d(st + 2 * PLANE_A + PLANE_BB + 16384,
              &mBlo, kt * 32, nBase + 128, fb);
    };

    if (tid == 0) issue_slab(0, 0);

    float acc[4][4][4];
    #pragma unroll
    for (int mi = 0; mi < 4; ++mi)
        #pragma unroll
        for (int ni = 0; ni < 4; ++ni)
            #pragma unroll
            for (int q = 0; q < 4; ++q) acc[mi][ni][q] = 0.f;

    for (int kt = 0; kt < KT_SLABS; ++kt) {
        const int s = kt & 1;

        if (tid == 0) {
            const int nk = kt + 1;
            if (nk < KT_SLABS) {
                if (nk >= NS) mbar_wait(empty0 + 8 * (nk & 1), (nk / NS - 1) & 1);
                issue_slab(nk & 1, nk);
            }
        }

        mbar_wait(full0 + 8 * s, (kt / NS) & 1);

        const uint32_t stg = sbase + (uint32_t)s * STAGE_B;
        #pragma unroll
        for (int t = 0; t < 4; ++t) {
            uint32_t afh[4][4], afl[4][4];
            #pragma unroll
            for (int mi = 0; mi < 4; ++mi) {
                const uint32_t a = stg +
                    sw128((uint32_t)((wm + mi * 16 + arow) * 128 + t * 32 + achk));
                ldsm4(afh[mi], a);
                ldsm4(afl[mi], a + PLANE_A);
            }
            uint32_t bfh[4][2], bfl[4][2];
            #pragma unroll
            for (int p = 0; p < 2; ++p) {
                const uint32_t b = stg + 2 * PLANE_A +
                    sw128((uint32_t)((wn + p * 16 + brow) * 128 + t * 32 + bchk));
                uint32_t tm[4];
                ldsm4(tm, b);
                bfh[2 * p][0] = tm[0]; bfh[2 * p][1] = tm[1];
                bfh[2 * p + 1][0] = tm[2]; bfh[2 * p + 1][1] = tm[3];
                ldsm4(tm, b + PLANE_BB);
                bfl[2 * p][0] = tm[0]; bfl[2 * p][1] = tm[1];
                bfl[2 * p + 1][0] = tm[2]; bfl[2 * p + 1][1] = tm[3];
            }
            #pragma unroll
            for (int ni = 0; ni < 4; ++ni)
                #pragma unroll
                for (int mi = 0; mi < 4; ++mi) {
                    MMA_BF16(acc[mi][ni], afh[mi][0], afh[mi][1], afh[mi][2],
                             afh[mi][3], bfh[ni][0], bfh[ni][1]);
                    MMA_BF16(acc[mi][ni], afh[mi][0], afh[mi][1], afh[mi][2],
                             afh[mi][3], bfl[ni][0], bfl[ni][1]);
                    MMA_BF16(acc[mi][ni], afl[mi][0], afl[mi][1], afl[mi][2],
                             afl[mi][3], bfh[ni][0], bfh[ni][1]);
                }
        }

        __syncwarp();
        if (lane == 0) mbar_arrive(empty0 + 8 * s);
    }

    #pragma unroll
    for (int mi = 0; mi < 4; ++mi) {
        const int row0 = mBase + wm + mi * 16 + r;
        #pragma unroll
        for (int ni = 0; ni < 4; ++ni) {
            const int col = nBase + wn + ni * 8 + c * 2;
            float2 v0 = make_float2(acc[mi][ni][0], acc[mi][ni][1]);
            float2 v1 = make_float2(acc[mi][ni][2], acc[mi][ni][3]);
            if (HAS_BIAS) {
                const float2 bb = *(const float2*)&bias[col];
                v0.x += bb.x; v0.y += bb.y;
                v1.x += bb.x; v1.y += bb.y;
            }
            *(float2*)&C[(size_t)row0 * N + col] = v0;
            *(float2*)&C[(size_t)(row0 + 8) * N + col] = v1;
        }
    }
}

// =======================================================================
// RoPE (interleaved pairs), in-place on Q and K slices of g_qkv.
// =======================================================================
__global__ void rope_kernel(const int* __restrict__ positions)
{
    const int totalQ = T_SEQ * NUM_HEADS * 32;
    const int totalK = T_SEQ * KV_GROUPS * 32;
    int idx = blockIdx.x * blockDim.x + threadIdx.x;

    int t, p, col0;
    if (idx < totalQ) {
        p = idx & 31;
        int h = (idx >> 5) & (NUM_HEADS - 1);
        t = idx >> 10;
        col0 = h * HEAD_DIM + 2 * p;
    } else {
        int rr = idx - totalQ;
        if (rr >= totalK) return;
        p = rr & 31;
        int g = (rr >> 5) & (KV_GROUPS - 1);
        t = rr >> 6;
        col0 = Q_SZ + g * HEAD_DIM + 2 * p;
    }

    const float pos   = (float)positions[t];
    const float theta = powf(10000.0f, -(float)p * (1.0f / 32.0f));
    float sn, cs;
    sincosf(pos * theta, &sn, &cs);

    float* b = g_qkv + (size_t)t * QKV_DIM + col0;
    const float x0 = b[0], x1 = b[1];
    b[0] = x0 * cs - x1 * sn;
    b[1] = x1 * cs + x0 * sn;
}

// =======================================================================
// Flash attention on tf32 mma.sync — ldmatrix everywhere (round 9),
// plus LPT scheduling: grid (head, mb-slow) with mb reversed so the
// longest CTAs launch first.
// =======================================================================
#define ABM 128
#define ABN 64

struct AttnSmem {
    float   Q[ABM][132];
    float   K[ABN][132];
    float   P[ABM][68];
    uint8_t VT[ABM * 256];     // [d][k] swizzled, 32 KB
};

__global__ __launch_bounds__(256)
void attn_tc(uint32_t* __restrict__ chi, uint32_t* __restrict__ clo)
{
    extern __shared__ char sraw[];
    AttnSmem& sm = *reinterpret_cast<AttnSmem*>(sraw);

    const int head = blockIdx.x;
    const int mb   = gridDim.y - 1 - blockIdx.y;     // LPT: heavy blocks first
    const int tid  = threadIdx.x;
    const int lane = tid & 31;
    const int wid  = tid >> 5;
    const int r    = lane >> 2;
    const int c    = lane & 3;
    const int rb   = wid * 16;
    const int g    = head / GQA_REP;
    const float scale = 0.08838834764831845f;   // 1/sqrt(128)

    const int lrow  = ((lane >> 3) & 1) * 8 + (lane & 7);
    const int lchk  = (lane >> 4) * 16;
    const int brow  = ((lane >> 4) & 1) * 8 + (lane & 7);
    const int bchk  = ((lane >> 3) & 1) * 16;

    const uint32_t qb  = smem_u32(&sm.Q[0][0]);
    const uint32_t kb  = smem_u32(&sm.K[0][0]);
    const uint32_t pb  = smem_u32(&sm.P[0][0]);
    const uint32_t vtb = smem_u32(&sm.VT[0]);

    for (int i = tid; i < ABM * 32; i += 256) {
        const int row = i >> 5, c4 = (i & 31) << 2;
        float4 v = *(const float4*)&g_qkv[(size_t)(mb * ABM + row) * QKV_DIM +
                                          head * HEAD_DIM + c4];
        v.x = f_tf32(v.x * scale); v.y = f_tf32(v.y * scale);
        v.z = f_tf32(v.z * scale); v.w = f_tf32(v.w * scale);
        *(float4*)&sm.Q[row][c4] = v;
    }

    float4 kr[8], vr[8];
    {
        #pragma unroll
        for (int q = 0; q < 8; ++q) {
            const int i = tid + 256 * q;
            const int row = i >> 5, c4 = (i & 31) << 2;
            kr[q] = *(const float4*)&g_qkv[(size_t)row * QKV_DIM + Q_SZ +
                                           g * HEAD_DIM + c4];
            const int d = i & 127, k0 = (i >> 7) * 4;
            const float* vbase = g_qkv + Q_SZ + KV_SZ + g * HEAD_DIM + d;
            vr[q].x = vbase[(size_t)(k0 + 0) * QKV_DIM];
            vr[q].y = vbase[(size_t)(k0 + 1) * QKV_DIM];
            vr[q].z = vbase[(size_t)(k0 + 2) * QKV_DIM];
            vr[q].w = vbase[(size_t)(k0 + 3) * QKV_DIM];
        }
    }

    float o[16][4];
    #pragma unroll
    for (int j = 0; j < 16; ++j)
        #pragma unroll
        for (int q = 0; q < 4; ++q) o[j][q] = 0.f;
    float mst0 = -1e30f, mst1 = -1e30f, lst0 = 0.f, lst1 = 0.f;

    const int nbEnd = 2 * mb + 1;
    for (int nb = 0; nb <= nbEnd; ++nb) {
        __syncthreads();
        #pragma unroll
        for (int q = 0; q < 8; ++q) {
            const int i = tid + 256 * q;
            const int row = i >> 5, c4 = (i & 31) << 2;
            *(float4*)&sm.K[row][c4] = f4_tf32(kr[q]);
            const int d = i & 127, kq = i >> 7;
            const uint32_t off = (uint32_t)d * 256 +
                                 (((uint32_t)kq * 16) ^ (((uint32_t)d & 7) << 4));
            *(float4*)&sm.VT[off] = f4_tf32(vr[q]);
        }
        __syncthreads();

        if (nb < nbEnd) {
            #pragma unroll
            for (int q = 0; q < 8; ++q) {
                const int i = tid + 256 * q;
                const int row = i >> 5, c4 = (i & 31) << 2;
                kr[q] = *(const float4*)&g_qkv[(size_t)((nb + 1) * ABN + row) *
                                               QKV_DIM + Q_SZ + g * HEAD_DIM + c4];
                const int d = i & 127, k0 = (i >> 7) * 4;
                const float* vbase = g_qkv + (size_t)((nb + 1) * ABN) * QKV_DIM +
                                     Q_SZ + KV_SZ + g * HEAD_DIM + d;
                vr[q].x = vbase[(size_t)(k0 + 0) * QKV_DIM];
                vr[q].y = vbase[(size_t)(k0 + 1) * QKV_DIM];
                vr[q].z = vbase[(size_t)(k0 + 2) * QKV_DIM];
                vr[q].w = vbase[(size_t)(k0 + 3) * QKV_DIM];
            }
        }

        float s[8][4];
        #pragma unroll
        for (int j = 0; j < 8; ++j)
            #pragma unroll
            for (int q = 0; q < 4; ++q) s[j][q] = 0.f;

        #pragma unroll 4
        for (int k0 = 0; k0 < 16; ++k0) {
            uint32_t aq[4];
            ldsm4(aq, qb + (uint32_t)((rb + lrow) * 132 + 8 * k0) * 4 + lchk);
            #pragma unroll
            for (int jp = 0; jp < 4; ++jp) {
                uint32_t kf[4];
                ldsm4(kf, kb + (uint32_t)((16 * jp + brow) * 132 + 8 * k0) * 4 + bchk);
                MMA_TF32(s[2 * jp],     aq[0], aq[1], aq[2], aq[3], kf[0], kf[1]);
                MMA_TF32(s[2 * jp + 1], aq[0], aq[1], aq[2], aq[3], kf[2], kf[3]);
            }
        }

        if (nb >= 2 * mb) {
            const int row0 = mb * ABM + rb + r;
            #pragma unroll
            for (int j = 0; j < 8; ++j) {
                const int col = nb * ABN + 8 * j + 2 * c;
                if (col     > row0)     s[j][0] = -1e30f;
                if (col + 1 > row0)     s[j][1] = -1e30f;
                if (col     > row0 + 8) s[j][2] = -1e30f;
                if (col + 1 > row0 + 8) s[j][3] = -1e30f;
            }
        }

        float mx0 = -1e30f, mx1 = -1e30f;
        #pragma unroll
        for (int j = 0; j < 8; ++j) {
            mx0 = fmaxf(mx0, fmaxf(s[j][0], s[j][1]));
            mx1 = fmaxf(mx1, fmaxf(s[j][2], s[j][3]));
        }
        mx0 = fmaxf(mx0, __shfl_xor_sync(0xffffffffu, mx0, 1));
        mx0 = fmaxf(mx0, __shfl_xor_sync(0xffffffffu, mx0, 2));
        mx1 = fmaxf(mx1, __shfl_xor_sync(0xffffffffu, mx1, 1));
        mx1 = fmaxf(mx1, __shfl_xor_sync(0xffffffffu, mx1, 2));
        const float mn0 = fmaxf(mst0, mx0), mn1 = fmaxf(mst1, mx1);
        const float al0 = __expf(mst0 - mn0), al1 = __expf(mst1 - mn1);
        float sum0 = 0.f, sum1 = 0.f;
        #pragma unroll
        for (int j = 0; j < 8; ++j) {
            s[j][0] = f_tf32(__expf(s[j][0] - mn0)); sum0 += s[j][0];
            s[j][1] = f_tf32(__expf(s[j][1] - mn0)); sum0 += s[j][1];
            s[j][2] = f_tf32(__expf(s[j][2] - mn1)); sum1 += s[j][2];
            s[j][3] = f_tf32(__expf(s[j][3] - mn1)); sum1 += s[j][3];
        }
        sum0 += __shfl_xor_sync(0xffffffffu, sum0, 1);
        sum0 += __shfl_xor_sync(0xffffffffu, sum0, 2);
        sum1 += __shfl_xor_sync(0xffffffffu, sum1, 1);
        sum1 += __shfl_xor_sync(0xffffffffu, sum1, 2);
        lst0 = lst0 * al0 + sum0;  mst0 = mn0;
        lst1 = lst1 * al1 + sum1;  mst1 = mn1;
        #pragma unroll
        for (int j = 0; j < 16; ++j) {
            o[j][0] *= al0; o[j][1] *= al0;
            o[j][2] *= al1; o[j][3] *= al1;
        }

        #pragma unroll
        for (int j = 0; j < 8; ++j) {
            *(float2*)&sm.P[rb + r][8 * j + 2 * c]     = make_float2(s[j][0], s[j][1]);
            *(float2*)&sm.P[rb + r + 8][8 * j + 2 * c] = make_float2(s[j][2], s[j][3]);
        }
        __syncwarp();

        #pragma unroll 4
        for (int kk = 0; kk < 8; ++kk) {
            uint32_t ap[4];
            ldsm4(ap, pb + (uint32_t)((rb + lrow) * 68 + 8 * kk) * 4 + lchk);
            #pragma unroll
            for (int jp = 0; jp < 8; ++jp) {
                const int vrow = 16 * jp + brow;
                const uint32_t addr = vtb + (uint32_t)vrow * 256 +
                    (((uint32_t)(kk * 32 + bchk)) ^ (((uint32_t)vrow & 7) << 4));
                uint32_t vf[4];
                ldsm4(vf, addr);
                MMA_TF32(o[2 * jp],     ap[0], ap[1], ap[2], ap[3], vf[0], vf[1]);
                MMA_TF32(o[2 * jp + 1], ap[0], ap[1], ap[2], ap[3], vf[2], vf[3]);
            }
        }
        __syncwarp();
    }

    const float il0 = 1.0f / lst0, il1 = 1.0f / lst1;
    const int trow = mb * ABM + rb + r;
    #pragma unroll
    for (int j = 0; j < 16; ++j) {
        const int col = head * HEAD_DIM + 8 * j + 2 * c;
        uint32_t h, l;
        bsplit(o[j][0] * il0, o[j][1] * il0, h, l);
        const size_t p0 = ((size_t)trow * HIDDEN + col) >> 1;
        chi[p0] = h; clo[p0] = l;
        bsplit(o[j][2] * il1, o[j][3] * il1, h, l);
        const size_t p1 = ((size_t)(trow + 8) * HIDDEN + col) >> 1;
        chi[p1] = h; clo[p1] = l;
    }
}

// =======================================================================
// host side: tensormaps via runtime-resolved driver entry point
// =======================================================================
typedef CUresult (*tmap_encode_fn)(
    CUtensorMap*, CUtensorMapDataType, cuuint32_t, void*,
    const cuuint64_t*, const cuuint64_t*, const cuuint32_t*, const cuuint32_t*,
    CUtensorMapInterleave, CUtensorMapSwizzle, CUtensorMapL2promotion,
    CUtensorMapFloatOOBfill);

static tmap_encode_fn get_encoder()
{
    void* p = nullptr;
    cudaDriverEntryPointQueryResult qr;
#if CUDART_VERSION >= 12050
    cudaGetDriverEntryPointByVersion("cuTensorMapEncodeTiled", &p, 12000,
                                     cudaEnableDefault, &qr);
#else
    cudaGetDriverEntryPoint("cuTensorMapEncodeTiled", &p, cudaEnableDefault, &qr);
#endif
    return (tmap_encode_fn)p;
}

static void make_map(tmap_encode_fn enc, CUtensorMap* m, void* ptr,
                     uint64_t rows)
{
    cuuint64_t dims[2]    = {K2DIM, rows};
    cuuint64_t strides[1] = {K2DIM * sizeof(uint32_t)};
    cuuint32_t box[2]     = {32, 128};
    cuuint32_t es[2]      = {1, 1};
    enc(m, CU_TENSOR_MAP_DATA_TYPE_UINT32, 2, ptr, dims, strides, box, es,
        CU_TENSOR_MAP_INTERLEAVE_NONE, CU_TENSOR_MAP_SWIZZLE_128B,
        CU_TENSOR_MAP_L2_PROMOTION_L2_128B, CU_TENSOR_MAP_FLOAT_OOB_FILL_NONE);
}

extern "C" void kernel_launch(void* const* d_in, const int* in_sizes, int n_in,
                              void* d_out, int out_size)
{
    const int*   positions = (const int*)d_in[0];
    const float* hidden    = (const float*)d_in[1];
    const float* w_qkv     = (const float*)d_in[2];
    const float* b_qkv     = (const float*)d_in[3];
    const float* w_dense   = (const float*)d_in[4];
    float*       out       = (float*)d_out;

    float* qkv_p;
    uint32_t *ahi, *alo, *bhi, *blo;
    cudaGetSymbolAddress((void**)&qkv_p, g_qkv);
    cudaGetSymbolAddress((void**)&ahi,   g_ahi);
    cudaGetSymbolAddress((void**)&alo,   g_alo);
    cudaGetSymbolAddress((void**)&bhi,   g_bhi);
    cudaGetSymbolAddress((void**)&blo,   g_blo);

    tmap_encode_fn enc = get_encoder();
    CUtensorMap mAhi, mAlo, mBhi, mBlo;
    make_map(enc, &mAhi, ahi, T_SEQ);
    make_map(enc, &mAlo, alo, T_SEQ);
    make_map(enc, &mBhi, bhi, QKV_DIM);
    make_map(enc, &mBlo, blo, QKV_DIM);

    cudaFuncSetAttribute(gemm_tma<true>,
                         cudaFuncAttributeMaxDynamicSharedMemorySize, GEMM_SMEM);
    cudaFuncSetAttribute(gemm_tma<false>,
                         cudaFuncAttributeMaxDynamicSharedMemorySize, GEMM_SMEM);
    cudaFuncSetAttribute(attn_tc,
                         cudaFuncAttributeMaxDynamicSharedMemorySize,
                         (int)sizeof(AttnSmem));

    const int aPairs = T_SEQ * HIDDEN / 2;

    // 1) split inputs, then QKV = hidden @ w_qkv + b_qkv
    split_pairs<<<(aPairs + 255) / 256, 256>>>(
        (const float2*)hidden, ahi, alo, aPairs);
    split_bmat_t<<<dim3(QKV_DIM / 32, K2DIM / 32), dim3(32, 8)>>>(
        w_qkv, bhi, blo, K2DIM, QKV_DIM);
    gemm_tma<true><<<dim3(QKV_DIM / 256, T_SEQ / 128), 512, GEMM_SMEM>>>(
        mAhi, mAlo, mBhi, mBlo, b_qkv, qkv_p, QKV_DIM);

    // 2) RoPE in place
    const int totalRope = T_SEQ * NUM_HEADS * 32 + T_SEQ * KV_GROUPS * 32;
    rope_kernel<<<(totalRope + 255) / 256, 256>>>(positions);

    // 3) attention -> ctx hi/lo planes (LPT grid: head fast, mb slow-reversed)
    attn_tc<<<dim3(NUM_HEADS, T_SEQ / ABM), 256, sizeof(AttnSmem)>>>(ahi, alo);

    // 4) split w_dense (transposed), then out = ctx @ w_dense
    split_bmat_t<<<dim3(HIDDEN / 32, K2DIM / 32), dim3(32, 8)>>>(
        w_dense, bhi, blo, K2DIM, HIDDEN);
    gemm_tma<false><<<dim3(HIDDEN / 256, T_SEQ / 128), 512, GEMM_SMEM>>>(
        mAhi, mAlo, mBhi, mBlo, nullptr, out, HIDDEN);
}

// round 11
// speedup vs baseline: 3.3698x; 1.0164x over previous
#include <cuda_runtime.h>
#include <cuda.h>
#include <math.h>
#include <stdint.h>

// ---------------- problem constants ----------------
#define T_SEQ      2048
#define HIDDEN     4096
#define NUM_HEADS  32
#define HEAD_DIM   128
#define KV_GROUPS  2
#define Q_SZ       (NUM_HEADS * HEAD_DIM)              // 4096
#define KV_SZ      (KV_GROUPS * HEAD_DIM)              // 256
#define QKV_DIM    (Q_SZ + 2 * KV_SZ)                  // 4608
#define GQA_REP    (NUM_HEADS / KV_GROUPS)             // 16
#define K2DIM      (HIDDEN / 2)                        // 2048 k-pairs

// ---------------- scratch (static device memory; no allocs allowed) ----
__device__ float    g_qkv[(size_t)T_SEQ * QKV_DIM];         // ~37.7 MB
__device__ uint32_t g_ahi[(size_t)T_SEQ * K2DIM];           // A hi plane [T][K2]
__device__ uint32_t g_alo[(size_t)T_SEQ * K2DIM];
__device__ uint32_t g_bhi[(size_t)QKV_DIM * K2DIM];         // B^T hi plane [N][K2]
__device__ uint32_t g_blo[(size_t)QKV_DIM * K2DIM];

// =======================================================================
// helpers
// =======================================================================
__device__ __forceinline__ uint32_t smem_u32(const void* p) {
    uint32_t a;
    asm("{ .reg .u64 t; cvta.to.shared.u64 t, %1; cvt.u32.u64 %0, t; }"
        : "=r"(a) : "l"(p));
    return a;
}
__device__ __forceinline__ float f_tf32(float x) {
    uint32_t r;
    asm("cvt.rna.tf32.f32 %0, %1;" : "=r"(r) : "f"(x));
    return __uint_as_float(r);
}
__device__ __forceinline__ float4 f4_tf32(float4 v) {
    v.x = f_tf32(v.x); v.y = f_tf32(v.y);
    v.z = f_tf32(v.z); v.w = f_tf32(v.w);
    return v;
}
// split (x0,x1) into packed bf16 hi pair and lo (residual) pair; x0 low half
__device__ __forceinline__ void bsplit(float x0, float x1,
                                       uint32_t& hi, uint32_t& lo) {
    uint32_t h;
    asm("cvt.rn.bf16x2.f32 %0, %1, %2;" : "=r"(h) : "f"(x1), "f"(x0));
    const float h0 = __uint_as_float(h << 16);
    const float h1 = __uint_as_float(h & 0xffff0000u);
    asm("cvt.rn.bf16x2.f32 %0, %1, %2;" : "=r"(lo) : "f"(x1 - h1), "f"(x0 - h0));
    hi = h;
}
__device__ __forceinline__ void ldsm4(uint32_t* f, uint32_t addr) {
    asm volatile("ldmatrix.sync.aligned.m8n8.x4.shared.b16 {%0,%1,%2,%3}, [%4];"
                 : "=r"(f[0]), "=r"(f[1]), "=r"(f[2]), "=r"(f[3]) : "r"(addr));
}
__device__ __forceinline__ uint32_t sw128(uint32_t off) {
    return off ^ ((off >> 3) & 0x70);
}
__device__ __forceinline__ void mbar_init(uint32_t a, uint32_t cnt) {
    asm volatile("mbarrier.init.shared.b64 [%0], %1;" :: "r"(a), "r"(cnt) : "memory");
}
__device__ __forceinline__ void mbar_expect_tx(uint32_t a, uint32_t bytes) {
    asm volatile("mbarrier.arrive.expect_tx.shared.b64 _, [%0], %1;"
                 :: "r"(a), "r"(bytes) : "memory");
}
__device__ __forceinline__ void mbar_arrive(uint32_t a) {
    asm volatile("mbarrier.arrive.shared.b64 _, [%0];" :: "r"(a) : "memory");
}
__device__ __forceinline__ void mbar_wait(uint32_t a, uint32_t parity) {
    asm volatile(
        "{\n\t.reg .pred P;\n\t"
        "W_%=:\n\t"
        "mbarrier.try_wait.parity.shared.b64 P, [%0], %1;\n\t"
        "@!P bra W_%=;\n\t}"
        :: "r"(a), "r"(parity) : "memory");
}
__device__ __forceinline__ void tma2d(uint32_t dst, const CUtensorMap* m,
                                      int x, int y, uint32_t mbar) {
    asm volatile(
        "cp.async.bulk.tensor.2d.shared::cta.global.tile.mbarrier::complete_tx::bytes "
        "[%0], [%1, {%2, %3}], [%4];"
        :: "r"(dst), "l"(m), "r"(x), "r"(y), "r"(mbar) : "memory");
}

#define MMA_TF32(d, a0, a1, a2, a3, b0, b1)                                   \
    asm volatile(                                                             \
        "mma.sync.aligned.m16n8k8.row.col.f32.tf32.tf32.f32 "                 \
        "{%0,%1,%2,%3}, {%4,%5,%6,%7}, {%8,%9}, {%0,%1,%2,%3};"               \
        : "+f"((d)[0]), "+f"((d)[1]), "+f"((d)[2]), "+f"((d)[3])              \
        : "r"(a0), "r"(a1), "r"(a2), "r"(a3), "r"(b0), "r"(b1))

#define MMA_BF16(d, a0, a1, a2, a3, b0, b1)                                   \
    asm volatile(                                                             \
        "mma.sync.aligned.m16n8k16.row.col.f32.bf16.bf16.f32 "                \
        "{%0,%1,%2,%3}, {%4,%5,%6,%7}, {%8,%9}, {%0,%1,%2,%3};"               \
        : "+f"((d)[0]), "+f"((d)[1]), "+f"((d)[2]), "+f"((d)[3])              \
        : "r"(a0), "r"(a1), "r"(a2), "r"(a3), "r"(b0), "r"(b1))

// =======================================================================
// split passes
// =======================================================================
__global__ void split_pairs(const float2* __restrict__ src,
                            uint32_t* __restrict__ hi,
                            uint32_t* __restrict__ lo, int total2)
{
    const int i = blockIdx.x * blockDim.x + threadIdx.x;
    if (i >= total2) return;
    const float2 v = src[i];
    uint32_t h, l;
    bsplit(v.x, v.y, h, l);
    hi[i] = h;
    lo[i] = l;
}
// B^T planes: BT[n][k2] = bsplit(B[2k2][n], B[2k2+1][n]); smem transpose.
__global__ void split_bmat_t(const float* __restrict__ B,
                             uint32_t* __restrict__ hiT,
                             uint32_t* __restrict__ loT, int K2, int N)
{
    __shared__ uint32_t th[32][33], tl[32][33];
    const int n0 = blockIdx.x * 32, k20 = blockIdx.y * 32;
    const int tx = threadIdx.x, ty = threadIdx.y;   // 32 x 8
    #pragma unroll
    for (int i = 0; i < 4; ++i) {
        const int k2 = ty + 8 * i;
        const float x0 = B[(size_t)(2 * (k20 + k2)) * N + n0 + tx];
        const float x1 = B[(size_t)(2 * (k20 + k2) + 1) * N + n0 + tx];
        uint32_t h, l;
        bsplit(x0, x1, h, l);
        th[k2][tx] = h;
        tl[k2][tx] = l;
    }
    __syncthreads();
    #pragma unroll
    for (int i = 0; i < 4; ++i) {
        const int n = ty + 8 * i;
        hiT[(size_t)(n0 + n) * K2 + k20 + tx] = th[tx][n];
        loT[(size_t)(n0 + n) * K2 + k20 + tx] = tl[tx][n];
    }
}

// =======================================================================
// bf16x3 tensor-core GEMM, TMA-fed (unchanged from round 10).
// =======================================================================
#define NS        2
#define PLANE_A   16384
#define PLANE_BB  32768
#define STAGE_B   (2 * PLANE_A + 2 * PLANE_BB)   // 98304
#define GEMM_SMEM (NS * STAGE_B + 64)            // 196672
#define KT_SLABS  (K2DIM / 32)                   // 64

template <bool HAS_BIAS>
__global__ void __launch_bounds__(512)
gemm_tma(const __grid_constant__ CUtensorMap mAhi,
         const __grid_constant__ CUtensorMap mAlo,
         const __grid_constant__ CUtensorMap mBhi,
         const __grid_constant__ CUtensorMap mBlo,
         const float* __restrict__ bias, float* __restrict__ C, int N)
{
    extern __shared__ __align__(1024) uint32_t smw[];
    const uint32_t sbase = smem_u32(smw);
    const uint32_t full0  = sbase + NS * STAGE_B;
    const uint32_t empty0 = full0 + 16;

    const int tid  = threadIdx.x;
    const int lane = tid & 31;
    const int wid  = tid >> 5;                 // 0..15
    const int wm   = (wid & 1) * 64;
    const int wn   = (wid >> 1) * 32;
    const int r    = lane >> 2;
    const int c    = lane & 3;
    const int mBase = blockIdx.y * 128;
    const int nBase = blockIdx.x * 256;

    const int arow = ((lane >> 3) & 1) * 8 + (lane & 7);
    const int achk = (lane >> 4) * 16;
    const int brow = ((lane >> 3) & 2) * 4 + (lane & 7);
    const int bchk = ((lane >> 3) & 1) * 16;

    if (tid == 0) {
        #pragma unroll
        for (int s = 0; s < NS; ++s) {
            mbar_init(full0 + 8 * s, 1);
            mbar_init(empty0 + 8 * s, 16);
        }
    }
    __syncthreads();

    auto issue_slab = [&](int s, int kt) {
        const uint32_t st = sbase + (uint32_t)s * STAGE_B;
        const uint32_t fb = full0 + 8 * s;
        mbar_expect_tx(fb, STAGE_B);
        tma2d(st,                          &mAhi, kt * 32, mBase, fb);
        tma2d(st + PLANE_A,                &mAlo, kt * 32, mBase, fb);
        tma2d(st + 2 * PLANE_A,            &mBhi, kt * 32, nBase, fb);
        tma2d(st + 2 * PLANE_A + 16384,    &mBhi, kt * 32, nBase + 128, fb);
        tma2d(st + 2 * PLANE_A + PLANE_BB, &mBlo, kt * 32, nBase, fb);
        tma2d(st + 2 * PLANE_A + PLANE_BB + 16384,
              &mBlo, kt * 32, nBase + 128, fb);
    };

    if (tid == 0) issue_slab(0, 0);

    float acc[4][4][4];
    #pragma unroll
    for (int mi = 0; mi < 4; ++mi)
        #pragma unroll
        for (int ni = 0; ni < 4; ++ni)
            #pragma unroll
            for (int q = 0; q < 4; ++q) acc[mi][ni][q] = 0.f;

    for (int kt = 0; kt < KT_SLABS; ++kt) {
        const int s = kt & 1;

        if (tid == 0) {
            const int nk = kt + 1;
            if (nk < KT_SLABS) {
                if (nk >= NS) mbar_wait(empty0 + 8 * (nk & 1), (nk / NS - 1) & 1);
                issue_slab(nk & 1, nk);
            }
        }

        mbar_wait(full0 + 8 * s, (kt / NS) & 1);

        const uint32_t stg = sbase + (uint32_t)s * STAGE_B;
        #pragma unroll
        for (int t = 0; t < 4; ++t) {
            uint32_t afh[4][4], afl[4][4];
            #pragma unroll
            for (int mi = 0; mi < 4; ++mi) {
                const uint32_t a = stg +
                    sw128((uint32_t)((wm + mi * 16 + arow) * 128 + t * 32 + achk));
                ldsm4(afh[mi], a);
                ldsm4(afl[mi], a + PLANE_A);
            }
            uint32_t bfh[4][2], bfl[4][2];
            #pragma unroll
            for (int p = 0; p < 2; ++p) {
                const uint32_t b = stg + 2 * PLANE_A +
                    sw128((uint32_t)((wn + p * 16 + brow) * 128 + t * 32 + bchk));
                uint32_t tm[4];
                ldsm4(tm, b);
                bfh[2 * p][0] = tm[0]; bfh[2 * p][1] = tm[1];
                bfh[2 * p + 1][0] = tm[2]; bfh[2 * p + 1][1] = tm[3];
                ldsm4(tm, b + PLANE_BB);
                bfl[2 * p][0] = tm[0]; bfl[2 * p][1] = tm[1];
                bfl[2 * p + 1][0] = tm[2]; bfl[2 * p + 1][1] = tm[3];
            }
            #pragma unroll
            for (int ni = 0; ni < 4; ++ni)
                #pragma unroll
                for (int mi = 0; mi < 4; ++mi) {
                    MMA_BF16(acc[mi][ni], afh[mi][0], afh[mi][1], afh[mi][2],
                             afh[mi][3], bfh[ni][0], bfh[ni][1]);
                    MMA_BF16(acc[mi][ni], afh[mi][0], afh[mi][1], afh[mi][2],
                             afh[mi][3], bfl[ni][0], bfl[ni][1]);
                    MMA_BF16(acc[mi][ni], afl[mi][0], afl[mi][1], afl[mi][2],
                             afl[mi][3], bfh[ni][0], bfh[ni][1]);
                }
        }

        __syncwarp();
        if (lane == 0) mbar_arrive(empty0 + 8 * s);
    }

    #pragma unroll
    for (int mi = 0; mi < 4; ++mi) {
        const int row0 = mBase + wm + mi * 16 + r;
        #pragma unroll
        for (int ni = 0; ni < 4; ++ni) {
            const int col = nBase + wn + ni * 8 + c * 2;
            float2 v0 = make_float2(acc[mi][ni][0], acc[mi][ni][1]);
            float2 v1 = make_float2(acc[mi][ni][2], acc[mi][ni][3]);
            if (HAS_BIAS) {
                const float2 bb = *(const float2*)&bias[col];
                v0.x += bb.x; v0.y += bb.y;
                v1.x += bb.x; v1.y += bb.y;
            }
            *(float2*)&C[(size_t)row0 * N + col] = v0;
            *(float2*)&C[(size_t)(row0 + 8) * N + col] = v1;
        }
    }
}

// =======================================================================
// RoPE (interleaved pairs), in-place on Q and K slices of g_qkv.
// =======================================================================
__global__ void rope_kernel(const int* __restrict__ positions)
{
    const int totalQ = T_SEQ * NUM_HEADS * 32;
    const int totalK = T_SEQ * KV_GROUPS * 32;
    int idx = blockIdx.x * blockDim.x + threadIdx.x;

    int t, p, col0;
    if (idx < totalQ) {
        p = idx & 31;
        int h = (idx >> 5) & (NUM_HEADS - 1);
        t = idx >> 10;
        col0 = h * HEAD_DIM + 2 * p;
    } else {
        int rr = idx - totalQ;
        if (rr >= totalK) return;
        p = rr & 31;
        int g = (rr >> 5) & (KV_GROUPS - 1);
        t = rr >> 6;
        col0 = Q_SZ + g * HEAD_DIM + 2 * p;
    }

    const float pos   = (float)positions[t];
    const float theta = powf(10000.0f, -(float)p * (1.0f / 32.0f));
    float sn, cs;
    sincosf(pos * theta, &sn, &cs);

    float* b = g_qkv + (size_t)t * QKV_DIM + col0;
    const float x0 = b[0], x1 = b[1];
    b[0] = x0 * cs - x1 * sn;
    b[1] = x1 * cs + x0 * sn;
}

// =======================================================================
// Flash attention, tf32 mma.sync.
//  - P kept in REGISTERS: S C-frags are reused as A-frags under the
//    k-permutation pi(i) = (i<4 ? 2i : 2(i-4)+1); V rows are stored into
//    VT pre-permuted so PV = sum_k P[m,k] V[k,d] exactly.
//  - Ping-pong K/VT buffers -> ONE __syncthreads per kv iteration.
//  - Q in smem (pitch 132), K pitch 132, VT [d][k] 256B rows w/ XOR swizzle.
//  - LPT launch order (heavy mb first).
// =======================================================================
#define ABM 128
#define ABN 64

#define AQ_BYTES  (ABM * 132 * 4)            // 67584
#define AK_BYTES  (ABN * 132 * 4)            // 33792
#define AVT_BYTES (HEAD_DIM * ABN * 4)       // 32768
#define ABUF_B    (AK_BYTES + AVT_BYTES)     // 66560
#define ATTN_SMEM (AQ_BYTES + 2 * ABUF_B)    // 200704

__global__ __launch_bounds__(256)
void attn_tc(uint32_t* __restrict__ chi, uint32_t* __restrict__ clo)
{
    extern __shared__ __align__(1024) char sraw[];
    const uint32_t sb = smem_u32(sraw);
    const uint32_t qb = sb;                       // Q tile

    const int head = blockIdx.x;
    const int mb   = gridDim.y - 1 - blockIdx.y;  // LPT: heavy blocks first
    const int tid  = threadIdx.x;
    const int lane = tid & 31;
    const int wid  = tid >> 5;
    const int r    = lane >> 2;
    const int c    = lane & 3;
    const int rb   = wid * 16;
    const int g    = head / GQA_REP;
    const float scale = 0.08838834764831845f;     // 1/sqrt(128)

    const int lrow  = ((lane >> 3) & 1) * 8 + (lane & 7);   // A-frag rows
    const int lchk  = (lane >> 4) * 16;                     // A-frag k-chunk
    const int brow  = ((lane >> 4) & 1) * 8 + (lane & 7);   // B-frag rows
    const int bchk  = ((lane >> 3) & 1) * 16;               // B-frag k-chunk

    // ---- load Q tile (scaled, tf32-RN) ----
    for (int i = tid; i < ABM * 32; i += 256) {
        const int row = i >> 5, c4 = (i & 31) << 2;
        float4 v = *(const float4*)&g_qkv[(size_t)(mb * ABM + row) * QKV_DIM +
                                          head * HEAD_DIM + c4];
        v.x = f_tf32(v.x * scale); v.y = f_tf32(v.y * scale);
        v.z = f_tf32(v.z * scale); v.w = f_tf32(v.w * scale);
        *(float4*)(sraw + (size_t)row * 528 + c4 * 4) = v;
    }

    // prefetch mappings:
    //   K: unit q -> row = (tid+256q)>>5, d4 = ((tid+256q)&31)*4
    //   V: unit q -> d = i&127, idx = i>>7, m = idx>>1, h = idx&1;
    //      loads k = 8m + 2t + h (t=0..3)  [permuted gather for P-in-reg MMA]
    float4 kr[8], vr[8];
    #pragma unroll
    for (int q = 0; q < 8; ++q) {
        const int i = tid + 256 * q;
        const int row = i >> 5, c4 = (i & 31) << 2;
        kr[q] = *(const float4*)&g_qkv[(size_t)row * QKV_DIM + Q_SZ +
                                       g * HEAD_DIM + c4];
        const int d = i & 127, idx = i >> 7, m = idx >> 1, h = idx & 1;
        const float* vbase = g_qkv + Q_SZ + KV_SZ + g * HEAD_DIM + d;
        vr[q].x = vbase[(size_t)(8 * m + h + 0) * QKV_DIM];
        vr[q].y = vbase[(size_t)(8 * m + h + 2) * QKV_DIM];
        vr[q].z = vbase[(size_t)(8 * m + h + 4) * QKV_DIM];
        vr[q].w = vbase[(size_t)(8 * m + h + 6) * QKV_DIM];
    }

    float o[16][4];
    #pragma unroll
    for (int j = 0; j < 16; ++j)
        #pragma unroll
        for (int q = 0; q < 4; ++q) o[j][q] = 0.f;
    float mst0 = -1e30f, mst1 = -1e30f, lst0 = 0.f, lst1 = 0.f;

    const int nbEnd = 2 * mb + 1;
    for (int nb = 0; nb <= nbEnd; ++nb) {
        const uint32_t kbuf  = sb + AQ_BYTES + (uint32_t)(nb & 1) * ABUF_B;
        const uint32_t vtbuf = kbuf + AK_BYTES;

        // ---- store prefetched K/VT into this iteration's buffer ----
        #pragma unroll
        for (int q = 0; q < 8; ++q) {
            const int i = tid + 256 * q;
            const int row = i >> 5, c4 = (i & 31) << 2;
            *(float4*)(sraw + (kbuf - sb) + (size_t)row * 528 + c4 * 4) =
                f4_tf32(kr[q]);
            const int d = i & 127, idx = i >> 7, m = idx >> 1, h = idx & 1;
            const uint32_t off = (uint32_t)d * 256 +
                (((uint32_t)(32 * m + 16 * h)) ^ (((uint32_t)d & 7) << 4));
            *(float4*)(sraw + (vtbuf - sb) + off) = f4_tf32(vr[q]);
        }
        __syncthreads();   // single barrier per iteration (ping-pong buffers)

        if (nb < nbEnd) {
            #pragma unroll
            for (int q = 0; q < 8; ++q) {
                const int i = tid + 256 * q;
                const int row = i >> 5, c4 = (i & 31) << 2;
                kr[q] = *(const float4*)&g_qkv[(size_t)((nb + 1) * ABN + row) *
                                               QKV_DIM + Q_SZ + g * HEAD_DIM + c4];
                const int d = i & 127, idx = i >> 7, m = idx >> 1, h = idx & 1;
                const float* vbase = g_qkv + (size_t)((nb + 1) * ABN) * QKV_DIM +
                                     Q_SZ + KV_SZ + g * HEAD_DIM + d;
                vr[q].x = vbase[(size_t)(8 * m + h + 0) * QKV_DIM];
                vr[q].y = vbase[(size_t)(8 * m + h + 2) * QKV_DIM];
                vr[q].z = vbase[(size_t)(8 * m + h + 4) * QKV_DIM];
                vr[q].w = vbase[(size_t)(8 * m + h + 6) * QKV_DIM];
            }
        }

        // ---- S = Q K^T (ldmatrix frags) ----
        float s[8][4];
        #pragma unroll
        for (int j = 0; j < 8; ++j)
            #pragma unroll
            for (int q = 0; q < 4; ++q) s[j][q] = 0.f;

        #pragma unroll 4
        for (int k0 = 0; k0 < 16; ++k0) {
            uint32_t aq[4];
            ldsm4(aq, qb + (uint32_t)((rb + lrow) * 132 + 8 * k0) * 4 + lchk);
            #pragma unroll
            for (int jp = 0; jp < 4; ++jp) {
                uint32_t kf[4];
                ldsm4(kf, kbuf + (uint32_t)((16 * jp + brow) * 132 + 8 * k0) * 4 + bchk);
                MMA_TF32(s[2 * jp],     aq[0], aq[1], aq[2], aq[3], kf[0], kf[1]);
                MMA_TF32(s[2 * jp + 1], aq[0], aq[1], aq[2], aq[3], kf[2], kf[3]);
            }
        }

        // ---- causal mask ----
        if (nb >= 2 * mb) {
            const int row0 = mb * ABM + rb + r;
            #pragma unroll
            for (int j = 0; j < 8; ++j) {
                const int col = nb * ABN + 8 * j + 2 * c;
                if (col     > row0)     s[j][0] = -1e30f;
                if (col + 1 > row0)     s[j][1] = -1e30f;
                if (col     > row0 + 8) s[j][2] = -1e30f;
                if (col + 1 > row0 + 8) s[j][3] = -1e30f;
            }
        }

        // ---- online softmax ----
        float mx0 = -1e30f, mx1 = -1e30f;
        #pragma unroll
        for (int j = 0; j < 8; ++j) {
            mx0 = fmaxf(mx0, fmaxf(s[j][0], s[j][1]));
            mx1 = fmaxf(mx1, fmaxf(s[j][2], s[j][3]));
        }
        mx0 = fmaxf(mx0, __shfl_xor_sync(0xffffffffu, mx0, 1));
        mx0 = fmaxf(mx0, __shfl_xor_sync(0xffffffffu, mx0, 2));
        mx1 = fmaxf(mx1, __shfl_xor_sync(0xffffffffu, mx1, 1));
        mx1 = fmaxf(mx1, __shfl_xor_sync(0xffffffffu, mx1, 2));
        const float mn0 = fmaxf(mst0, mx0), mn1 = fmaxf(mst1, mx1);
        const float al0 = __expf(mst0 - mn0), al1 = __expf(mst1 - mn1);
        float sum0 = 0.f, sum1 = 0.f;
        #pragma unroll
        for (int j = 0; j < 8; ++j) {
            s[j][0] = f_tf32(__expf(s[j][0] - mn0)); sum0 += s[j][0];
            s[j][1] = f_tf32(__expf(s[j][1] - mn0)); sum0 += s[j][1];
            s[j][2] = f_tf32(__expf(s[j][2] - mn1)); sum1 += s[j][2];
            s[j][3] = f_tf32(__expf(s[j][3] - mn1)); sum1 += s[j][3];
        }
        sum0 += __shfl_xor_sync(0xffffffffu, sum0, 1);
        sum0 += __shfl_xor_sync(0xffffffffu, sum0, 2);
        sum1 += __shfl_xor_sync(0xffffffffu, sum1, 1);
        sum1 += __shfl_xor_sync(0xffffffffu, sum1, 2);
        lst0 = lst0 * al0 + sum0;  mst0 = mn0;
        lst1 = lst1 * al1 + sum1;  mst1 = mn1;
        #pragma unroll
        for (int j = 0; j < 16; ++j) {
            o[j][0] *= al0; o[j][1] *= al0;
            o[j][2] *= al1; o[j][3] *= al1;
        }

        // ---- O += P @ V  (P direct from s-regs; VT rows pre-permuted) ----
        #pragma unroll
        for (int kk = 0; kk < 8; ++kk) {
            const uint32_t a0 = __float_as_uint(s[kk][0]);
            const uint32_t a1 = __float_as_uint(s[kk][2]);
            const uint32_t a2 = __float_as_uint(s[kk][1]);
            const uint32_t a3 = __float_as_uint(s[kk][3]);
            #pragma unroll
            for (int jp = 0; jp < 8; ++jp) {
                const int vrow = 16 * jp + brow;
                const uint32_t addr = vtbuf + (uint32_t)vrow * 256 +
                    (((uint32_t)(kk * 32 + bchk)) ^ (((uint32_t)vrow & 7) << 4));
                uint32_t vf[4];
                ldsm4(vf, addr);
                MMA_TF32(o[2 * jp],     a0, a1, a2, a3, vf[0], vf[1]);
                MMA_TF32(o[2 * jp + 1], a0, a1, a2, a3, vf[2], vf[3]);
            }
        }
    }

    // ---- normalize + write ctx as pre-split bf16 hi/lo planes ----
    const float il0 = 1.0f / lst0, il1 = 1.0f / lst1;
    const int trow = mb * ABM + rb + r;
    #pragma unroll
    for (int j = 0; j < 16; ++j) {
        const int col = head * HEAD_DIM + 8 * j + 2 * c;
        uint32_t h, l;
        bsplit(o[j][0] * il0, o[j][1] * il0, h, l);
        const size_t p0 = ((size_t)trow * HIDDEN + col) >> 1;
        chi[p0] = h; clo[p0] = l;
        bsplit(o[j][2] * il1, o[j][3] * il1, h, l);
        const size_t p1 = ((size_t)(trow + 8) * HIDDEN + col) >> 1;
        chi[p1] = h; clo[p1] = l;
    }
}

// =======================================================================
// host side: tensormaps via runtime-resolved driver entry point
// =======================================================================
typedef CUresult (*tmap_encode_fn)(
    CUtensorMap*, CUtensorMapDataType, cuuint32_t, void*,
    const cuuint64_t*, const cuuint64_t*, const cuuint32_t*, const cuuint32_t*,
    CUtensorMapInterleave, CUtensorMapSwizzle, CUtensorMapL2promotion,
    CUtensorMapFloatOOBfill);

static tmap_encode_fn get_encoder()
{
    void* p = nullptr;
    cudaDriverEntryPointQueryResult qr;
#if CUDART_VERSION >= 12050
    cudaGetDriverEntryPointByVersion("cuTensorMapEncodeTiled", &p, 12000,
                                     cudaEnableDefault, &qr);
#else
    cudaGetDriverEntryPoint("cuTensorMapEncodeTiled", &p, cudaEnableDefault, &qr);
#endif
    return (tmap_encode_fn)p;
}

static void make_map(tmap_encode_fn enc, CUtensorMap* m, void* ptr,
                     uint64_t rows)
{
    cuuint64_t dims[2]    = {K2DIM, rows};
    cuuint64_t strides[1] = {K2DIM * sizeof(uint32_t)};
    cuuint32_t box[2]     = {32, 128};
    cuuint32_t es[2]      = {1, 1};
    enc(m, CU_TENSOR_MAP_DATA_TYPE_UINT32, 2, ptr, dims, strides, box, es,
        CU_TENSOR_MAP_INTERLEAVE_NONE, CU_TENSOR_MAP_SWIZZLE_128B,
        CU_TENSOR_MAP_L2_PROMOTION_L2_128B, CU_TENSOR_MAP_FLOAT_OOB_FILL_NONE);
}

extern "C" void kernel_launch(void* const* d_in, const int* in_sizes, int n_in,
                              void* d_out, int out_size)
{
    const int*   positions = (const int*)d_in[0];
    const float* hidden    = (const float*)d_in[1];
    const float* w_qkv     = (const float*)d_in[2];
    const float* b_qkv     = (const float*)d_in[3];
    const float* w_dense   = (const float*)d_in[4];
    float*       out       = (float*)d_out;

    float* qkv_p;
    uint32_t *ahi, *alo, *bhi, *blo;
    cudaGetSymbolAddress((void**)&qkv_p, g_qkv);
    cudaGetSymbolAddress((void**)&ahi,   g_ahi);
    cudaGetSymbolAddress((void**)&alo,   g_alo);
    cudaGetSymbolAddress((void**)&bhi,   g_bhi);
    cudaGetSymbolAddress((void**)&blo,   g_blo);

    tmap_encode_fn enc = get_encoder();
    CUtensorMap mAhi, mAlo, mBhi, mBlo;
    make_map(enc, &mAhi, ahi, T_SEQ);
    make_map(enc, &mAlo, alo, T_SEQ);
    make_map(enc, &mBhi, bhi, QKV_DIM);
    make_map(enc, &mBlo, blo, QKV_DIM);

    cudaFuncSetAttribute(gemm_tma<true>,
                         cudaFuncAttributeMaxDynamicSharedMemorySize, GEMM_SMEM);
    cudaFuncSetAttribute(gemm_tma<false>,
                         cudaFuncAttributeMaxDynamicSharedMemorySize, GEMM_SMEM);
    cudaFuncSetAttribute(attn_tc,
                         cudaFuncAttributeMaxDynamicSharedMemorySize, ATTN_SMEM);

    const int aPairs = T_SEQ * HIDDEN / 2;

    // 1) split inputs, then QKV = hidden @ w_qkv + b_qkv
    split_pairs<<<(aPairs + 255) / 256, 256>>>(
        (const float2*)hidden, ahi, alo, aPairs);
    split_bmat_t<<<dim3(QKV_DIM / 32, K2DIM / 32), dim3(32, 8)>>>(
        w_qkv, bhi, blo, K2DIM, QKV_DIM);
    gemm_tma<true><<<dim3(QKV_DIM / 256, T_SEQ / 128), 512, GEMM_SMEM>>>(
        mAhi, mAlo, mBhi, mBlo, b_qkv, qkv_p, QKV_DIM);

    // 2) RoPE in place
    const int totalRope = T_SEQ * NUM_HEADS * 32 + T_SEQ * KV_GROUPS * 32;
    rope_kernel<<<(totalRope + 255) / 256, 256>>>(positions);

    // 3) attention -> ctx hi/lo planes (LPT grid: head fast, mb slow-reversed)
    attn_tc<<<dim3(NUM_HEADS, T_SEQ / ABM), 256, ATTN_SMEM>>>(ahi, alo);

    // 4) split w_dense (transposed), then out = ctx @ w_dense
    split_bmat_t<<<dim3(HIDDEN / 32, K2DIM / 32), dim3(32, 8)>>>(
        w_dense, bhi, blo, K2DIM, HIDDEN);
    gemm_tma<false><<<dim3(HIDDEN / 256, T_SEQ / 128), 512, GEMM_SMEM>>>(
        mAhi, mAlo, mBhi, mBlo, nullptr, out, HIDDEN);
}